// round 1
// baseline (speedup 1.0000x reference)
#include <cuda_runtime.h>
#include <math.h>

// ---------------- problem constants ----------------
#define BB   16
#define SS   128
#define TT   256
#define DD   1024
#define FIN  (DD * SS)          // 131072
#define LN_EPS 1e-5f

// ---------------- scratch (device globals; no allocation allowed) ----------
// offsets in floats
#define OFF_SGM   0L                         // 16*128*1024   = 2097152
#define OFF_VELO  2097152L                   // 16*256*1024   = 4194304
#define OFF_Q     6291456L                   // 2097152
#define OFF_K     8388608L                   // 4194304
#define OFF_V1    12582912L                  // 16*256*512    = 2097152
#define OFF_ATTN  14680064L                  // 16*128*256    = 524288
#define OFF_X     15204352L                  // 16*131072     = 2097152
#define OFF_TMP   17301504L                  // 4096*1024     = 4194304
#define OFF_PART  21495808L                  // 256*16*1024   = 4194304
#define OFF_Y     25690112L                  // 16*1024
#define OFF_X1    25706496L
#define OFF_X2    25722880L
#define BUF_TOTAL 25739264L

__device__ float g_buf[BUF_TOTAL];

// ---------------- zero the dense (padded) activation buffers ---------------
__global__ void zero_dense_kernel() {
    long i = (long)blockIdx.x * blockDim.x + threadIdx.x;           // float4 index
    const long n1 = (2097152L) / 4;   // sgm dense
    const long n2 = (4194304L) / 4;   // velo dense
    float4 z = make_float4(0.f, 0.f, 0.f, 0.f);
    if (i < n1)            reinterpret_cast<float4*>(g_buf + OFF_SGM)[i] = z;
    else if (i < n1 + n2)  reinterpret_cast<float4*>(g_buf + OFF_VELO)[i - n1] = z;
}

// ---------------- flatten_pad scatter --------------------------------------
// one block per input row; binary search for batch start (bidx sorted)
__global__ void scatter_kernel(const float* __restrict__ feats,
                               const int* __restrict__ bidx,
                               int N, float* __restrict__ dense, int local) {
    int i = blockIdx.x;
    int b = bidx[i];
    __shared__ int s_rank;
    if (threadIdx.x == 0) {
        int lo = 0, hi = N;
        while (lo < hi) { int mid = (lo + hi) >> 1; if (bidx[mid] < b) lo = mid + 1; else hi = mid; }
        s_rank = i - lo;
    }
    __syncthreads();
    int r = s_rank;
    if (r >= local) return;
    float* drow = dense + ((long)b * local + r) * DD;
    const float* srow = feats + (long)i * DD;
    int c = threadIdx.x * 4;   // 256 threads * 4 = 1024 exactly
    float4 v = *reinterpret_cast<const float4*>(srow + c);
    *reinterpret_cast<float4*>(drow + c) = v;
}

// ---------------- tiled SGEMM: C[M,N] = A[M,K] @ B[K,N]  (NN) --------------
// BM=BN=128, BK=8, 256 threads, 8x8 register tile. All dims divisible.
__global__ __launch_bounds__(256, 2)
void gemm_nn(const float* __restrict__ A, const float* __restrict__ Bm,
             float* __restrict__ C, int M, int N, int K, int ldc,
             long aB, long bB, long cB) {
    A  += (long)blockIdx.z * aB;
    Bm += (long)blockIdx.z * bB;
    C  += (long)blockIdx.z * cB;
    __shared__ float As[8][128];
    __shared__ float Bs[8][128];
    const int tid = threadIdx.x;
    const int m0 = blockIdx.y * 128, n0 = blockIdx.x * 128;
    const int ar = tid >> 1, ac = (tid & 1) * 4;
    const int br = tid >> 5, bc = (tid & 31) * 4;
    const int tr = (tid >> 4) * 8, tc = (tid & 15) * 8;
    float acc[8][8];
#pragma unroll
    for (int i = 0; i < 8; i++)
#pragma unroll
        for (int j = 0; j < 8; j++) acc[i][j] = 0.f;

    for (int k0 = 0; k0 < K; k0 += 8) {
        float4 a4 = *reinterpret_cast<const float4*>(&A[(long)(m0 + ar) * K + k0 + ac]);
        As[ac + 0][ar] = a4.x; As[ac + 1][ar] = a4.y; As[ac + 2][ar] = a4.z; As[ac + 3][ar] = a4.w;
        *reinterpret_cast<float4*>(&Bs[br][bc]) =
            *reinterpret_cast<const float4*>(&Bm[(long)(k0 + br) * N + n0 + bc]);
        __syncthreads();
#pragma unroll
        for (int kk = 0; kk < 8; kk++) {
            float4 ta0 = *reinterpret_cast<const float4*>(&As[kk][tr]);
            float4 ta1 = *reinterpret_cast<const float4*>(&As[kk][tr + 4]);
            float4 tb0 = *reinterpret_cast<const float4*>(&Bs[kk][tc]);
            float4 tb1 = *reinterpret_cast<const float4*>(&Bs[kk][tc + 4]);
            float ra[8] = {ta0.x, ta0.y, ta0.z, ta0.w, ta1.x, ta1.y, ta1.z, ta1.w};
            float rb[8] = {tb0.x, tb0.y, tb0.z, tb0.w, tb1.x, tb1.y, tb1.z, tb1.w};
#pragma unroll
            for (int i = 0; i < 8; i++)
#pragma unroll
                for (int j = 0; j < 8; j++) acc[i][j] += ra[i] * rb[j];
        }
        __syncthreads();
    }
#pragma unroll
    for (int i = 0; i < 8; i++)
#pragma unroll
        for (int j = 0; j < 8; j += 4) {
            float4 v = make_float4(acc[i][j], acc[i][j + 1], acc[i][j + 2], acc[i][j + 3]);
            *reinterpret_cast<float4*>(&C[(long)(m0 + tr + i) * ldc + n0 + tc + j]) = v;
        }
}

// ---------------- tiled SGEMM: C[M,N] = A[M,K] @ B[N,K]^T (NT) -------------
__global__ __launch_bounds__(256, 2)
void gemm_nt(const float* __restrict__ A, const float* __restrict__ Bm,
             float* __restrict__ C, int M, int N, int K, int ldc,
             long aB, long bB, long cB) {
    A  += (long)blockIdx.z * aB;
    Bm += (long)blockIdx.z * bB;
    C  += (long)blockIdx.z * cB;
    __shared__ float As[8][128];
    __shared__ float Bs[8][128];
    const int tid = threadIdx.x;
    const int m0 = blockIdx.y * 128, n0 = blockIdx.x * 128;
    const int ar = tid >> 1, ac = (tid & 1) * 4;
    const int tr = (tid >> 4) * 8, tc = (tid & 15) * 8;
    float acc[8][8];
#pragma unroll
    for (int i = 0; i < 8; i++)
#pragma unroll
        for (int j = 0; j < 8; j++) acc[i][j] = 0.f;

    for (int k0 = 0; k0 < K; k0 += 8) {
        float4 a4 = *reinterpret_cast<const float4*>(&A[(long)(m0 + ar) * K + k0 + ac]);
        As[ac + 0][ar] = a4.x; As[ac + 1][ar] = a4.y; As[ac + 2][ar] = a4.z; As[ac + 3][ar] = a4.w;
        float4 b4 = *reinterpret_cast<const float4*>(&Bm[(long)(n0 + ar) * K + k0 + ac]);
        Bs[ac + 0][ar] = b4.x; Bs[ac + 1][ar] = b4.y; Bs[ac + 2][ar] = b4.z; Bs[ac + 3][ar] = b4.w;
        __syncthreads();
#pragma unroll
        for (int kk = 0; kk < 8; kk++) {
            float4 ta0 = *reinterpret_cast<const float4*>(&As[kk][tr]);
            float4 ta1 = *reinterpret_cast<const float4*>(&As[kk][tr + 4]);
            float4 tb0 = *reinterpret_cast<const float4*>(&Bs[kk][tc]);
            float4 tb1 = *reinterpret_cast<const float4*>(&Bs[kk][tc + 4]);
            float ra[8] = {ta0.x, ta0.y, ta0.z, ta0.w, ta1.x, ta1.y, ta1.z, ta1.w};
            float rb[8] = {tb0.x, tb0.y, tb0.z, tb0.w, tb1.x, tb1.y, tb1.z, tb1.w};
#pragma unroll
            for (int i = 0; i < 8; i++)
#pragma unroll
                for (int j = 0; j < 8; j++) acc[i][j] += ra[i] * rb[j];
        }
        __syncthreads();
    }
#pragma unroll
    for (int i = 0; i < 8; i++)
#pragma unroll
        for (int j = 0; j < 8; j += 4) {
            float4 v = make_float4(acc[i][j], acc[i][j + 1], acc[i][j + 2], acc[i][j + 3]);
            *reinterpret_cast<float4*>(&C[(long)(m0 + tr + i) * ldc + n0 + tc + j]) = v;
        }
}

// ---------------- LayerNorm + ReLU (row-wise over C), flexible output map --
// out index = (row / rows_per_b)*ob + (row % rows_per_b)*orr + c
__global__ void ln_relu_kernel(const float* __restrict__ in,
                               const float* __restrict__ gamma,
                               const float* __restrict__ beta,
                               float* __restrict__ outbase,
                               int C, int rows_per_b, long ob, long orr) {
    int row = blockIdx.x;
    int t = threadIdx.x;
    const float* ip = in + (long)row * C;
    float s = 0.f, ss = 0.f;
    for (int c = t; c < C; c += 256) { float v = ip[c]; s += v; ss += v * v; }
    __shared__ float rs[256], rq[256];
    rs[t] = s; rq[t] = ss;
    __syncthreads();
    for (int o = 128; o > 0; o >>= 1) {
        if (t < o) { rs[t] += rs[t + o]; rq[t] += rq[t + o]; }
        __syncthreads();
    }
    float mean = rs[0] / C;
    float var  = rq[0] / C - mean * mean;
    float r = rsqrtf(var + LN_EPS);
    float* op = outbase + (long)(row / rows_per_b) * ob + (long)(row % rows_per_b) * orr;
    for (int c = t; c < C; c += 256) {
        float v = (ip[c] - mean) * r * gamma[c] + beta[c];
        op[c] = fmaxf(v, 0.f);
    }
}

// ---------------- softmax over last dim (C == 256, in place) ---------------
__global__ void softmax256_kernel(float* __restrict__ attn) {
    int row = blockIdx.x;
    int t = threadIdx.x;
    float v = attn[(long)row * 256 + t];
    __shared__ float red[256];
    red[t] = v;
    __syncthreads();
    for (int o = 128; o > 0; o >>= 1) {
        if (t < o) red[t] = fmaxf(red[t], red[t + o]);
        __syncthreads();
    }
    float mx = red[0];
    __syncthreads();
    float e = __expf(v - mx);
    red[t] = e;
    __syncthreads();
    for (int o = 128; o > 0; o >>= 1) {
        if (t < o) red[t] += red[t + o];
        __syncthreads();
    }
    attn[(long)row * 256 + t] = e / red[0];
}

// ---------------- fc3a: split-K partials over W3a (memory-bound) -----------
// grid (DD/256, FIN/512); part[(chunk*16 + b)*DD + n]
__global__ __launch_bounds__(256)
void fc3a_partial_kernel(const float* __restrict__ x, const float* __restrict__ W,
                         float* __restrict__ part) {
    __shared__ float xs[BB][512];
    int n  = blockIdx.x * 256 + threadIdx.x;
    int f0 = blockIdx.y * 512;
    for (int i = threadIdx.x; i < BB * 512; i += 256) {
        int b = i >> 9, f = i & 511;
        xs[b][f] = x[(long)b * FIN + f0 + f];
    }
    __syncthreads();
    float acc[BB];
#pragma unroll
    for (int b = 0; b < BB; b++) acc[b] = 0.f;
#pragma unroll 4
    for (int f = 0; f < 512; f++) {
        float w = W[(long)(f0 + f) * DD + n];
#pragma unroll
        for (int b = 0; b < BB; b++) acc[b] += xs[b][f] * w;
    }
#pragma unroll
    for (int b = 0; b < BB; b++)
        part[((long)blockIdx.y * BB + b) * DD + n] = acc[b];
}

__global__ void fc3a_reduce_kernel(const float* __restrict__ part, float* __restrict__ y) {
    int id = blockIdx.x * 256 + threadIdx.x;   // id = b*DD + n, 16384 total
    int b = id >> 10, n = id & 1023;
    float s = 0.f;
#pragma unroll 4
    for (int c = 0; c < 256; c++) s += part[((long)c * BB + b) * DD + n];
    y[id] = s;
}

// ---------------- fc3b: [16,1024] @ [1024,1024] ----------------------------
__global__ void small_gemm_kernel(const float* __restrict__ A, const float* __restrict__ W,
                                  float* __restrict__ C, int K, int N) {
    int n = blockIdx.x * 256 + threadIdx.x;
    int b = blockIdx.y;
    float acc = 0.f;
#pragma unroll 4
    for (int k = 0; k < K; k++) acc += A[(long)b * K + k] * W[(long)k * N + n];
    C[(long)b * N + n] = acc;
}

// ---------------- heads: quat (normalized) + trans -------------------------
__global__ void heads_kernel(const float* __restrict__ x2,
                             const float* __restrict__ Wr, const float* __restrict__ br,
                             const float* __restrict__ Wt, const float* __restrict__ bt,
                             float* __restrict__ out) {
    int b = blockIdx.x;
    int w = threadIdx.x >> 5, lane = threadIdx.x & 31;
    __shared__ float vals[7];
    if (w < 7) {
        const float* Wp = (w < 4) ? Wr : Wt;
        int ncol = (w < 4) ? 4 : 3;
        int j    = (w < 4) ? w : (w - 4);
        float acc = 0.f;
        for (int k = lane; k < DD; k += 32) acc += x2[(long)b * DD + k] * Wp[(long)k * ncol + j];
        for (int o = 16; o > 0; o >>= 1) acc += __shfl_down_sync(0xffffffffu, acc, o);
        if (lane == 0) vals[w] = acc + ((w < 4) ? br[j] : bt[j]);
    }
    __syncthreads();
    if (threadIdx.x == 0) {
        float nn = sqrtf(vals[0]*vals[0] + vals[1]*vals[1] + vals[2]*vals[2] + vals[3]*vals[3]);
        nn = fmaxf(nn, 1e-12f);
        for (int j = 0; j < 4; j++) out[b * 4 + j] = vals[j] / nn;
        for (int j = 0; j < 3; j++) out[64 + b * 3 + j] = vals[4 + j];
    }
}

// ---------------- host driver ----------------------------------------------
extern "C" void kernel_launch(void* const* d_in, const int* in_sizes, int n_in,
                              void* d_out, int out_size) {
    const float* sgm_feats = nullptr; const float* velo_feats = nullptr;
    const int* sbidx = nullptr; const int* vbidx = nullptr;
    int N_sgm = 0, N_velo = 0;
    const float* w[22]; int wi = 0;
    for (int i = 0; i < n_in; i++) {
        int s = in_sizes[i];
        if (s == 3000 * 1024)      { sgm_feats = (const float*)d_in[i]; }
        else if (s == 6000 * 1024) { velo_feats = (const float*)d_in[i]; }
        else if (s == 3000)        { sbidx = (const int*)d_in[i]; N_sgm = s; }
        else if (s == 6000)        { vbidx = (const int*)d_in[i]; N_velo = s; }
        else if (wi < 22)          { w[wi++] = (const float*)d_in[i]; }
    }
    const float *Wq = w[0], *gq = w[1], *bq = w[2];
    const float *Wk = w[3], *gk = w[4], *bk = w[5];
    const float *Wv1 = w[6], *gv1 = w[7], *bv1 = w[8];
    const float *Wv2 = w[9], *gv2 = w[10], *bv2 = w[11];
    const float *W3a = w[12], *g3a = w[13], *b3a = w[14];
    const float *W3b = w[15], *g3b = w[16], *b3b = w[17];
    const float *Wr = w[18], *brr = w[19], *Wt = w[20], *btt = w[21];

    float* base = nullptr;
    cudaGetSymbolAddress((void**)&base, g_buf);
    float* dSGM  = base + OFF_SGM;
    float* dVELO = base + OFF_VELO;
    float* dQ    = base + OFF_Q;
    float* dK    = base + OFF_K;
    float* dV1   = base + OFF_V1;
    float* dATT  = base + OFF_ATTN;
    float* dX    = base + OFF_X;
    float* dTMP  = base + OFF_TMP;
    float* dPART = base + OFF_PART;
    float* dY    = base + OFF_Y;
    float* dX1   = base + OFF_X1;
    float* dX2   = base + OFF_X2;
    float* out   = (float*)d_out;

    // 1. zero padded dense buffers, scatter ragged rows
    zero_dense_kernel<<<(1572864 + 255) / 256, 256>>>();
    scatter_kernel<<<N_sgm, 256>>>(sgm_feats, sbidx, N_sgm, dSGM, SS);
    scatter_kernel<<<N_velo, 256>>>(velo_feats, vbidx, N_velo, dVELO, TT);

    // 2. q = relu(ln(sgm @ Wq))      [2048,1024]
    gemm_nn<<<dim3(8, 16, 1), 256>>>(dSGM, Wq, dTMP, BB * SS, DD, DD, DD, 0, 0, 0);
    ln_relu_kernel<<<BB * SS, 256>>>(dTMP, gq, bq, dQ, DD, 1 << 20, 0, DD);

    // 3. k = relu(ln(velo @ Wk))     [4096,1024]
    gemm_nn<<<dim3(8, 32, 1), 256>>>(dVELO, Wk, dTMP, BB * TT, DD, DD, DD, 0, 0, 0);
    ln_relu_kernel<<<BB * TT, 256>>>(dTMP, gk, bk, dK, DD, 1 << 20, 0, DD);

    // 4. v1 = relu(ln(velo @ Wv1))   [4096,512]
    gemm_nn<<<dim3(4, 32, 1), 256>>>(dVELO, Wv1, dTMP, BB * TT, 512, DD, 512, 0, 0, 0);
    ln_relu_kernel<<<BB * TT, 256>>>(dTMP, gv1, bv1, dV1, 512, 1 << 20, 0, 512);

    // 5. v2 = relu(ln(sgm @ Wv2)) -> written straight into x[b, s*1024 + 0..511]
    gemm_nn<<<dim3(4, 16, 1), 256>>>(dSGM, Wv2, dTMP, BB * SS, 512, DD, 512, 0, 0, 0);
    ln_relu_kernel<<<BB * SS, 256>>>(dTMP, gv2, bv2, dX, 512, SS, (long)FIN, DD);

    // 6. scores = q @ k^T (batched NT), softmax in place
    gemm_nt<<<dim3(2, 1, BB), 256>>>(dQ, dK, dATT, SS, TT, DD, TT,
                                     (long)SS * DD, (long)TT * DD, (long)SS * TT);
    softmax256_kernel<<<BB * SS, 256>>>(dATT);

    // 7. ctx = attn @ v1 -> x[b, s*1024 + 512..1023]
    gemm_nn<<<dim3(4, 1, BB), 256>>>(dATT, dV1, dX + 512, SS, 512, TT, DD,
                                     (long)SS * TT, (long)TT * 512, (long)FIN);

    // 8. fc3a: y = x @ W3a (memory-bound over 536MB), reduce, LN+ReLU -> x1
    fc3a_partial_kernel<<<dim3(DD / 256, FIN / 512), 256>>>(dX, W3a, dPART);
    fc3a_reduce_kernel<<<(BB * DD) / 256, 256>>>(dPART, dY);
    ln_relu_kernel<<<BB, 256>>>(dY, g3a, b3a, dX1, DD, 1 << 20, 0, DD);

    // 9. fc3b + LN+ReLU -> x2
    small_gemm_kernel<<<dim3(DD / 256, BB), 256>>>(dX1, W3b, dTMP, DD, DD);
    ln_relu_kernel<<<BB, 256>>>(dTMP, g3b, b3b, dX2, DD, 1 << 20, 0, DD);

    // 10. heads
    heads_kernel<<<BB, 256>>>(dX2, Wr, brr, Wt, btt, out);
    (void)out_size;
}

// round 3
// speedup vs baseline: 1.8002x; 1.8002x over previous
#include <cuda_runtime.h>
#include <cuda_bf16.h>
#include <math.h>
#include <stdint.h>

// ---------------- problem constants ----------------
#define BB   16
#define SS   128
#define TT   256
#define DD   1024
#define FIN  (DD * SS)          // 131072
#define LN_EPS 1e-5f

// ---------------- fp32 scratch (floats) ----------------
#define OFF_TMP   0L             // 4194304 (max 4096x1024)
#define OFF_V1F   4194304L       // 2097152 (16*256*512)
#define OFF_X     6291456L       // 2097152 (16*131072)
#define OFF_ATTNF 8388608L       // 524288  (16*128*256)
#define OFF_PART  8912896L       // 4194304 (256*16*1024)
#define OFF_Y     13107200L      // 16384
#define OFF_X1    13123584L
#define OFF_X2    13139968L
#define FBUF_TOTAL 13156352L
__device__ __align__(128) float g_buf[FBUF_TOTAL];

// ---------------- bf16 scratch (elements) ----------------
#define BO_SGMH   0L             // 2097152
#define BO_SGML   2097152L
#define BO_VELOH  4194304L       // 4194304
#define BO_VELOL  8388608L
#define BO_QH     12582912L      // 2097152
#define BO_QL     14680064L
#define BO_KH     16777216L      // 4194304
#define BO_KL     20971520L
#define BO_WQTH   25165824L      // 1048576
#define BO_WQTL   26214400L
#define BO_WKTH   27262976L
#define BO_WKTL   28311552L
#define BO_WV1TH  29360128L      // 524288
#define BO_WV1TL  29884416L
#define BO_WV2TH  30408704L      // 524288
#define BO_WV2TL  30932992L
#define BO_V1TH   31457280L      // 2097152
#define BO_V1TL   33554432L
#define BO_ATH    35651584L      // 524288
#define BO_ATL    36175872L
#define BBUF_TOTAL 36700160L
__device__ __align__(128) __nv_bfloat16 g_bf[BBUF_TOTAL];

// ================= PTX helpers (baseline ISA, works on plain sm_103) =======
__device__ __forceinline__ uint32_t smem_u32(const void* p) {
    uint32_t a;
    asm("{ .reg .u64 t; cvta.to.shared.u64 t, %1; cvt.u32.u64 %0, t; }" : "=r"(a) : "l"(p));
    return a;
}
__device__ __forceinline__ void cpasync16(uint32_t dst, const void* src) {
    asm volatile("cp.async.cg.shared.global [%0], [%1], 16;" :: "r"(dst), "l"(src));
}
#define CP_COMMIT() asm volatile("cp.async.commit_group;" ::: "memory")
#define CP_WAIT(n)  asm volatile("cp.async.wait_group %0;" :: "n"(n) : "memory")

__device__ __forceinline__ void ldm_x4(uint32_t addr, uint32_t* r) {
    asm volatile("ldmatrix.sync.aligned.m8n8.x4.shared.b16 {%0,%1,%2,%3}, [%4];"
                 : "=r"(r[0]), "=r"(r[1]), "=r"(r[2]), "=r"(r[3]) : "r"(addr));
}
__device__ __forceinline__ void mma16816(float* d, const uint32_t* a, const uint32_t* b) {
    asm volatile("mma.sync.aligned.m16n8k16.row.col.f32.bf16.bf16.f32 "
                 "{%0,%1,%2,%3}, {%4,%5,%6,%7}, {%8,%9}, {%0,%1,%2,%3};"
                 : "+f"(d[0]), "+f"(d[1]), "+f"(d[2]), "+f"(d[3])
                 : "r"(a[0]), "r"(a[1]), "r"(a[2]), "r"(a[3]), "r"(b[0]), "r"(b[1]));
}

// ---------------- hi/lo split helpers ----------------
__device__ __forceinline__ void split2(float a, float b, unsigned& h, unsigned& l) {
    __nv_bfloat162 hh = __floats2bfloat162_rn(a, b);
    float ra = a - __bfloat162float(__low2bfloat16(hh));
    float rb = b - __bfloat162float(__high2bfloat16(hh));
    __nv_bfloat162 ll = __floats2bfloat162_rn(ra, rb);
    h = *reinterpret_cast<unsigned*>(&hh);
    l = *reinterpret_cast<unsigned*>(&ll);
}

// ================= zero dense bf16 buffers =================
__global__ void zero_bf_kernel() {
    long i = (long)blockIdx.x * blockDim.x + threadIdx.x;    // uint4 index
    const long n = (12582912L * 2) / 16;                     // sgm+velo hi/lo
    if (i < n) reinterpret_cast<uint4*>(g_bf)[i] = make_uint4(0, 0, 0, 0);
}

// ================= scatter ragged rows -> dense hi/lo bf16 =================
__global__ void scatter_split_kernel(const float* __restrict__ feats,
                                     const int* __restrict__ bidx, int N,
                                     __nv_bfloat16* __restrict__ dh,
                                     __nv_bfloat16* __restrict__ dl, int local) {
    int i = blockIdx.x;
    int b = bidx[i];
    __shared__ int s_rank;
    if (threadIdx.x == 0) {
        int lo = 0, hi = N;
        while (lo < hi) { int mid = (lo + hi) >> 1; if (bidx[mid] < b) lo = mid + 1; else hi = mid; }
        s_rank = i - lo;
    }
    __syncthreads();
    int r = s_rank;
    if (r >= local) return;
    long row = (long)b * local + r;
    const float4 v = *reinterpret_cast<const float4*>(feats + (long)i * DD + threadIdx.x * 4);
    uint2 h, l;
    split2(v.x, v.y, h.x, l.x);
    split2(v.z, v.w, h.y, l.y);
    *reinterpret_cast<uint2*>(dh + row * DD + threadIdx.x * 4) = h;
    *reinterpret_cast<uint2*>(dl + row * DD + threadIdx.x * 4) = l;
}

// ================= transpose + split: in[R][C] fp32 -> out[C][R] bf16 hi/lo ===
__global__ void transpose_split_kernel(const float* __restrict__ in,
                                       __nv_bfloat16* __restrict__ oh,
                                       __nv_bfloat16* __restrict__ ol,
                                       int R, int C, long inB, long outB) {
    __shared__ float t[32][33];
    int z = blockIdx.z;
    in += (long)z * inB; oh += (long)z * outB; ol += (long)z * outB;
    int r0 = blockIdx.y * 32, c0 = blockIdx.x * 32;
    int tx = threadIdx.x & 31, ty = threadIdx.x >> 5;   // 256 threads: ty 0..7
#pragma unroll
    for (int i = 0; i < 32; i += 8)
        t[ty + i][tx] = in[(long)(r0 + ty + i) * C + c0 + tx];
    __syncthreads();
#pragma unroll
    for (int i = 0; i < 32; i += 8) {
        float v = t[tx][ty + i];
        __nv_bfloat16 h = __float2bfloat16(v);
        __nv_bfloat16 l = __float2bfloat16(v - __bfloat162float(h));
        long o = (long)(c0 + ty + i) * R + r0 + tx;
        oh[o] = h; ol[o] = l;
    }
}

// ================= elementwise fp32 -> hi/lo bf16 =================
__global__ void split_kernel(const float* __restrict__ in,
                             __nv_bfloat16* __restrict__ oh,
                             __nv_bfloat16* __restrict__ ol, long n4) {
    long i = (long)blockIdx.x * blockDim.x + threadIdx.x;
    if (i >= n4) return;
    float4 v = reinterpret_cast<const float4*>(in)[i];
    uint2 h, l;
    split2(v.x, v.y, h.x, l.x);
    split2(v.z, v.w, h.y, l.y);
    reinterpret_cast<uint2*>(oh)[i] = h;
    reinterpret_cast<uint2*>(ol)[i] = l;
}

// ================= HMMA GEMM: C[M,N] = A[M,K] @ B[N,K]^T ====================
// A,B hi/lo bf16, K-contiguous rows. CTA tile 128x128, 8 warps (4m x 2n),
// warp tile 32x64. k-chunk 32, cp.async double buffer.
// smem stage layout (32KB): Ah[128][32] @0, Al @8K, Bh @16K, Bl @24K.
// Row = 64B, stored as 4 16B chunks with swizzle chunk' = chunk ^ (row&3).
#define MG_SMEM 65536

__global__ __launch_bounds__(256, 1)
void mma_gemm(const __nv_bfloat16* __restrict__ Ahp, const __nv_bfloat16* __restrict__ Alp,
              const __nv_bfloat16* __restrict__ Bhp, const __nv_bfloat16* __restrict__ Blp,
              float* __restrict__ C, int K, int ldc,
              long aB, long bB, long cB) {
    extern __shared__ char smem[];
    const uint32_t sb = smem_u32(smem);
    const int tid = threadIdx.x, lane = tid & 31, wid = tid >> 5;
    const int wm = wid & 3, wn = wid >> 2;
    const int z = blockIdx.z;
    const long m0 = (long)blockIdx.y * 128, n0 = (long)blockIdx.x * 128;

    const __nv_bfloat16* Ah = Ahp + (long)z * aB + m0 * K;
    const __nv_bfloat16* Al = Alp + (long)z * aB + m0 * K;
    const __nv_bfloat16* Bh = Bhp + (long)z * bB + n0 * K;
    const __nv_bfloat16* Bl = Blp + (long)z * bB + n0 * K;
    float* Cp = C + (long)z * cB + m0 * ldc + n0;

    // gmem->smem assignment: thread covers rows r_ld and r_ld+64, chunk c_ld
    const int r_ld = tid >> 2, c_ld = tid & 3;
    const int r_ld2 = r_ld + 64;
    const uint32_t d0 = (uint32_t)(r_ld * 64 + ((c_ld ^ (r_ld & 3)) << 4));
    const uint32_t d1 = (uint32_t)(r_ld2 * 64 + ((c_ld ^ (r_ld2 & 3)) << 4));

    float acc[2][8][4];
#pragma unroll
    for (int i = 0; i < 2; i++)
#pragma unroll
        for (int j = 0; j < 8; j++)
#pragma unroll
            for (int q = 0; q < 4; q++) acc[i][j][q] = 0.f;

    const int NC = K >> 5;

    auto load_chunk = [&](int ci, int st) {
        const int k0 = ci << 5;
        const uint32_t s0 = sb + (st ? 32768u : 0u);
        const long ro = (long)r_ld * K + k0 + c_ld * 8;
        const long ro2 = (long)r_ld2 * K + k0 + c_ld * 8;
        cpasync16(s0 + d0,          Ah + ro);
        cpasync16(s0 + d1,          Ah + ro2);
        cpasync16(s0 + 8192 + d0,   Al + ro);
        cpasync16(s0 + 8192 + d1,   Al + ro2);
        cpasync16(s0 + 16384 + d0,  Bh + ro);
        cpasync16(s0 + 16384 + d1,  Bh + ro2);
        cpasync16(s0 + 24576 + d0,  Bl + ro);
        cpasync16(s0 + 24576 + d1,  Bl + ro2);
    };

    // ldmatrix lane-derived pieces
    const int a_sub = ((lane >> 3) & 1) * 8 + (lane & 7);   // row within 16-block
    const int a_kc = lane >> 4;                             // k half (0/1)
    const int b_sub = ((lane >> 4) & 1) * 8 + (lane & 7);   // n within 16-block
    const int b_kc = (lane >> 3) & 1;

    load_chunk(0, 0); CP_COMMIT();

    for (int i = 0; i < NC; i++) {
        if (i + 1 < NC) { load_chunk(i + 1, (i + 1) & 1); CP_COMMIT(); CP_WAIT(1); }
        else            { CP_WAIT(0); }
        __syncthreads();
        const uint32_t s0 = sb + ((i & 1) ? 32768u : 0u);
#pragma unroll
        for (int ks = 0; ks < 2; ks++) {
            uint32_t ah[2][4], al[2][4], bh[8][2], bl[8][2];
#pragma unroll
            for (int mi = 0; mi < 2; mi++) {
                int mrow = wm * 32 + mi * 16 + a_sub;
                int kc = ks * 2 + a_kc;
                uint32_t ad = s0 + mrow * 64 + ((kc ^ (mrow & 3)) << 4);
                ldm_x4(ad, ah[mi]);
                ldm_x4(ad + 8192, al[mi]);
            }
#pragma unroll
            for (int np = 0; np < 4; np++) {
                int nrow = wn * 64 + np * 16 + b_sub;
                int kc = ks * 2 + b_kc;
                uint32_t bd = s0 + 16384 + nrow * 64 + ((kc ^ (nrow & 3)) << 4);
                uint32_t t[4];
                ldm_x4(bd, t);
                bh[np * 2][0] = t[0]; bh[np * 2][1] = t[1];
                bh[np * 2 + 1][0] = t[2]; bh[np * 2 + 1][1] = t[3];
                ldm_x4(bd + 8192, t);
                bl[np * 2][0] = t[0]; bl[np * 2][1] = t[1];
                bl[np * 2 + 1][0] = t[2]; bl[np * 2 + 1][1] = t[3];
            }
#pragma unroll
            for (int mi = 0; mi < 2; mi++)
#pragma unroll
                for (int nj = 0; nj < 8; nj++) {
                    mma16816(acc[mi][nj], ah[mi], bh[nj]);
                    mma16816(acc[mi][nj], ah[mi], bl[nj]);
                    mma16816(acc[mi][nj], al[mi], bh[nj]);
                }
        }
        __syncthreads();
    }

    // epilogue: direct fp32 stores (float2 per fragment half)
    const int er = lane >> 2, ec = (lane & 3) * 2;
    const long mb = wm * 32 + er;
    const int nb = wn * 64 + ec;
#pragma unroll
    for (int mi = 0; mi < 2; mi++)
#pragma unroll
        for (int nj = 0; nj < 8; nj++) {
            float* p0 = Cp + (mb + mi * 16) * ldc + nb + nj * 8;
            float* p1 = p0 + 8L * ldc;
            *reinterpret_cast<float2*>(p0) = make_float2(acc[mi][nj][0], acc[mi][nj][1]);
            *reinterpret_cast<float2*>(p1) = make_float2(acc[mi][nj][2], acc[mi][nj][3]);
        }
}

// ================= LayerNorm + ReLU, optional fp32 out + optional hi/lo out ==
__global__ void ln_relu_kernel(const float* __restrict__ in,
                               const float* __restrict__ gamma,
                               const float* __restrict__ beta,
                               float* __restrict__ outbase,
                               int C, int rows_per_b, long ob, long orr,
                               __nv_bfloat16* __restrict__ oh,
                               __nv_bfloat16* __restrict__ ol) {
    int row = blockIdx.x;
    int t = threadIdx.x;
    const float* ip = in + (long)row * C;
    float s = 0.f, ss = 0.f;
    for (int c = t; c < C; c += 256) { float v = ip[c]; s += v; ss += v * v; }
    __shared__ float rs[256], rq[256];
    rs[t] = s; rq[t] = ss;
    __syncthreads();
    for (int o = 128; o > 0; o >>= 1) {
        if (t < o) { rs[t] += rs[t + o]; rq[t] += rq[t + o]; }
        __syncthreads();
    }
    float mean = rs[0] / C;
    float var = rq[0] / C - mean * mean;
    float r = rsqrtf(var + LN_EPS);
    float* op = outbase ? outbase + (long)(row / rows_per_b) * ob + (long)(row % rows_per_b) * orr
                        : nullptr;
    for (int c = t; c < C; c += 256) {
        float v = (ip[c] - mean) * r * gamma[c] + beta[c];
        v = fmaxf(v, 0.f);
        if (op) op[c] = v;
        if (oh) {
            __nv_bfloat16 h = __float2bfloat16(v);
            oh[(long)row * C + c] = h;
            ol[(long)row * C + c] = __float2bfloat16(v - __bfloat162float(h));
        }
    }
}

// ================= softmax over last dim (256, in place) =================
__global__ void softmax256_kernel(float* __restrict__ attn) {
    int row = blockIdx.x;
    int t = threadIdx.x;
    float v = attn[(long)row * 256 + t];
    __shared__ float red[256];
    red[t] = v;
    __syncthreads();
    for (int o = 128; o > 0; o >>= 1) { if (t < o) red[t] = fmaxf(red[t], red[t + o]); __syncthreads(); }
    float mx = red[0];
    __syncthreads();
    float e = __expf(v - mx);
    red[t] = e;
    __syncthreads();
    for (int o = 128; o > 0; o >>= 1) { if (t < o) red[t] += red[t + o]; __syncthreads(); }
    attn[(long)row * 256 + t] = e / red[0];
}

// ================= fc3a: streaming split-K over W3a =================
__global__ __launch_bounds__(256)
void fc3a_partial_kernel(const float* __restrict__ x, const float* __restrict__ W,
                         float* __restrict__ part) {
    __shared__ float xs[BB][512];
    int n = blockIdx.x * 256 + threadIdx.x;
    int f0 = blockIdx.y * 512;
    for (int i = threadIdx.x; i < BB * 512; i += 256) {
        int b = i >> 9, f = i & 511;
        xs[b][f] = x[(long)b * FIN + f0 + f];
    }
    __syncthreads();
    float acc[BB];
#pragma unroll
    for (int b = 0; b < BB; b++) acc[b] = 0.f;
#pragma unroll 4
    for (int f = 0; f < 512; f++) {
        float w = W[(long)(f0 + f) * DD + n];
#pragma unroll
        for (int b = 0; b < BB; b++) acc[b] += xs[b][f] * w;
    }
#pragma unroll
    for (int b = 0; b < BB; b++)
        part[((long)blockIdx.y * BB + b) * DD + n] = acc[b];
}

__global__ void fc3a_reduce_kernel(const float* __restrict__ part, float* __restrict__ y) {
    int id = blockIdx.x * 256 + threadIdx.x;
    int b = id >> 10, n = id & 1023;
    float s = 0.f;
#pragma unroll 4
    for (int c = 0; c < 256; c++) s += part[((long)c * BB + b) * DD + n];
    y[id] = s;
}

// ================= fc3b: [16,1024] @ [1024,1024] =================
__global__ void small_gemm_kernel(const float* __restrict__ A, const float* __restrict__ W,
                                  float* __restrict__ C, int K, int N) {
    int n = blockIdx.x * 256 + threadIdx.x;
    int b = blockIdx.y;
    float acc = 0.f;
#pragma unroll 4
    for (int k = 0; k < K; k++) acc += A[(long)b * K + k] * W[(long)k * N + n];
    C[(long)b * N + n] = acc;
}

// ================= heads =================
__global__ void heads_kernel(const float* __restrict__ x2,
                             const float* __restrict__ Wr, const float* __restrict__ br,
                             const float* __restrict__ Wt, const float* __restrict__ bt,
                             float* __restrict__ out) {
    int b = blockIdx.x;
    int w = threadIdx.x >> 5, lane = threadIdx.x & 31;
    __shared__ float vals[7];
    if (w < 7) {
        const float* Wp = (w < 4) ? Wr : Wt;
        int ncol = (w < 4) ? 4 : 3;
        int j = (w < 4) ? w : (w - 4);
        float acc = 0.f;
        for (int k = lane; k < DD; k += 32) acc += x2[(long)b * DD + k] * Wp[(long)k * ncol + j];
        for (int o = 16; o > 0; o >>= 1) acc += __shfl_down_sync(0xffffffffu, acc, o);
        if (lane == 0) vals[w] = acc + ((w < 4) ? br[j] : bt[j]);
    }
    __syncthreads();
    if (threadIdx.x == 0) {
        float nn = sqrtf(vals[0]*vals[0] + vals[1]*vals[1] + vals[2]*vals[2] + vals[3]*vals[3]);
        nn = fmaxf(nn, 1e-12f);
        for (int j = 0; j < 4; j++) out[b * 4 + j] = vals[j] / nn;
        for (int j = 0; j < 3; j++) out[64 + b * 3 + j] = vals[4 + j];
    }
}

// ================= host driver =================
extern "C" void kernel_launch(void* const* d_in, const int* in_sizes, int n_in,
                              void* d_out, int out_size) {
    const float* sgm_feats = nullptr; const float* velo_feats = nullptr;
    const int* sbidx = nullptr; const int* vbidx = nullptr;
    int N_sgm = 0, N_velo = 0;
    const float* w[22]; int wi = 0;
    for (int i = 0; i < n_in; i++) {
        int s = in_sizes[i];
        if (s == 3000 * 1024)      { sgm_feats = (const float*)d_in[i]; }
        else if (s == 6000 * 1024) { velo_feats = (const float*)d_in[i]; }
        else if (s == 3000)        { sbidx = (const int*)d_in[i]; N_sgm = s; }
        else if (s == 6000)        { vbidx = (const int*)d_in[i]; N_velo = s; }
        else if (wi < 22)          { w[wi++] = (const float*)d_in[i]; }
    }
    const float *Wq = w[0], *gq = w[1], *bq = w[2];
    const float *Wk = w[3], *gk = w[4], *bk = w[5];
    const float *Wv1 = w[6], *gv1 = w[7], *bv1 = w[8];
    const float *Wv2 = w[9], *gv2 = w[10], *bv2 = w[11];
    const float *W3a = w[12], *g3a = w[13], *b3a = w[14];
    const float *W3b = w[15], *g3b = w[16], *b3b = w[17];
    const float *Wr = w[18], *brr = w[19], *Wt = w[20], *btt = w[21];

    float* fb = nullptr;
    cudaGetSymbolAddress((void**)&fb, g_buf);
    __nv_bfloat16* bb = nullptr;
    cudaGetSymbolAddress((void**)&bb, g_bf);

    float* dTMP  = fb + OFF_TMP;
    float* dV1F  = fb + OFF_V1F;
    float* dX    = fb + OFF_X;
    float* dATT  = fb + OFF_ATTNF;
    float* dPART = fb + OFF_PART;
    float* dY    = fb + OFF_Y;
    float* dX1   = fb + OFF_X1;
    float* dX2   = fb + OFF_X2;
    float* out   = (float*)d_out;

    cudaFuncSetAttribute(mma_gemm, cudaFuncAttributeMaxDynamicSharedMemorySize, MG_SMEM);

    // 1. zero + scatter (fp32 -> hi/lo bf16 dense)
    zero_bf_kernel<<<(int)((12582912L * 2 / 16 + 255) / 256), 256>>>();
    scatter_split_kernel<<<N_sgm, 256>>>(sgm_feats, sbidx, N_sgm, bb + BO_SGMH, bb + BO_SGML, SS);
    scatter_split_kernel<<<N_velo, 256>>>(velo_feats, vbidx, N_velo, bb + BO_VELOH, bb + BO_VELOL, TT);

    // 2. transpose+split weights: W[K][N] -> WT[N][K] hi/lo
    transpose_split_kernel<<<dim3(32, 32, 1), 256>>>(Wq,  bb + BO_WQTH,  bb + BO_WQTL,  1024, 1024, 0, 0);
    transpose_split_kernel<<<dim3(32, 32, 1), 256>>>(Wk,  bb + BO_WKTH,  bb + BO_WKTL,  1024, 1024, 0, 0);
    transpose_split_kernel<<<dim3(16, 32, 1), 256>>>(Wv1, bb + BO_WV1TH, bb + BO_WV1TL, 1024, 512, 0, 0);
    transpose_split_kernel<<<dim3(16, 32, 1), 256>>>(Wv2, bb + BO_WV2TH, bb + BO_WV2TL, 1024, 512, 0, 0);

    // 3. q = relu(ln(sgm @ Wq)) -> hi/lo
    mma_gemm<<<dim3(8, 16, 1), 256, MG_SMEM>>>(bb + BO_SGMH, bb + BO_SGML,
                                               bb + BO_WQTH, bb + BO_WQTL,
                                               dTMP, DD, DD, 0, 0, 0);
    ln_relu_kernel<<<BB * SS, 256>>>(dTMP, gq, bq, nullptr, DD, 1 << 20, 0, DD,
                                     bb + BO_QH, bb + BO_QL);

    // 4. k = relu(ln(velo @ Wk)) -> hi/lo
    mma_gemm<<<dim3(8, 32, 1), 256, MG_SMEM>>>(bb + BO_VELOH, bb + BO_VELOL,
                                               bb + BO_WKTH, bb + BO_WKTL,
                                               dTMP, DD, DD, 0, 0, 0);
    ln_relu_kernel<<<BB * TT, 256>>>(dTMP, gk, bk, nullptr, DD, 1 << 20, 0, DD,
                                     bb + BO_KH, bb + BO_KL);

    // 5. v1 = relu(ln(velo @ Wv1)) -> fp32, then batched transpose-split -> v1T
    mma_gemm<<<dim3(4, 32, 1), 256, MG_SMEM>>>(bb + BO_VELOH, bb + BO_VELOL,
                                               bb + BO_WV1TH, bb + BO_WV1TL,
                                               dTMP, DD, 512, 0, 0, 0);
    ln_relu_kernel<<<BB * TT, 256>>>(dTMP, gv1, bv1, dV1F, 512, 1 << 20, 0, 512,
                                     nullptr, nullptr);
    transpose_split_kernel<<<dim3(16, 8, BB), 256>>>(dV1F, bb + BO_V1TH, bb + BO_V1TL,
                                                     TT, 512, (long)TT * 512, (long)TT * 512);

    // 6. v2 = relu(ln(sgm @ Wv2)) -> X[:, s*1024 + 0..511]
    mma_gemm<<<dim3(4, 16, 1), 256, MG_SMEM>>>(bb + BO_SGMH, bb + BO_SGML,
                                               bb + BO_WV2TH, bb + BO_WV2TL,
                                               dTMP, DD, 512, 0, 0, 0);
    ln_relu_kernel<<<BB * SS, 256>>>(dTMP, gv2, bv2, dX, 512, SS, (long)FIN, DD,
                                     nullptr, nullptr);

    // 7. scores = q @ k^T (batched), softmax, split
    mma_gemm<<<dim3(2, 1, BB), 256, MG_SMEM>>>(bb + BO_QH, bb + BO_QL,
                                               bb + BO_KH, bb + BO_KL,
                                               dATT, DD, TT,
                                               (long)SS * DD, (long)TT * DD, (long)SS * TT);
    softmax256_kernel<<<BB * SS, 256>>>(dATT);
    split_kernel<<<(int)((524288L / 4 + 255) / 256), 256>>>(dATT, bb + BO_ATH, bb + BO_ATL, 524288L / 4);

    // 8. ctx = attn @ v1 -> X[:, s*1024 + 512..1023]
    mma_gemm<<<dim3(4, 1, BB), 256, MG_SMEM>>>(bb + BO_ATH, bb + BO_ATL,
                                               bb + BO_V1TH, bb + BO_V1TL,
                                               dX + 512, TT, DD,
                                               (long)SS * TT, (long)512 * TT, (long)FIN);

    // 9. fc3a (HBM streaming) + LN -> x1
    fc3a_partial_kernel<<<dim3(DD / 256, FIN / 512), 256>>>(dX, W3a, dPART);
    fc3a_reduce_kernel<<<(BB * DD) / 256, 256>>>(dPART, dY);
    ln_relu_kernel<<<BB, 256>>>(dY, g3a, b3a, dX1, DD, 1 << 20, 0, DD, nullptr, nullptr);

    // 10. fc3b + LN -> x2
    small_gemm_kernel<<<dim3(DD / 256, BB), 256>>>(dX1, W3b, dTMP, DD, DD);
    ln_relu_kernel<<<BB, 256>>>(dTMP, g3b, b3b, dX2, DD, 1 << 20, 0, DD, nullptr, nullptr);

    // 11. heads
    heads_kernel<<<BB, 256>>>(dX2, Wr, brr, Wt, btt, out);
    (void)out_size;
}

// round 4
// speedup vs baseline: 1.8975x; 1.0540x over previous
#include <cuda_runtime.h>
#include <cuda_bf16.h>
#include <math.h>
#include <stdint.h>

// ---------------- problem constants ----------------
#define BB   16
#define SS   128
#define TT   256
#define DD   1024
#define FIN  (DD * SS)          // 131072
#define LN_EPS 1e-5f

// ---------------- fp32 scratch (floats) ----------------
#define OFF_TMP   0L             // 6291456 (4096 x 1536)
#define OFF_V1F   6291456L       // 2097152 (16*256*512)
#define OFF_X     8388608L       // 2097152 (16*131072)
#define OFF_ATTNF 10485760L      // 524288  (16*128*256)
#define OFF_PART  11010048L      // 4194304 (256*16*1024)
#define OFF_Y     15204352L      // 16384
#define OFF_X1    15220736L
#define OFF_X2    15237120L
#define FBUF_TOTAL 15253504L
__device__ __align__(128) float g_buf[FBUF_TOTAL];

// ---------------- bf16 scratch (elements) ----------------
#define BO_SGMH   0L             // 2097152
#define BO_SGML   2097152L
#define BO_VELOH  4194304L       // 4194304
#define BO_VELOL  8388608L
#define BO_QH     12582912L      // 2097152
#define BO_QL     14680064L
#define BO_KH     16777216L      // 4194304
#define BO_KL     20971520L
#define BO_WQV2H  25165824L      // 1572864 ([1536][1024]: rows 0..1023 WqT, 1024..1535 Wv2T)
#define BO_WQV2L  26738688L
#define BO_WKV1H  28311552L      // 1572864 (rows 0..1023 WkT, 1024..1535 Wv1T)
#define BO_WKV1L  29884416L
#define BO_V1TH   31457280L      // 2097152 ([16][512][256])
#define BO_V1TL   33554432L
#define BO_ATH    35651584L      // 524288
#define BO_ATL    36175872L
#define BBUF_TOTAL 36700160L
__device__ __align__(128) __nv_bfloat16 g_bf[BBUF_TOTAL];

// ================= PTX helpers (baseline ISA, plain sm_103) =======
__device__ __forceinline__ uint32_t smem_u32(const void* p) {
    uint32_t a;
    asm("{ .reg .u64 t; cvta.to.shared.u64 t, %1; cvt.u32.u64 %0, t; }" : "=r"(a) : "l"(p));
    return a;
}
__device__ __forceinline__ void cpasync16(uint32_t dst, const void* src) {
    asm volatile("cp.async.cg.shared.global [%0], [%1], 16;" :: "r"(dst), "l"(src));
}
#define CP_COMMIT() asm volatile("cp.async.commit_group;" ::: "memory")
#define CP_WAIT(n)  asm volatile("cp.async.wait_group %0;" :: "n"(n) : "memory")

__device__ __forceinline__ void ldm_x4(uint32_t addr, uint32_t* r) {
    asm volatile("ldmatrix.sync.aligned.m8n8.x4.shared.b16 {%0,%1,%2,%3}, [%4];"
                 : "=r"(r[0]), "=r"(r[1]), "=r"(r[2]), "=r"(r[3]) : "r"(addr));
}
__device__ __forceinline__ void mma16816(float* d, const uint32_t* a, const uint32_t* b) {
    asm volatile("mma.sync.aligned.m16n8k16.row.col.f32.bf16.bf16.f32 "
                 "{%0,%1,%2,%3}, {%4,%5,%6,%7}, {%8,%9}, {%0,%1,%2,%3};"
                 : "+f"(d[0]), "+f"(d[1]), "+f"(d[2]), "+f"(d[3])
                 : "r"(a[0]), "r"(a[1]), "r"(a[2]), "r"(a[3]), "r"(b[0]), "r"(b[1]));
}

// ---------------- hi/lo split helpers ----------------
__device__ __forceinline__ void split2(float a, float b, unsigned& h, unsigned& l) {
    __nv_bfloat162 hh = __floats2bfloat162_rn(a, b);
    float ra = a - __bfloat162float(__low2bfloat16(hh));
    float rb = b - __bfloat162float(__high2bfloat16(hh));
    __nv_bfloat162 ll = __floats2bfloat162_rn(ra, rb);
    h = *reinterpret_cast<unsigned*>(&hh);
    l = *reinterpret_cast<unsigned*>(&ll);
}

// ================= zero dense bf16 buffers =================
__global__ void zero_bf_kernel() {
    long i = (long)blockIdx.x * blockDim.x + threadIdx.x;    // uint4 index
    const long n = (12582912L * 2) / 16;                     // sgm+velo hi/lo
    if (i < n) reinterpret_cast<uint4*>(g_bf)[i] = make_uint4(0, 0, 0, 0);
}

// ================= scatter ragged rows -> dense hi/lo bf16 =================
__global__ void scatter_split_kernel(const float* __restrict__ feats,
                                     const int* __restrict__ bidx, int N,
                                     __nv_bfloat16* __restrict__ dh,
                                     __nv_bfloat16* __restrict__ dl, int local) {
    int i = blockIdx.x;
    int b = bidx[i];
    __shared__ int s_rank;
    if (threadIdx.x == 0) {
        int lo = 0, hi = N;
        while (lo < hi) { int mid = (lo + hi) >> 1; if (bidx[mid] < b) lo = mid + 1; else hi = mid; }
        s_rank = i - lo;
    }
    __syncthreads();
    int r = s_rank;
    if (r >= local) return;
    long row = (long)b * local + r;
    const float4 v = *reinterpret_cast<const float4*>(feats + (long)i * DD + threadIdx.x * 4);
    uint2 h, l;
    split2(v.x, v.y, h.x, l.x);
    split2(v.z, v.w, h.y, l.y);
    *reinterpret_cast<uint2*>(dh + row * DD + threadIdx.x * 4) = h;
    *reinterpret_cast<uint2*>(dl + row * DD + threadIdx.x * 4) = l;
}

// ================= transpose + split: in[R][C] fp32 -> out[C][R] bf16 hi/lo ===
__global__ void transpose_split_kernel(const float* __restrict__ in,
                                       __nv_bfloat16* __restrict__ oh,
                                       __nv_bfloat16* __restrict__ ol,
                                       int R, int C, long inB, long outB) {
    __shared__ float t[32][33];
    int z = blockIdx.z;
    in += (long)z * inB; oh += (long)z * outB; ol += (long)z * outB;
    int r0 = blockIdx.y * 32, c0 = blockIdx.x * 32;
    int tx = threadIdx.x & 31, ty = threadIdx.x >> 5;   // 256 threads: ty 0..7
#pragma unroll
    for (int i = 0; i < 32; i += 8)
        t[ty + i][tx] = in[(long)(r0 + ty + i) * C + c0 + tx];
    __syncthreads();
#pragma unroll
    for (int i = 0; i < 32; i += 8) {
        float v = t[tx][ty + i];
        __nv_bfloat16 h = __float2bfloat16(v);
        __nv_bfloat16 l = __float2bfloat16(v - __bfloat162float(h));
        long o = (long)(c0 + ty + i) * R + r0 + tx;
        oh[o] = h; ol[o] = l;
    }
}

// ================= templated HMMA GEMM: C = A[M,K] @ B[N,K]^T ================
// CTA tile BM x BN, warps WM_CNT x WN_CNT, k-chunk 32, cp.async double buffer.
// smem stage: Ah[BM][32] @0, Al @BM*64, Bh @2*BM*64, Bl @(2*BM+BN)*64.
// Row = 64B as 4x16B chunks, swizzle chunk' = chunk ^ (row&3).
template<int BM, int BN, int WM_CNT, int WN_CNT>
__global__ __launch_bounds__(32 * WM_CNT * WN_CNT)
void mma_gemm_t(const __nv_bfloat16* __restrict__ Ahp, const __nv_bfloat16* __restrict__ Alp,
                const __nv_bfloat16* __restrict__ Bhp, const __nv_bfloat16* __restrict__ Blp,
                float* __restrict__ C, int K, int ldc,
                long aB, long bB, long cB) {
    constexpr int T   = 32 * WM_CNT * WN_CNT;
    constexpr int WTM = BM / WM_CNT, WTN = BN / WN_CNT;
    constexpr int MI  = WTM / 16;       // a 16-row blocks per warp
    constexpr int NB  = WTN / 16;       // b 16-row blocks per warp
    constexpr int NJ  = WTN / 8;        // n8 fragments per warp
    constexpr int OAL = BM * 64, OBH = 2 * BM * 64, OBL = OBH + BN * 64;
    constexpr int STAGE = 2 * (BM + BN) * 64;
    constexpr int RPT = T >> 2;
    constexpr int AIT = BM / RPT, BIT = BN / RPT;

    extern __shared__ char smem[];
    const uint32_t sb = smem_u32(smem);
    const int tid = threadIdx.x, lane = tid & 31, wid = tid >> 5;
    const int wm = wid % WM_CNT, wn = wid / WM_CNT;
    const int z = blockIdx.z;
    const long m0 = (long)blockIdx.y * BM, n0 = (long)blockIdx.x * BN;

    const __nv_bfloat16* Ah = Ahp + (long)z * aB + m0 * K;
    const __nv_bfloat16* Al = Alp + (long)z * aB + m0 * K;
    const __nv_bfloat16* Bh = Bhp + (long)z * bB + n0 * K;
    const __nv_bfloat16* Bl = Blp + (long)z * bB + n0 * K;
    float* Cp = C + (long)z * cB + m0 * ldc + n0;

    const int r_ld = tid >> 2, c_ld = tid & 3;

    float acc[MI][NJ][4];
#pragma unroll
    for (int i = 0; i < MI; i++)
#pragma unroll
        for (int j = 0; j < NJ; j++)
#pragma unroll
            for (int q = 0; q < 4; q++) acc[i][j][q] = 0.f;

    const int NC = K >> 5;

    auto load_chunk = [&](int ci, int st) {
        const int k0 = ci << 5;
        const uint32_t s0 = sb + (uint32_t)st * STAGE;
#pragma unroll
        for (int i = 0; i < AIT; i++) {
            int r = r_ld + i * RPT;
            uint32_t d = (uint32_t)(r * 64 + ((c_ld ^ (r & 3)) << 4));
            long go = (long)r * K + k0 + c_ld * 8;
            cpasync16(s0 + d,       Ah + go);
            cpasync16(s0 + OAL + d, Al + go);
        }
#pragma unroll
        for (int i = 0; i < BIT; i++) {
            int r = r_ld + i * RPT;
            uint32_t d = (uint32_t)(r * 64 + ((c_ld ^ (r & 3)) << 4));
            long go = (long)r * K + k0 + c_ld * 8;
            cpasync16(s0 + OBH + d, Bh + go);
            cpasync16(s0 + OBL + d, Bl + go);
        }
    };

    const int a_sub = ((lane >> 3) & 1) * 8 + (lane & 7);
    const int a_kc = lane >> 4;
    const int b_sub = ((lane >> 4) & 1) * 8 + (lane & 7);
    const int b_kc = (lane >> 3) & 1;

    load_chunk(0, 0); CP_COMMIT();

    for (int i = 0; i < NC; i++) {
        if (i + 1 < NC) { load_chunk(i + 1, (i + 1) & 1); CP_COMMIT(); CP_WAIT(1); }
        else            { CP_WAIT(0); }
        __syncthreads();
        const uint32_t s0 = sb + ((i & 1) ? (uint32_t)STAGE : 0u);
#pragma unroll
        for (int ks = 0; ks < 2; ks++) {
            uint32_t ah[MI][4], al[MI][4], bh[NJ][2], bl[NJ][2];
#pragma unroll
            for (int mi = 0; mi < MI; mi++) {
                int mrow = wm * WTM + mi * 16 + a_sub;
                int kc = ks * 2 + a_kc;
                uint32_t ad = s0 + mrow * 64 + ((kc ^ (mrow & 3)) << 4);
                ldm_x4(ad, ah[mi]);
                ldm_x4(ad + OAL, al[mi]);
            }
#pragma unroll
            for (int np = 0; np < NB; np++) {
                int nrow = wn * WTN + np * 16 + b_sub;
                int kc = ks * 2 + b_kc;
                uint32_t bd = s0 + OBH + nrow * 64 + ((kc ^ (nrow & 3)) << 4);
                uint32_t t4[4];
                ldm_x4(bd, t4);
                bh[np * 2][0] = t4[0]; bh[np * 2][1] = t4[1];
                bh[np * 2 + 1][0] = t4[2]; bh[np * 2 + 1][1] = t4[3];
                ldm_x4(bd + BN * 64, t4);
                bl[np * 2][0] = t4[0]; bl[np * 2][1] = t4[1];
                bl[np * 2 + 1][0] = t4[2]; bl[np * 2 + 1][1] = t4[3];
            }
#pragma unroll
            for (int mi = 0; mi < MI; mi++)
#pragma unroll
                for (int nj = 0; nj < NJ; nj++) {
                    mma16816(acc[mi][nj], ah[mi], bh[nj]);
                    mma16816(acc[mi][nj], ah[mi], bl[nj]);
                    mma16816(acc[mi][nj], al[mi], bh[nj]);
                }
        }
        __syncthreads();
    }

    const int er = lane >> 2, ec = (lane & 3) * 2;
    const long mb = wm * WTM + er;
    const int nb = wn * WTN + ec;
#pragma unroll
    for (int mi = 0; mi < MI; mi++)
#pragma unroll
        for (int nj = 0; nj < NJ; nj++) {
            float* p0 = Cp + (mb + mi * 16) * ldc + nb + nj * 8;
            float* p1 = p0 + 8L * ldc;
            *reinterpret_cast<float2*>(p0) = make_float2(acc[mi][nj][0], acc[mi][nj][1]);
            *reinterpret_cast<float2*>(p1) = make_float2(acc[mi][nj][2], acc[mi][nj][3]);
        }
}

// ================= dual LayerNorm+ReLU on merged GEMM rows ==================
// row = blockIdx.x over [ldin] cols: seg1 = cols [0,1024) -> LN(g1,b1), ReLU,
// bf16 hi/lo at row*1024; seg2 = cols [1024,1536) -> LN(g2,b2), ReLU, fp32 at
// out2 + (row/rpb)*ob + (row%rpb)*orr.
__global__ void dual_ln_kernel(const float* __restrict__ in, int ldin,
                               const float* __restrict__ g1, const float* __restrict__ b1,
                               __nv_bfloat16* __restrict__ oh, __nv_bfloat16* __restrict__ ol,
                               const float* __restrict__ g2, const float* __restrict__ b2,
                               float* __restrict__ out2, int rpb, long ob, long orr) {
    int row = blockIdx.x, t = threadIdx.x;
    const float* ip = in + (long)row * ldin;
    __shared__ float rs[256], rq[256];

    float va[4]; float s = 0.f, ss = 0.f;
#pragma unroll
    for (int i = 0; i < 4; i++) { va[i] = ip[t + 256 * i]; s += va[i]; ss += va[i] * va[i]; }
    rs[t] = s; rq[t] = ss;
    __syncthreads();
    for (int o = 128; o > 0; o >>= 1) {
        if (t < o) { rs[t] += rs[t + o]; rq[t] += rq[t + o]; }
        __syncthreads();
    }
    float mean = rs[0] * (1.f / 1024.f);
    float var = rq[0] * (1.f / 1024.f) - mean * mean;
    float r = rsqrtf(var + LN_EPS);
    __syncthreads();
#pragma unroll
    for (int i = 0; i < 4; i++) {
        int c = t + 256 * i;
        float v = (va[i] - mean) * r * g1[c] + b1[c];
        v = fmaxf(v, 0.f);
        __nv_bfloat16 h = __float2bfloat16(v);
        oh[(long)row * 1024 + c] = h;
        ol[(long)row * 1024 + c] = __float2bfloat16(v - __bfloat162float(h));
    }

    float vb[2]; s = 0.f; ss = 0.f;
#pragma unroll
    for (int i = 0; i < 2; i++) { vb[i] = ip[1024 + t + 256 * i]; s += vb[i]; ss += vb[i] * vb[i]; }
    rs[t] = s; rq[t] = ss;
    __syncthreads();
    for (int o = 128; o > 0; o >>= 1) {
        if (t < o) { rs[t] += rs[t + o]; rq[t] += rq[t + o]; }
        __syncthreads();
    }
    mean = rs[0] * (1.f / 512.f);
    var = rq[0] * (1.f / 512.f) - mean * mean;
    r = rsqrtf(var + LN_EPS);
    float* op = out2 + (long)(row / rpb) * ob + (long)(row % rpb) * orr;
#pragma unroll
    for (int i = 0; i < 2; i++) {
        int c = t + 256 * i;
        float v = (vb[i] - mean) * r * g2[c] + b2[c];
        op[c] = fmaxf(v, 0.f);
    }
}

// ================= plain LN+ReLU (fp32 out) =================
__global__ void ln_relu_kernel(const float* __restrict__ in,
                               const float* __restrict__ gamma,
                               const float* __restrict__ beta,
                               float* __restrict__ outp, int C) {
    int row = blockIdx.x;
    int t = threadIdx.x;
    const float* ip = in + (long)row * C;
    float s = 0.f, ss = 0.f;
    for (int c = t; c < C; c += 256) { float v = ip[c]; s += v; ss += v * v; }
    __shared__ float rs[256], rq[256];
    rs[t] = s; rq[t] = ss;
    __syncthreads();
    for (int o = 128; o > 0; o >>= 1) {
        if (t < o) { rs[t] += rs[t + o]; rq[t] += rq[t + o]; }
        __syncthreads();
    }
    float mean = rs[0] / C;
    float var = rq[0] / C - mean * mean;
    float r = rsqrtf(var + LN_EPS);
    float* op = outp + (long)row * C;
    for (int c = t; c < C; c += 256) {
        float v = (ip[c] - mean) * r * gamma[c] + beta[c];
        op[c] = fmaxf(v, 0.f);
    }
}

// ================= softmax (256 wide) -> bf16 hi/lo directly ================
__global__ void softmax_bf_kernel(const float* __restrict__ sc,
                                  __nv_bfloat16* __restrict__ oh,
                                  __nv_bfloat16* __restrict__ ol) {
    int row = blockIdx.x;
    int t = threadIdx.x;
    float v = sc[(long)row * 256 + t];
    __shared__ float red[256];
    red[t] = v;
    __syncthreads();
    for (int o = 128; o > 0; o >>= 1) { if (t < o) red[t] = fmaxf(red[t], red[t + o]); __syncthreads(); }
    float mx = red[0];
    __syncthreads();
    float e = __expf(v - mx);
    red[t] = e;
    __syncthreads();
    for (int o = 128; o > 0; o >>= 1) { if (t < o) red[t] += red[t + o]; __syncthreads(); }
    float p = e / red[0];
    __nv_bfloat16 h = __float2bfloat16(p);
    oh[(long)row * 256 + t] = h;
    ol[(long)row * 256 + t] = __float2bfloat16(p - __bfloat162float(h));
}

// ================= fc3a: streaming split-K over W3a =================
__global__ __launch_bounds__(256)
void fc3a_partial_kernel(const float* __restrict__ x, const float* __restrict__ W,
                         float* __restrict__ part) {
    __shared__ float xs[BB][512];
    int n = blockIdx.x * 256 + threadIdx.x;
    int f0 = blockIdx.y * 512;
    for (int i = threadIdx.x; i < BB * 512; i += 256) {
        int b = i >> 9, f = i & 511;
        xs[b][f] = x[(long)b * FIN + f0 + f];
    }
    __syncthreads();
    float acc[BB];
#pragma unroll
    for (int b = 0; b < BB; b++) acc[b] = 0.f;
#pragma unroll 4
    for (int f = 0; f < 512; f++) {
        float w = W[(long)(f0 + f) * DD + n];
#pragma unroll
        for (int b = 0; b < BB; b++) acc[b] += xs[b][f] * w;
    }
#pragma unroll
    for (int b = 0; b < BB; b++)
        part[((long)blockIdx.y * BB + b) * DD + n] = acc[b];
}

__global__ void fc3a_reduce_kernel(const float* __restrict__ part, float* __restrict__ y) {
    int id = blockIdx.x * 256 + threadIdx.x;
    int b = id >> 10, n = id & 1023;
    float s = 0.f;
#pragma unroll 4
    for (int c = 0; c < 256; c++) s += part[((long)c * BB + b) * DD + n];
    y[id] = s;
}

// ================= fc3b: [16,1024] @ [1024,1024] =================
__global__ void small_gemm_kernel(const float* __restrict__ A, const float* __restrict__ W,
                                  float* __restrict__ C, int K, int N) {
    int n = blockIdx.x * 256 + threadIdx.x;
    int b = blockIdx.y;
    float acc = 0.f;
#pragma unroll 4
    for (int k = 0; k < K; k++) acc += A[(long)b * K + k] * W[(long)k * N + n];
    C[(long)b * N + n] = acc;
}

// ================= heads =================
__global__ void heads_kernel(const float* __restrict__ x2,
                             const float* __restrict__ Wr, const float* __restrict__ br,
                             const float* __restrict__ Wt, const float* __restrict__ bt,
                             float* __restrict__ out) {
    int b = blockIdx.x;
    int w = threadIdx.x >> 5, lane = threadIdx.x & 31;
    __shared__ float vals[7];
    if (w < 7) {
        const float* Wp = (w < 4) ? Wr : Wt;
        int ncol = (w < 4) ? 4 : 3;
        int j = (w < 4) ? w : (w - 4);
        float acc = 0.f;
        for (int k = lane; k < DD; k += 32) acc += x2[(long)b * DD + k] * Wp[(long)k * ncol + j];
        for (int o = 16; o > 0; o >>= 1) acc += __shfl_down_sync(0xffffffffu, acc, o);
        if (lane == 0) vals[w] = acc + ((w < 4) ? br[j] : bt[j]);
    }
    __syncthreads();
    if (threadIdx.x == 0) {
        float nn = sqrtf(vals[0]*vals[0] + vals[1]*vals[1] + vals[2]*vals[2] + vals[3]*vals[3]);
        nn = fmaxf(nn, 1e-12f);
        for (int j = 0; j < 4; j++) out[b * 4 + j] = vals[j] / nn;
        for (int j = 0; j < 3; j++) out[64 + b * 3 + j] = vals[4 + j];
    }
}

// ================= host driver =================
extern "C" void kernel_launch(void* const* d_in, const int* in_sizes, int n_in,
                              void* d_out, int out_size) {
    const float* sgm_feats = nullptr; const float* velo_feats = nullptr;
    const int* sbidx = nullptr; const int* vbidx = nullptr;
    int N_sgm = 0, N_velo = 0;
    const float* w[22]; int wi = 0;
    for (int i = 0; i < n_in; i++) {
        int s = in_sizes[i];
        if (s == 3000 * 1024)      { sgm_feats = (const float*)d_in[i]; }
        else if (s == 6000 * 1024) { velo_feats = (const float*)d_in[i]; }
        else if (s == 3000)        { sbidx = (const int*)d_in[i]; N_sgm = s; }
        else if (s == 6000)        { vbidx = (const int*)d_in[i]; N_velo = s; }
        else if (wi < 22)          { w[wi++] = (const float*)d_in[i]; }
    }
    const float *Wq = w[0], *gq = w[1], *bq = w[2];
    const float *Wk = w[3], *gk = w[4], *bk = w[5];
    const float *Wv1 = w[6], *gv1 = w[7], *bv1 = w[8];
    const float *Wv2 = w[9], *gv2 = w[10], *bv2 = w[11];
    const float *W3a = w[12], *g3a = w[13], *b3a = w[14];
    const float *W3b = w[15], *g3b = w[16], *b3b = w[17];
    const float *Wr = w[18], *brr = w[19], *Wt = w[20], *btt = w[21];

    float* fb = nullptr;
    cudaGetSymbolAddress((void**)&fb, g_buf);
    __nv_bfloat16* bb = nullptr;
    cudaGetSymbolAddress((void**)&bb, g_bf);

    float* dTMP  = fb + OFF_TMP;
    float* dV1F  = fb + OFF_V1F;
    float* dX    = fb + OFF_X;
    float* dATT  = fb + OFF_ATTNF;
    float* dPART = fb + OFF_PART;
    float* dY    = fb + OFF_Y;
    float* dX1   = fb + OFF_X1;
    float* dX2   = fb + OFF_X2;
    float* out   = (float*)d_out;

    // big-tile variant: 128x128, 8 warps; small-tile: 64x64, 4 warps
    constexpr int SMEM_A = 2 * 2 * (128 + 128) * 64;   // 65536
    constexpr int SMEM_B = 2 * 2 * (64 + 64) * 64;     // 32768
    cudaFuncSetAttribute(mma_gemm_t<128, 128, 4, 2>,
                         cudaFuncAttributeMaxDynamicSharedMemorySize, SMEM_A);

    // 1. zero + scatter (fp32 -> hi/lo bf16 dense)
    zero_bf_kernel<<<(int)((12582912L * 2 / 16 + 255) / 256), 256>>>();
    scatter_split_kernel<<<N_sgm, 256>>>(sgm_feats, sbidx, N_sgm, bb + BO_SGMH, bb + BO_SGML, SS);
    scatter_split_kernel<<<N_velo, 256>>>(velo_feats, vbidx, N_velo, bb + BO_VELOH, bb + BO_VELOL, TT);

    // 2. transpose+split weights into merged [1536][1024] layouts
    transpose_split_kernel<<<dim3(32, 32, 1), 256>>>(Wq,  bb + BO_WQV2H, bb + BO_WQV2L, 1024, 1024, 0, 0);
    transpose_split_kernel<<<dim3(16, 32, 1), 256>>>(Wv2, bb + BO_WQV2H + 1048576L,
                                                     bb + BO_WQV2L + 1048576L, 1024, 512, 0, 0);
    transpose_split_kernel<<<dim3(32, 32, 1), 256>>>(Wk,  bb + BO_WKV1H, bb + BO_WKV1L, 1024, 1024, 0, 0);
    transpose_split_kernel<<<dim3(16, 32, 1), 256>>>(Wv1, bb + BO_WKV1H + 1048576L,
                                                     bb + BO_WKV1L + 1048576L, 1024, 512, 0, 0);

    // 3. [q | v2] = sgm @ [WqT | Wv2T]^T  (M=2048, N=1536)
    mma_gemm_t<128, 128, 4, 2><<<dim3(12, 16, 1), 256, SMEM_A>>>(
        bb + BO_SGMH, bb + BO_SGML, bb + BO_WQV2H, bb + BO_WQV2L,
        dTMP, DD, 1536, 0, 0, 0);
    dual_ln_kernel<<<BB * SS, 256>>>(dTMP, 1536, gq, bq, bb + BO_QH, bb + BO_QL,
                                     gv2, bv2, dX, SS, (long)FIN, DD);

    // 4. [k | v1] = velo @ [WkT | Wv1T]^T  (M=4096, N=1536)
    mma_gemm_t<128, 128, 4, 2><<<dim3(12, 32, 1), 256, SMEM_A>>>(
        bb + BO_VELOH, bb + BO_VELOL, bb + BO_WKV1H, bb + BO_WKV1L,
        dTMP, DD, 1536, 0, 0, 0);
    dual_ln_kernel<<<BB * TT, 256>>>(dTMP, 1536, gk, bk, bb + BO_KH, bb + BO_KL,
                                     gv1, bv1, dV1F, 1 << 20, 0, 512);

    // 5. v1T: [16][256][512] -> [16][512][256] hi/lo
    transpose_split_kernel<<<dim3(16, 8, BB), 256>>>(dV1F, bb + BO_V1TH, bb + BO_V1TL,
                                                     TT, 512, (long)TT * 512, (long)TT * 512);

    // 6. scores = q @ k^T (batched, 64x64 tiles -> 128 CTAs), softmax -> bf16
    mma_gemm_t<64, 64, 2, 2><<<dim3(4, 2, BB), 128, SMEM_B>>>(
        bb + BO_QH, bb + BO_QL, bb + BO_KH, bb + BO_KL,
        dATT, DD, TT, (long)SS * DD, (long)TT * DD, (long)SS * TT);
    softmax_bf_kernel<<<BB * SS, 256>>>(dATT, bb + BO_ATH, bb + BO_ATL);

    // 7. ctx = attn @ v1 -> X[:, s*1024 + 512..1023] (64x64 tiles -> 256 CTAs)
    mma_gemm_t<64, 64, 2, 2><<<dim3(8, 2, BB), 128, SMEM_B>>>(
        bb + BO_ATH, bb + BO_ATL, bb + BO_V1TH, bb + BO_V1TL,
        dX + 512, TT, DD, (long)SS * TT, (long)512 * TT, (long)FIN);

    // 8. fc3a (HBM streaming) + LN -> x1
    fc3a_partial_kernel<<<dim3(DD / 256, FIN / 512), 256>>>(dX, W3a, dPART);
    fc3a_reduce_kernel<<<(BB * DD) / 256, 256>>>(dPART, dY);
    ln_relu_kernel<<<BB, 256>>>(dY, g3a, b3a, dX1, DD);

    // 9. fc3b + LN -> x2
    small_gemm_kernel<<<dim3(DD / 256, BB), 256>>>(dX1, W3b, dTMP, DD, DD);
    ln_relu_kernel<<<BB, 256>>>(dTMP, g3b, b3b, dX2, DD);

    // 10. heads
    heads_kernel<<<BB, 256>>>(dX2, Wr, brr, Wt, btt, out);
    (void)out_size;
}

// round 5
// speedup vs baseline: 2.1922x; 1.1553x over previous
#include <cuda_runtime.h>
#include <cuda_bf16.h>
#include <math.h>
#include <stdint.h>

// ---------------- problem constants ----------------
#define BB   16
#define SS   128
#define TT   256
#define DD   1024
#define FIN  (DD * SS)          // 131072
#define LN_EPS 1e-5f

// ---------------- fp32 scratch (floats) ----------------
#define OFF_TMP   0L             // 6291456 (4096 x 1536)
#define OFF_V1F   6291456L       // 2097152 (16*256*512)
#define OFF_X     8388608L       // 2097152 (16*131072)
#define OFF_ATTNF 10485760L      // 524288  (16*128*256)
#define OFF_PART  11010048L      // 4194304 (256*16*1024)
#define OFF_Y     15204352L      // 16384
#define OFF_X1    15220736L
#define OFF_X2    15237120L
#define FBUF_TOTAL 15253504L
__device__ __align__(128) float g_buf[FBUF_TOTAL];

// ---------------- bf16 scratch (elements) ----------------
#define BO_SGMH   0L             // 2097152
#define BO_SGML   2097152L
#define BO_VELOH  4194304L       // 4194304
#define BO_VELOL  8388608L
#define BO_QH     12582912L      // 2097152
#define BO_QL     14680064L
#define BO_KH     16777216L      // 4194304
#define BO_KL     20971520L
#define BO_WQV2H  25165824L      // 1572864 ([1536][1024]: rows 0..1023 WqT, 1024..1535 Wv2T)
#define BO_WQV2L  26738688L
#define BO_WKV1H  28311552L      // 1572864 (rows 0..1023 WkT, 1024..1535 Wv1T)
#define BO_WKV1L  29884416L
#define BO_V1TH   31457280L      // 2097152 ([16][512][256])
#define BO_V1TL   33554432L
#define BO_ATH    35651584L      // 524288
#define BO_ATL    36175872L
#define BBUF_TOTAL 36700160L
__device__ __align__(128) __nv_bfloat16 g_bf[BBUF_TOTAL];

// ================= PTX helpers (baseline ISA, plain sm_103) =======
__device__ __forceinline__ uint32_t smem_u32(const void* p) {
    uint32_t a;
    asm("{ .reg .u64 t; cvta.to.shared.u64 t, %1; cvt.u32.u64 %0, t; }" : "=r"(a) : "l"(p));
    return a;
}
__device__ __forceinline__ void cpasync16(uint32_t dst, const void* src) {
    asm volatile("cp.async.cg.shared.global [%0], [%1], 16;" :: "r"(dst), "l"(src));
}
#define CP_COMMIT() asm volatile("cp.async.commit_group;" ::: "memory")
#define CP_WAIT(n)  asm volatile("cp.async.wait_group %0;" :: "n"(n) : "memory")

__device__ __forceinline__ void ldm_x4(uint32_t addr, uint32_t* r) {
    asm volatile("ldmatrix.sync.aligned.m8n8.x4.shared.b16 {%0,%1,%2,%3}, [%4];"
                 : "=r"(r[0]), "=r"(r[1]), "=r"(r[2]), "=r"(r[3]) : "r"(addr));
}
__device__ __forceinline__ void mma16816(float* d, const uint32_t* a, const uint32_t* b) {
    asm volatile("mma.sync.aligned.m16n8k16.row.col.f32.bf16.bf16.f32 "
                 "{%0,%1,%2,%3}, {%4,%5,%6,%7}, {%8,%9}, {%0,%1,%2,%3};"
                 : "+f"(d[0]), "+f"(d[1]), "+f"(d[2]), "+f"(d[3])
                 : "r"(a[0]), "r"(a[1]), "r"(a[2]), "r"(a[3]), "r"(b[0]), "r"(b[1]));
}

// ---------------- hi/lo split helpers ----------------
__device__ __forceinline__ void split2(float a, float b, unsigned& h, unsigned& l) {
    __nv_bfloat162 hh = __floats2bfloat162_rn(a, b);
    float ra = a - __bfloat162float(__low2bfloat16(hh));
    float rb = b - __bfloat162float(__high2bfloat16(hh));
    __nv_bfloat162 ll = __floats2bfloat162_rn(ra, rb);
    h = *reinterpret_cast<unsigned*>(&hh);
    l = *reinterpret_cast<unsigned*>(&ll);
}

// ================= zero dense bf16 buffers =================
__global__ void zero_bf_kernel() {
    long i = (long)blockIdx.x * blockDim.x + threadIdx.x;    // uint4 index
    const long n = (12582912L * 2) / 16;                     // sgm+velo hi/lo
    if (i < n) reinterpret_cast<uint4*>(g_bf)[i] = make_uint4(0, 0, 0, 0);
}

// ================= scatter ragged rows -> dense hi/lo bf16 =================
__global__ void scatter_split_kernel(const float* __restrict__ feats,
                                     const int* __restrict__ bidx, int N,
                                     __nv_bfloat16* __restrict__ dh,
                                     __nv_bfloat16* __restrict__ dl, int local) {
    int i = blockIdx.x;
    int b = bidx[i];
    __shared__ int s_rank;
    if (threadIdx.x == 0) {
        int lo = 0, hi = N;
        while (lo < hi) { int mid = (lo + hi) >> 1; if (bidx[mid] < b) lo = mid + 1; else hi = mid; }
        s_rank = i - lo;
    }
    __syncthreads();
    int r = s_rank;
    if (r >= local) return;
    long row = (long)b * local + r;
    const float4 v = *reinterpret_cast<const float4*>(feats + (long)i * DD + threadIdx.x * 4);
    uint2 h, l;
    split2(v.x, v.y, h.x, l.x);
    split2(v.z, v.w, h.y, l.y);
    *reinterpret_cast<uint2*>(dh + row * DD + threadIdx.x * 4) = h;
    *reinterpret_cast<uint2*>(dl + row * DD + threadIdx.x * 4) = l;
}

// ================= transpose + split: in[R][C] fp32 -> out[C][R] bf16 hi/lo ===
__global__ void transpose_split_kernel(const float* __restrict__ in,
                                       __nv_bfloat16* __restrict__ oh,
                                       __nv_bfloat16* __restrict__ ol,
                                       int R, int C, long inB, long outB) {
    __shared__ float t[32][33];
    int z = blockIdx.z;
    in += (long)z * inB; oh += (long)z * outB; ol += (long)z * outB;
    int r0 = blockIdx.y * 32, c0 = blockIdx.x * 32;
    int tx = threadIdx.x & 31, ty = threadIdx.x >> 5;   // 256 threads: ty 0..7
#pragma unroll
    for (int i = 0; i < 32; i += 8)
        t[ty + i][tx] = in[(long)(r0 + ty + i) * C + c0 + tx];
    __syncthreads();
#pragma unroll
    for (int i = 0; i < 32; i += 8) {
        float v = t[tx][ty + i];
        __nv_bfloat16 h = __float2bfloat16(v);
        __nv_bfloat16 l = __float2bfloat16(v - __bfloat162float(h));
        long o = (long)(c0 + ty + i) * R + r0 + tx;
        oh[o] = h; ol[o] = l;
    }
}

// ================= templated HMMA GEMM: C = A[M,K] @ B[N,K]^T ================
// CTA tile BM x BN, warps WM_CNT x WN_CNT, k-chunk 32, cp.async double buffer.
// smem stage: Ah[BM][32] @0, Al @BM*64, Bh @2*BM*64, Bl @(2*BM+BN)*64.
// Row = 64B as 4x16B chunks, swizzle chunk' = chunk ^ (row&3).
template<int BM, int BN, int WM_CNT, int WN_CNT>
__global__ __launch_bounds__(32 * WM_CNT * WN_CNT, 2)
void mma_gemm_t(const __nv_bfloat16* __restrict__ Ahp, const __nv_bfloat16* __restrict__ Alp,
                const __nv_bfloat16* __restrict__ Bhp, const __nv_bfloat16* __restrict__ Blp,
                float* __restrict__ C, int K, int ldc,
                long aB, long bB, long cB) {
    constexpr int T   = 32 * WM_CNT * WN_CNT;
    constexpr int WTM = BM / WM_CNT, WTN = BN / WN_CNT;
    constexpr int MI  = WTM / 16;       // a 16-row blocks per warp
    constexpr int NB  = WTN / 16;       // b 16-row blocks per warp
    constexpr int NJ  = WTN / 8;        // n8 fragments per warp
    constexpr int OAL = BM * 64, OBH = 2 * BM * 64, OBL = OBH + BN * 64;
    constexpr int STAGE = 2 * (BM + BN) * 64;
    constexpr int RPT = T >> 2;
    constexpr int AIT = BM / RPT, BIT = BN / RPT;

    extern __shared__ char smem[];
    const uint32_t sb = smem_u32(smem);
    const int tid = threadIdx.x, lane = tid & 31, wid = tid >> 5;
    const int wm = wid % WM_CNT, wn = wid / WM_CNT;
    const int z = blockIdx.z;
    const long m0 = (long)blockIdx.y * BM, n0 = (long)blockIdx.x * BN;

    const __nv_bfloat16* Ah = Ahp + (long)z * aB + m0 * K;
    const __nv_bfloat16* Al = Alp + (long)z * aB + m0 * K;
    const __nv_bfloat16* Bh = Bhp + (long)z * bB + n0 * K;
    const __nv_bfloat16* Bl = Blp + (long)z * bB + n0 * K;
    float* Cp = C + (long)z * cB + m0 * ldc + n0;

    const int r_ld = tid >> 2, c_ld = tid & 3;

    float acc[MI][NJ][4];
#pragma unroll
    for (int i = 0; i < MI; i++)
#pragma unroll
        for (int j = 0; j < NJ; j++)
#pragma unroll
            for (int q = 0; q < 4; q++) acc[i][j][q] = 0.f;

    const int NC = K >> 5;

    auto load_chunk = [&](int ci, int st) {
        const int k0 = ci << 5;
        const uint32_t s0 = sb + (uint32_t)st * STAGE;
#pragma unroll
        for (int i = 0; i < AIT; i++) {
            int r = r_ld + i * RPT;
            uint32_t d = (uint32_t)(r * 64 + ((c_ld ^ (r & 3)) << 4));
            long go = (long)r * K + k0 + c_ld * 8;
            cpasync16(s0 + d,       Ah + go);
            cpasync16(s0 + OAL + d, Al + go);
        }
#pragma unroll
        for (int i = 0; i < BIT; i++) {
            int r = r_ld + i * RPT;
            uint32_t d = (uint32_t)(r * 64 + ((c_ld ^ (r & 3)) << 4));
            long go = (long)r * K + k0 + c_ld * 8;
            cpasync16(s0 + OBH + d, Bh + go);
            cpasync16(s0 + OBL + d, Bl + go);
        }
    };

    const int a_sub = ((lane >> 3) & 1) * 8 + (lane & 7);
    const int a_kc = lane >> 4;
    const int b_sub = ((lane >> 4) & 1) * 8 + (lane & 7);
    const int b_kc = (lane >> 3) & 1;

    load_chunk(0, 0); CP_COMMIT();

    for (int i = 0; i < NC; i++) {
        if (i + 1 < NC) { load_chunk(i + 1, (i + 1) & 1); CP_COMMIT(); CP_WAIT(1); }
        else            { CP_WAIT(0); }
        __syncthreads();
        const uint32_t s0 = sb + ((i & 1) ? (uint32_t)STAGE : 0u);
#pragma unroll
        for (int ks = 0; ks < 2; ks++) {
            uint32_t ah[MI][4], al[MI][4];
#pragma unroll
            for (int mi = 0; mi < MI; mi++) {
                int mrow = wm * WTM + mi * 16 + a_sub;
                int kc = ks * 2 + a_kc;
                uint32_t ad = s0 + mrow * 64 + ((kc ^ (mrow & 3)) << 4);
                ldm_x4(ad, ah[mi]);
                ldm_x4(ad + OAL, al[mi]);
            }
#pragma unroll
            for (int np = 0; np < NB; np++) {
                int nrow = wn * WTN + np * 16 + b_sub;
                int kc = ks * 2 + b_kc;
                uint32_t bd = s0 + OBH + nrow * 64 + ((kc ^ (nrow & 3)) << 4);
                uint32_t bh[4], bl[4];
                ldm_x4(bd, bh);
                ldm_x4(bd + BN * 64, bl);
#pragma unroll
                for (int mi = 0; mi < MI; mi++)
#pragma unroll
                    for (int j = 0; j < 2; j++) {
                        float* a4 = acc[mi][np * 2 + j];
                        mma16816(a4, ah[mi], bh + 2 * j);
                        mma16816(a4, ah[mi], bl + 2 * j);
                        mma16816(a4, al[mi], bh + 2 * j);
                    }
            }
        }
        __syncthreads();
    }

    const int er = lane >> 2, ec = (lane & 3) * 2;
    const long mb = wm * WTM + er;
    const int nb = wn * WTN + ec;
#pragma unroll
    for (int mi = 0; mi < MI; mi++)
#pragma unroll
        for (int nj = 0; nj < NJ; nj++) {
            float* p0 = Cp + (mb + mi * 16) * ldc + nb + nj * 8;
            float* p1 = p0 + 8L * ldc;
            *reinterpret_cast<float2*>(p0) = make_float2(acc[mi][nj][0], acc[mi][nj][1]);
            *reinterpret_cast<float2*>(p1) = make_float2(acc[mi][nj][2], acc[mi][nj][3]);
        }
}

// ================= dual LayerNorm+ReLU on merged GEMM rows ==================
__global__ void dual_ln_kernel(const float* __restrict__ in, int ldin,
                               const float* __restrict__ g1, const float* __restrict__ b1,
                               __nv_bfloat16* __restrict__ oh, __nv_bfloat16* __restrict__ ol,
                               const float* __restrict__ g2, const float* __restrict__ b2,
                               float* __restrict__ out2, int rpb, long ob, long orr) {
    int row = blockIdx.x, t = threadIdx.x;
    const float* ip = in + (long)row * ldin;
    __shared__ float rs[256], rq[256];

    float va[4]; float s = 0.f, ss = 0.f;
#pragma unroll
    for (int i = 0; i < 4; i++) { va[i] = ip[t + 256 * i]; s += va[i]; ss += va[i] * va[i]; }
    rs[t] = s; rq[t] = ss;
    __syncthreads();
    for (int o = 128; o > 0; o >>= 1) {
        if (t < o) { rs[t] += rs[t + o]; rq[t] += rq[t + o]; }
        __syncthreads();
    }
    float mean = rs[0] * (1.f / 1024.f);
    float var = rq[0] * (1.f / 1024.f) - mean * mean;
    float r = rsqrtf(var + LN_EPS);
    __syncthreads();
#pragma unroll
    for (int i = 0; i < 4; i++) {
        int c = t + 256 * i;
        float v = (va[i] - mean) * r * g1[c] + b1[c];
        v = fmaxf(v, 0.f);
        __nv_bfloat16 h = __float2bfloat16(v);
        oh[(long)row * 1024 + c] = h;
        ol[(long)row * 1024 + c] = __float2bfloat16(v - __bfloat162float(h));
    }

    float vb[2]; s = 0.f; ss = 0.f;
#pragma unroll
    for (int i = 0; i < 2; i++) { vb[i] = ip[1024 + t + 256 * i]; s += vb[i]; ss += vb[i] * vb[i]; }
    rs[t] = s; rq[t] = ss;
    __syncthreads();
    for (int o = 128; o > 0; o >>= 1) {
        if (t < o) { rs[t] += rs[t + o]; rq[t] += rq[t + o]; }
        __syncthreads();
    }
    mean = rs[0] * (1.f / 512.f);
    var = rq[0] * (1.f / 512.f) - mean * mean;
    r = rsqrtf(var + LN_EPS);
    float* op = out2 + (long)(row / rpb) * ob + (long)(row % rpb) * orr;
#pragma unroll
    for (int i = 0; i < 2; i++) {
        int c = t + 256 * i;
        float v = (vb[i] - mean) * r * g2[c] + b2[c];
        op[c] = fmaxf(v, 0.f);
    }
}

// ================= plain LN+ReLU (fp32 out) =================
__global__ void ln_relu_kernel(const float* __restrict__ in,
                               const float* __restrict__ gamma,
                               const float* __restrict__ beta,
                               float* __restrict__ outp, int C) {
    int row = blockIdx.x;
    int t = threadIdx.x;
    const float* ip = in + (long)row * C;
    float s = 0.f, ss = 0.f;
    for (int c = t; c < C; c += 256) { float v = ip[c]; s += v; ss += v * v; }
    __shared__ float rs[256], rq[256];
    rs[t] = s; rq[t] = ss;
    __syncthreads();
    for (int o = 128; o > 0; o >>= 1) {
        if (t < o) { rs[t] += rs[t + o]; rq[t] += rq[t + o]; }
        __syncthreads();
    }
    float mean = rs[0] / C;
    float var = rq[0] / C - mean * mean;
    float r = rsqrtf(var + LN_EPS);
    float* op = outp + (long)row * C;
    for (int c = t; c < C; c += 256) {
        float v = (ip[c] - mean) * r * gamma[c] + beta[c];
        op[c] = fmaxf(v, 0.f);
    }
}

// ================= softmax (256 wide) -> bf16 hi/lo directly ================
__global__ void softmax_bf_kernel(const float* __restrict__ sc,
                                  __nv_bfloat16* __restrict__ oh,
                                  __nv_bfloat16* __restrict__ ol) {
    int row = blockIdx.x;
    int t = threadIdx.x;
    float v = sc[(long)row * 256 + t];
    __shared__ float red[256];
    red[t] = v;
    __syncthreads();
    for (int o = 128; o > 0; o >>= 1) { if (t < o) red[t] = fmaxf(red[t], red[t + o]); __syncthreads(); }
    float mx = red[0];
    __syncthreads();
    float e = __expf(v - mx);
    red[t] = e;
    __syncthreads();
    for (int o = 128; o > 0; o >>= 1) { if (t < o) red[t] += red[t + o]; __syncthreads(); }
    float p = e / red[0];
    __nv_bfloat16 h = __float2bfloat16(p);
    oh[(long)row * 256 + t] = h;
    ol[(long)row * 256 + t] = __float2bfloat16(p - __bfloat162float(h));
}

// ================= fc3a: streaming split-K over W3a (packed f32x2 FMA) ======
// xs[f][bp] float2 pairs (b=2bp, 2bp+1), bp XOR-swizzled by (f&7).
__global__ __launch_bounds__(256)
void fc3a_partial_kernel(const float* __restrict__ x, const float* __restrict__ W,
                         float* __restrict__ part) {
    __shared__ float2 xs[512][8];   // 32KB
    const int n = blockIdx.x * 256 + threadIdx.x;
    const int f0 = blockIdx.y * 512;
#pragma unroll
    for (int it = 0; it < 32; it++) {
        int i = threadIdx.x + 256 * it;
        int b = i >> 9, f = i & 511;
        float v = x[(long)b * FIN + f0 + f];
        reinterpret_cast<float*>(&xs[f][(b >> 1) ^ (f & 7)])[b & 1] = v;
    }
    __syncthreads();

    unsigned long long acc[8];
#pragma unroll
    for (int p = 0; p < 8; p++) acc[p] = 0ull;

    const float* Wp = W + (long)f0 * DD + n;
#pragma unroll 8
    for (int f = 0; f < 512; f++) {
        float w = Wp[(long)f * DD];
        unsigned long long wp;
        asm("mov.b64 %0, {%1,%1};" : "=l"(wp) : "r"(__float_as_uint(w)));
        const float2* row = xs[f];
        const int f7 = f & 7;
#pragma unroll
        for (int p = 0; p < 8; p++) {
            unsigned long long xv =
                *reinterpret_cast<const unsigned long long*>(&row[p ^ f7]);
            asm("fma.rn.f32x2 %0, %1, %2, %0;" : "+l"(acc[p]) : "l"(xv), "l"(wp));
        }
    }
#pragma unroll
    for (int p = 0; p < 8; p++) {
        unsigned lo, hi;
        asm("mov.b64 {%0,%1}, %2;" : "=r"(lo), "=r"(hi) : "l"(acc[p]));
        part[((long)blockIdx.y * BB + 2 * p) * DD + n]     = __uint_as_float(lo);
        part[((long)blockIdx.y * BB + 2 * p + 1) * DD + n] = __uint_as_float(hi);
    }
}

__global__ void fc3a_reduce_kernel(const float* __restrict__ part, float* __restrict__ y) {
    int id = blockIdx.x * 256 + threadIdx.x;
    int b = id >> 10, n = id & 1023;
    float s = 0.f;
#pragma unroll 4
    for (int c = 0; c < 256; c++) s += part[((long)c * BB + b) * DD + n];
    y[id] = s;
}

// ================= fc3b: [16,1024] @ [1024,1024] =================
__global__ void small_gemm_kernel(const float* __restrict__ A, const float* __restrict__ W,
                                  float* __restrict__ C, int K, int N) {
    int n = blockIdx.x * 256 + threadIdx.x;
    int b = blockIdx.y;
    float acc = 0.f;
#pragma unroll 4
    for (int k = 0; k < K; k++) acc += A[(long)b * K + k] * W[(long)k * N + n];
    C[(long)b * N + n] = acc;
}

// ================= heads =================
__global__ void heads_kernel(const float* __restrict__ x2,
                             const float* __restrict__ Wr, const float* __restrict__ br,
                             const float* __restrict__ Wt, const float* __restrict__ bt,
                             float* __restrict__ out) {
    int b = blockIdx.x;
    int w = threadIdx.x >> 5, lane = threadIdx.x & 31;
    __shared__ float vals[7];
    if (w < 7) {
        const float* Wp = (w < 4) ? Wr : Wt;
        int ncol = (w < 4) ? 4 : 3;
        int j = (w < 4) ? w : (w - 4);
        float acc = 0.f;
        for (int k = lane; k < DD; k += 32) acc += x2[(long)b * DD + k] * Wp[(long)k * ncol + j];
        for (int o = 16; o > 0; o >>= 1) acc += __shfl_down_sync(0xffffffffu, acc, o);
        if (lane == 0) vals[w] = acc + ((w < 4) ? br[j] : bt[j]);
    }
    __syncthreads();
    if (threadIdx.x == 0) {
        float nn = sqrtf(vals[0]*vals[0] + vals[1]*vals[1] + vals[2]*vals[2] + vals[3]*vals[3]);
        nn = fmaxf(nn, 1e-12f);
        for (int j = 0; j < 4; j++) out[b * 4 + j] = vals[j] / nn;
        for (int j = 0; j < 3; j++) out[64 + b * 3 + j] = vals[4 + j];
    }
}

// ================= host driver =================
extern "C" void kernel_launch(void* const* d_in, const int* in_sizes, int n_in,
                              void* d_out, int out_size) {
    const float* sgm_feats = nullptr; const float* velo_feats = nullptr;
    const int* sbidx = nullptr; const int* vbidx = nullptr;
    int N_sgm = 0, N_velo = 0;
    const float* w[22]; int wi = 0;
    for (int i = 0; i < n_in; i++) {
        int s = in_sizes[i];
        if (s == 3000 * 1024)      { sgm_feats = (const float*)d_in[i]; }
        else if (s == 6000 * 1024) { velo_feats = (const float*)d_in[i]; }
        else if (s == 3000)        { sbidx = (const int*)d_in[i]; N_sgm = s; }
        else if (s == 6000)        { vbidx = (const int*)d_in[i]; N_velo = s; }
        else if (wi < 22)          { w[wi++] = (const float*)d_in[i]; }
    }
    const float *Wq = w[0], *gq = w[1], *bq = w[2];
    const float *Wk = w[3], *gk = w[4], *bk = w[5];
    const float *Wv1 = w[6], *gv1 = w[7], *bv1 = w[8];
    const float *Wv2 = w[9], *gv2 = w[10], *bv2 = w[11];
    const float *W3a = w[12], *g3a = w[13], *b3a = w[14];
    const float *W3b = w[15], *g3b = w[16], *b3b = w[17];
    const float *Wr = w[18], *brr = w[19], *Wt = w[20], *btt = w[21];

    float* fb = nullptr;
    cudaGetSymbolAddress((void**)&fb, g_buf);
    __nv_bfloat16* bb = nullptr;
    cudaGetSymbolAddress((void**)&bb, g_bf);

    float* dTMP  = fb + OFF_TMP;
    float* dV1F  = fb + OFF_V1F;
    float* dX    = fb + OFF_X;
    float* dATT  = fb + OFF_ATTNF;
    float* dPART = fb + OFF_PART;
    float* dY    = fb + OFF_Y;
    float* dX1   = fb + OFF_X1;
    float* dX2   = fb + OFF_X2;
    float* out   = (float*)d_out;

    constexpr int SMEM_A = 2 * 2 * (128 + 128) * 64;   // 65536
    constexpr int SMEM_B = 2 * 2 * (64 + 64) * 64;     // 32768
    cudaFuncSetAttribute(mma_gemm_t<128, 128, 4, 2>,
                         cudaFuncAttributeMaxDynamicSharedMemorySize, SMEM_A);

    // 1. zero + scatter (fp32 -> hi/lo bf16 dense)
    zero_bf_kernel<<<(int)((12582912L * 2 / 16 + 255) / 256), 256>>>();
    scatter_split_kernel<<<N_sgm, 256>>>(sgm_feats, sbidx, N_sgm, bb + BO_SGMH, bb + BO_SGML, SS);
    scatter_split_kernel<<<N_velo, 256>>>(velo_feats, vbidx, N_velo, bb + BO_VELOH, bb + BO_VELOL, TT);

    // 2. transpose+split weights into merged [1536][1024] layouts
    transpose_split_kernel<<<dim3(32, 32, 1), 256>>>(Wq,  bb + BO_WQV2H, bb + BO_WQV2L, 1024, 1024, 0, 0);
    transpose_split_kernel<<<dim3(16, 32, 1), 256>>>(Wv2, bb + BO_WQV2H + 1048576L,
                                                     bb + BO_WQV2L + 1048576L, 1024, 512, 0, 0);
    transpose_split_kernel<<<dim3(32, 32, 1), 256>>>(Wk,  bb + BO_WKV1H, bb + BO_WKV1L, 1024, 1024, 0, 0);
    transpose_split_kernel<<<dim3(16, 32, 1), 256>>>(Wv1, bb + BO_WKV1H + 1048576L,
                                                     bb + BO_WKV1L + 1048576L, 1024, 512, 0, 0);

    // 3. [q | v2] = sgm @ [WqT | Wv2T]^T  (M=2048, N=1536)
    mma_gemm_t<128, 128, 4, 2><<<dim3(12, 16, 1), 256, SMEM_A>>>(
        bb + BO_SGMH, bb + BO_SGML, bb + BO_WQV2H, bb + BO_WQV2L,
        dTMP, DD, 1536, 0, 0, 0);
    dual_ln_kernel<<<BB * SS, 256>>>(dTMP, 1536, gq, bq, bb + BO_QH, bb + BO_QL,
                                     gv2, bv2, dX, SS, (long)FIN, DD);

    // 4. [k | v1] = velo @ [WkT | Wv1T]^T  (M=4096, N=1536)
    mma_gemm_t<128, 128, 4, 2><<<dim3(12, 32, 1), 256, SMEM_A>>>(
        bb + BO_VELOH, bb + BO_VELOL, bb + BO_WKV1H, bb + BO_WKV1L,
        dTMP, DD, 1536, 0, 0, 0);
    dual_ln_kernel<<<BB * TT, 256>>>(dTMP, 1536, gk, bk, bb + BO_KH, bb + BO_KL,
                                     gv1, bv1, dV1F, 1 << 20, 0, 512);

    // 5. v1T: [16][256][512] -> [16][512][256] hi/lo
    transpose_split_kernel<<<dim3(16, 8, BB), 256>>>(dV1F, bb + BO_V1TH, bb + BO_V1TL,
                                                     TT, 512, (long)TT * 512, (long)TT * 512);

    // 6. scores = q @ k^T (batched, 64x64 tiles -> 128 CTAs), softmax -> bf16
    mma_gemm_t<64, 64, 2, 2><<<dim3(4, 2, BB), 128, SMEM_B>>>(
        bb + BO_QH, bb + BO_QL, bb + BO_KH, bb + BO_KL,
        dATT, DD, TT, (long)SS * DD, (long)TT * DD, (long)SS * TT);
    softmax_bf_kernel<<<BB * SS, 256>>>(dATT, bb + BO_ATH, bb + BO_ATL);

    // 7. ctx = attn @ v1 -> X[:, s*1024 + 512..1023] (64x64 tiles -> 256 CTAs)
    mma_gemm_t<64, 64, 2, 2><<<dim3(8, 2, BB), 128, SMEM_B>>>(
        bb + BO_ATH, bb + BO_ATL, bb + BO_V1TH, bb + BO_V1TL,
        dX + 512, TT, DD, (long)SS * TT, (long)512 * TT, (long)FIN);

    // 8. fc3a (f32x2 FMA, DRAM streaming) + LN -> x1
    fc3a_partial_kernel<<<dim3(DD / 256, FIN / 512), 256>>>(dX, W3a, dPART);
    fc3a_reduce_kernel<<<(BB * DD) / 256, 256>>>(dPART, dY);
    ln_relu_kernel<<<BB, 256>>>(dY, g3a, b3a, dX1, DD);

    // 9. fc3b + LN -> x2
    small_gemm_kernel<<<dim3(DD / 256, BB), 256>>>(dX1, W3b, dTMP, DD, DD);
    ln_relu_kernel<<<BB, 256>>>(dTMP, g3b, b3b, dX2, DD);

    // 10. heads
    heads_kernel<<<BB, 256>>>(dX2, Wr, brr, Wt, btt, out);
    (void)out_size;
}

// round 6
// speedup vs baseline: 2.4544x; 1.1196x over previous
#include <cuda_runtime.h>
#include <cuda_bf16.h>
#include <math.h>
#include <stdint.h>

// ---------------- problem constants ----------------
#define BB   16
#define SS   128
#define TT   256
#define DD   1024
#define FIN  (DD * SS)          // 131072
#define LN_EPS 1e-5f

// ---------------- fp32 scratch (floats) ----------------
#define OFF_TMP   0L             // 3145728 (2048 x 1536)  qv2 out
#define OFF_TMP2  3145728L       // 6291456 (4096 x 1536)  kv1 out
#define OFF_V1F   9437184L       // 2097152 (16*256*512)
#define OFF_X     11534336L      // 2097152 (16*131072)
#define OFF_ATTNF 13631488L      // 524288  (16*128*256)
#define OFF_PART  14155776L      // 4194304 (256*16*1024)
#define OFF_X1    18350080L      // 16384
#define OFF_X2    18366464L      // 16384
#define FBUF_TOTAL 18382848L
__device__ __align__(128) float g_buf[FBUF_TOTAL];

// ---------------- bf16 scratch (elements) ----------------
#define BO_SGMH   0L             // 2097152
#define BO_SGML   2097152L
#define BO_VELOH  4194304L       // 4194304
#define BO_VELOL  8388608L
#define BO_QH     12582912L      // 2097152
#define BO_QL     14680064L
#define BO_KH     16777216L      // 4194304
#define BO_KL     20971520L
#define BO_WQV2H  25165824L      // 1572864 ([1536][1024])
#define BO_WQV2L  26738688L
#define BO_WKV1H  28311552L
#define BO_WKV1L  29884416L
#define BO_V1TH   31457280L      // 2097152 ([16][512][256])
#define BO_V1TL   33554432L
#define BO_ATH    35651584L      // 524288
#define BO_ATL    36175872L
#define BBUF_TOTAL 36700160L
__device__ __align__(128) __nv_bfloat16 g_bf[BBUF_TOTAL];

// ================= PTX helpers (baseline ISA, plain sm_103) =======
__device__ __forceinline__ uint32_t smem_u32(const void* p) {
    uint32_t a;
    asm("{ .reg .u64 t; cvta.to.shared.u64 t, %1; cvt.u32.u64 %0, t; }" : "=r"(a) : "l"(p));
    return a;
}
__device__ __forceinline__ void cpasync16(uint32_t dst, const void* src) {
    asm volatile("cp.async.cg.shared.global [%0], [%1], 16;" :: "r"(dst), "l"(src));
}
#define CP_COMMIT() asm volatile("cp.async.commit_group;" ::: "memory")
#define CP_WAIT(n)  asm volatile("cp.async.wait_group %0;" :: "n"(n) : "memory")

__device__ __forceinline__ void ldm_x4(uint32_t addr, uint32_t* r) {
    asm volatile("ldmatrix.sync.aligned.m8n8.x4.shared.b16 {%0,%1,%2,%3}, [%4];"
                 : "=r"(r[0]), "=r"(r[1]), "=r"(r[2]), "=r"(r[3]) : "r"(addr));
}
__device__ __forceinline__ void mma16816(float* d, const uint32_t* a, const uint32_t* b) {
    asm volatile("mma.sync.aligned.m16n8k16.row.col.f32.bf16.bf16.f32 "
                 "{%0,%1,%2,%3}, {%4,%5,%6,%7}, {%8,%9}, {%0,%1,%2,%3};"
                 : "+f"(d[0]), "+f"(d[1]), "+f"(d[2]), "+f"(d[3])
                 : "r"(a[0]), "r"(a[1]), "r"(a[2]), "r"(a[3]), "r"(b[0]), "r"(b[1]));
}

// ---------------- hi/lo split helpers ----------------
__device__ __forceinline__ void split2(float a, float b, unsigned& h, unsigned& l) {
    __nv_bfloat162 hh = __floats2bfloat162_rn(a, b);
    float ra = a - __bfloat162float(__low2bfloat16(hh));
    float rb = b - __bfloat162float(__high2bfloat16(hh));
    __nv_bfloat162 ll = __floats2bfloat162_rn(ra, rb);
    h = *reinterpret_cast<unsigned*>(&hh);
    l = *reinterpret_cast<unsigned*>(&ll);
}

// ================= build dense hi/lo bf16 (gather; zero-fill missing) =======
// one block per dense slot; sgm slots [0, 2048), velo slots [2048, 6144)
__global__ void build_dense_kernel(const float* __restrict__ sgm, const int* __restrict__ sb,
                                   int Ns, const float* __restrict__ velo,
                                   const int* __restrict__ vb, int Nv) {
    int slot = blockIdx.x;
    const float* feats; const int* bidx; int N, local; long base;
    if (slot < BB * SS) { feats = sgm; bidx = sb; N = Ns; local = SS; base = BO_SGMH; }
    else { slot -= BB * SS; feats = velo; bidx = vb; N = Nv; local = TT; base = BO_VELOH; }
    int b = slot / local, r = slot % local;
    __shared__ int s_src;
    if (threadIdx.x == 0) {
        int lo = 0, hi = N;
        while (lo < hi) { int mid = (lo + hi) >> 1; if (bidx[mid] < b) lo = mid + 1; else hi = mid; }
        int src = lo + r;
        s_src = (src < N && bidx[src] == b) ? src : -1;
    }
    __syncthreads();
    int src = s_src;
    __nv_bfloat16* dh = g_bf + base + (long)slot * DD;
    __nv_bfloat16* dl = dh + ((base == BO_SGMH) ? (BO_SGML - BO_SGMH) : (BO_VELOL - BO_VELOH));
    int c = threadIdx.x * 4;
    uint2 h = make_uint2(0, 0), l = make_uint2(0, 0);
    if (src >= 0) {
        const float4 v = *reinterpret_cast<const float4*>(feats + (long)src * DD + c);
        split2(v.x, v.y, h.x, l.x);
        split2(v.z, v.w, h.y, l.y);
    }
    *reinterpret_cast<uint2*>(dh + c) = h;
    *reinterpret_cast<uint2*>(dl + c) = l;
}

// ================= transpose + split (generic body) ==========================
__device__ __forceinline__ void tsp_body(const float* __restrict__ in,
                                         __nv_bfloat16* __restrict__ oh,
                                         __nv_bfloat16* __restrict__ ol,
                                         int R, int C, int bx, int by) {
    __shared__ float t[32][33];
    int r0 = by * 32, c0 = bx * 32;
    int tx = threadIdx.x & 31, ty = threadIdx.x >> 5;
#pragma unroll
    for (int i = 0; i < 32; i += 8)
        t[ty + i][tx] = in[(long)(r0 + ty + i) * C + c0 + tx];
    __syncthreads();
#pragma unroll
    for (int i = 0; i < 32; i += 8) {
        float v = t[tx][ty + i];
        __nv_bfloat16 h = __float2bfloat16(v);
        __nv_bfloat16 l = __float2bfloat16(v - __bfloat162float(h));
        long o = (long)(c0 + ty + i) * R + r0 + tx;
        oh[o] = h; ol[o] = l;
    }
}

// all 4 weight transposes in one launch; grid (32, 32, 4)
__global__ void transpose_w4_kernel(const float* __restrict__ Wq, const float* __restrict__ Wk,
                                    const float* __restrict__ Wv2, const float* __restrict__ Wv1) {
    int z = blockIdx.z;
    if (z == 0)      tsp_body(Wq,  g_bf + BO_WQV2H, g_bf + BO_WQV2L, 1024, 1024, blockIdx.x, blockIdx.y);
    else if (z == 1) tsp_body(Wk,  g_bf + BO_WKV1H, g_bf + BO_WKV1L, 1024, 1024, blockIdx.x, blockIdx.y);
    else if (z == 2) { if (blockIdx.x < 16)
        tsp_body(Wv2, g_bf + BO_WQV2H + 1048576L, g_bf + BO_WQV2L + 1048576L, 1024, 512, blockIdx.x, blockIdx.y); }
    else             { if (blockIdx.x < 16)
        tsp_body(Wv1, g_bf + BO_WKV1H + 1048576L, g_bf + BO_WKV1L + 1048576L, 1024, 512, blockIdx.x, blockIdx.y); }
}

// batched v1 transpose (unchanged semantics)
__global__ void transpose_split_kernel(const float* __restrict__ in,
                                       __nv_bfloat16* __restrict__ oh,
                                       __nv_bfloat16* __restrict__ ol,
                                       int R, int C, long inB, long outB) {
    int z = blockIdx.z;
    tsp_body(in + (long)z * inB, oh + (long)z * outB, ol + (long)z * outB,
             R, C, blockIdx.x, blockIdx.y);
}

// ================= HMMA GEMM body: C = A[M,K] @ B[N,K]^T (tile) =============
template<int BM, int BN, int WM_CNT, int WN_CNT>
__device__ __forceinline__ void gemm_body(
    const __nv_bfloat16* __restrict__ Ah, const __nv_bfloat16* __restrict__ Al,
    const __nv_bfloat16* __restrict__ Bh, const __nv_bfloat16* __restrict__ Bl,
    float* __restrict__ Cp, int K, int ldc, uint32_t sb) {
    constexpr int T   = 32 * WM_CNT * WN_CNT;
    constexpr int WTM = BM / WM_CNT, WTN = BN / WN_CNT;
    constexpr int MI  = WTM / 16;
    constexpr int NB  = WTN / 16;
    constexpr int NJ  = WTN / 8;
    constexpr int OAL = BM * 64, OBH = 2 * BM * 64, OBL = OBH + BN * 64;
    constexpr int STAGE = 2 * (BM + BN) * 64;
    constexpr int RPT = T >> 2;
    constexpr int AIT = BM / RPT, BIT = BN / RPT;

    const int tid = threadIdx.x, lane = tid & 31, wid = tid >> 5;
    const int wm = wid % WM_CNT, wn = wid / WM_CNT;
    const int r_ld = tid >> 2, c_ld = tid & 3;

    float acc[MI][NJ][4];
#pragma unroll
    for (int i = 0; i < MI; i++)
#pragma unroll
        for (int j = 0; j < NJ; j++)
#pragma unroll
            for (int q = 0; q < 4; q++) acc[i][j][q] = 0.f;

    const int NC = K >> 5;

    auto load_chunk = [&](int ci, int st) {
        const int k0 = ci << 5;
        const uint32_t s0 = sb + (uint32_t)st * STAGE;
#pragma unroll
        for (int i = 0; i < AIT; i++) {
            int r = r_ld + i * RPT;
            uint32_t d = (uint32_t)(r * 64 + ((c_ld ^ (r & 3)) << 4));
            long go = (long)r * K + k0 + c_ld * 8;
            cpasync16(s0 + d,       Ah + go);
            cpasync16(s0 + OAL + d, Al + go);
        }
#pragma unroll
        for (int i = 0; i < BIT; i++) {
            int r = r_ld + i * RPT;
            uint32_t d = (uint32_t)(r * 64 + ((c_ld ^ (r & 3)) << 4));
            long go = (long)r * K + k0 + c_ld * 8;
            cpasync16(s0 + OBH + d, Bh + go);
            cpasync16(s0 + OBL + d, Bl + go);
        }
    };

    const int a_sub = ((lane >> 3) & 1) * 8 + (lane & 7);
    const int a_kc = lane >> 4;
    const int b_sub = ((lane >> 4) & 1) * 8 + (lane & 7);
    const int b_kc = (lane >> 3) & 1;

    load_chunk(0, 0); CP_COMMIT();

    for (int i = 0; i < NC; i++) {
        if (i + 1 < NC) { load_chunk(i + 1, (i + 1) & 1); CP_COMMIT(); CP_WAIT(1); }
        else            { CP_WAIT(0); }
        __syncthreads();
        const uint32_t s0 = sb + ((i & 1) ? (uint32_t)STAGE : 0u);
#pragma unroll
        for (int ks = 0; ks < 2; ks++) {
            uint32_t ah[MI][4], al[MI][4];
#pragma unroll
            for (int mi = 0; mi < MI; mi++) {
                int mrow = wm * WTM + mi * 16 + a_sub;
                int kc = ks * 2 + a_kc;
                uint32_t ad = s0 + mrow * 64 + ((kc ^ (mrow & 3)) << 4);
                ldm_x4(ad, ah[mi]);
                ldm_x4(ad + OAL, al[mi]);
            }
#pragma unroll
            for (int np = 0; np < NB; np++) {
                int nrow = wn * WTN + np * 16 + b_sub;
                int kc = ks * 2 + b_kc;
                uint32_t bd = s0 + OBH + nrow * 64 + ((kc ^ (nrow & 3)) << 4);
                uint32_t bh[4], bl[4];
                ldm_x4(bd, bh);
                ldm_x4(bd + BN * 64, bl);
#pragma unroll
                for (int mi = 0; mi < MI; mi++)
#pragma unroll
                    for (int j = 0; j < 2; j++) {
                        float* a4 = acc[mi][np * 2 + j];
                        mma16816(a4, ah[mi], bh + 2 * j);
                        mma16816(a4, ah[mi], bl + 2 * j);
                        mma16816(a4, al[mi], bh + 2 * j);
                    }
            }
        }
        __syncthreads();
    }

    const int er = lane >> 2, ec = (lane & 3) * 2;
    const long mb = wm * WTM + er;
    const int nb = wn * WTN + ec;
#pragma unroll
    for (int mi = 0; mi < MI; mi++)
#pragma unroll
        for (int nj = 0; nj < NJ; nj++) {
            float* p0 = Cp + (mb + mi * 16) * ldc + nb + nj * 8;
            float* p1 = p0 + 8L * ldc;
            *reinterpret_cast<float2*>(p0) = make_float2(acc[mi][nj][0], acc[mi][nj][1]);
            *reinterpret_cast<float2*>(p1) = make_float2(acc[mi][nj][2], acc[mi][nj][3]);
        }
}

// merged big GEMM: qv2 (blockIdx.y<16) + kv1 (y>=16); grid (12, 48)
__global__ __launch_bounds__(256, 2)
void mma_gemm_big(float* __restrict__ c1, float* __restrict__ c2) {
    extern __shared__ char smem[];
    const uint32_t sb = smem_u32(smem);
    const int K = DD, ldc = 1536;
    const long n0 = (long)blockIdx.x * 128;
    const __nv_bfloat16 *Ah, *Al, *Bh, *Bl;
    float* Cp;
    if (blockIdx.y < 16) {
        long m0 = (long)blockIdx.y * 128;
        Ah = g_bf + BO_SGMH + m0 * K;  Al = g_bf + BO_SGML + m0 * K;
        Bh = g_bf + BO_WQV2H + n0 * K; Bl = g_bf + BO_WQV2L + n0 * K;
        Cp = c1 + m0 * ldc + n0;
    } else {
        long m0 = (long)(blockIdx.y - 16) * 128;
        Ah = g_bf + BO_VELOH + m0 * K; Al = g_bf + BO_VELOL + m0 * K;
        Bh = g_bf + BO_WKV1H + n0 * K; Bl = g_bf + BO_WKV1L + n0 * K;
        Cp = c2 + m0 * ldc + n0;
    }
    gemm_body<128, 128, 4, 2>(Ah, Al, Bh, Bl, Cp, K, ldc, sb);
}

// small batched GEMM kernel (scores / ctx)
template<int BM, int BN, int WM_CNT, int WN_CNT>
__global__ __launch_bounds__(32 * WM_CNT * WN_CNT, 2)
void mma_gemm_t(const __nv_bfloat16* __restrict__ Ahp, const __nv_bfloat16* __restrict__ Alp,
                const __nv_bfloat16* __restrict__ Bhp, const __nv_bfloat16* __restrict__ Blp,
                float* __restrict__ C, int K, int ldc,
                long aB, long bB, long cB) {
    extern __shared__ char smem[];
    const uint32_t sb = smem_u32(smem);
    const int z = blockIdx.z;
    const long m0 = (long)blockIdx.y * BM, n0 = (long)blockIdx.x * BN;
    gemm_body<BM, BN, WM_CNT, WN_CNT>(
        Ahp + (long)z * aB + m0 * K, Alp + (long)z * aB + m0 * K,
        Bhp + (long)z * bB + n0 * K, Blp + (long)z * bB + n0 * K,
        C + (long)z * cB + m0 * ldc + n0, K, ldc, sb);
}

// ================= merged dual LayerNorm+ReLU (qv2 rows + kv1 rows) =========
__global__ void dual_ln2_kernel(const float* __restrict__ in1, const float* __restrict__ in2,
                                const float* __restrict__ gq, const float* __restrict__ bq,
                                const float* __restrict__ gv2, const float* __restrict__ bv2,
                                const float* __restrict__ gk, const float* __restrict__ bk,
                                const float* __restrict__ gv1, const float* __restrict__ bv1,
                                float* __restrict__ dX, float* __restrict__ dV1F) {
    int row = blockIdx.x, t = threadIdx.x;
    const float* ip;
    const float *g1, *b1, *g2, *b2;
    __nv_bfloat16 *oh, *ol;
    float* out2;
    if (row < 2048) {
        ip = in1 + (long)row * 1536;
        g1 = gq; b1 = bq; g2 = gv2; b2 = bv2;
        oh = g_bf + BO_QH + (long)row * 1024;
        ol = g_bf + BO_QL + (long)row * 1024;
        out2 = dX + (long)(row >> 7) * FIN + (long)(row & 127) * 1024;
    } else {
        int r2 = row - 2048;
        ip = in2 + (long)r2 * 1536;
        g1 = gk; b1 = bk; g2 = gv1; b2 = bv1;
        oh = g_bf + BO_KH + (long)r2 * 1024;
        ol = g_bf + BO_KL + (long)r2 * 1024;
        out2 = dV1F + (long)r2 * 512;
    }
    __shared__ float rs[256], rq[256];

    float va[4]; float s = 0.f, ss = 0.f;
#pragma unroll
    for (int i = 0; i < 4; i++) { va[i] = ip[t + 256 * i]; s += va[i]; ss += va[i] * va[i]; }
    rs[t] = s; rq[t] = ss;
    __syncthreads();
    for (int o = 128; o > 0; o >>= 1) {
        if (t < o) { rs[t] += rs[t + o]; rq[t] += rq[t + o]; }
        __syncthreads();
    }
    float mean = rs[0] * (1.f / 1024.f);
    float var = rq[0] * (1.f / 1024.f) - mean * mean;
    float r = rsqrtf(var + LN_EPS);
    __syncthreads();
#pragma unroll
    for (int i = 0; i < 4; i++) {
        int c = t + 256 * i;
        float v = (va[i] - mean) * r * g1[c] + b1[c];
        v = fmaxf(v, 0.f);
        __nv_bfloat16 h = __float2bfloat16(v);
        oh[c] = h;
        ol[c] = __float2bfloat16(v - __bfloat162float(h));
    }

    float vb[2]; s = 0.f; ss = 0.f;
#pragma unroll
    for (int i = 0; i < 2; i++) { vb[i] = ip[1024 + t + 256 * i]; s += vb[i]; ss += vb[i] * vb[i]; }
    rs[t] = s; rq[t] = ss;
    __syncthreads();
    for (int o = 128; o > 0; o >>= 1) {
        if (t < o) { rs[t] += rs[t + o]; rq[t] += rq[t + o]; }
        __syncthreads();
    }
    mean = rs[0] * (1.f / 512.f);
    var = rq[0] * (1.f / 512.f) - mean * mean;
    r = rsqrtf(var + LN_EPS);
#pragma unroll
    for (int i = 0; i < 2; i++) {
        int c = t + 256 * i;
        float v = (vb[i] - mean) * r * g2[c] + b2[c];
        out2[c] = fmaxf(v, 0.f);
    }
}

// ================= plain LN+ReLU (fp32 out) =================
__global__ void ln_relu_kernel(const float* __restrict__ in,
                               const float* __restrict__ gamma,
                               const float* __restrict__ beta,
                               float* __restrict__ outp, int C) {
    int row = blockIdx.x;
    int t = threadIdx.x;
    const float* ip = in + (long)row * C;
    float s = 0.f, ss = 0.f;
    for (int c = t; c < C; c += 256) { float v = ip[c]; s += v; ss += v * v; }
    __shared__ float rs[256], rq[256];
    rs[t] = s; rq[t] = ss;
    __syncthreads();
    for (int o = 128; o > 0; o >>= 1) {
        if (t < o) { rs[t] += rs[t + o]; rq[t] += rq[t + o]; }
        __syncthreads();
    }
    float mean = rs[0] / C;
    float var = rq[0] / C - mean * mean;
    float r = rsqrtf(var + LN_EPS);
    float* op = outp + (long)row * C;
    for (int c = t; c < C; c += 256) {
        float v = (ip[c] - mean) * r * gamma[c] + beta[c];
        op[c] = fmaxf(v, 0.f);
    }
}

// ================= softmax (256 wide) -> bf16 hi/lo directly ================
__global__ void softmax_bf_kernel(const float* __restrict__ sc,
                                  __nv_bfloat16* __restrict__ oh,
                                  __nv_bfloat16* __restrict__ ol) {
    int row = blockIdx.x;
    int t = threadIdx.x;
    float v = sc[(long)row * 256 + t];
    __shared__ float red[256];
    red[t] = v;
    __syncthreads();
    for (int o = 128; o > 0; o >>= 1) { if (t < o) red[t] = fmaxf(red[t], red[t + o]); __syncthreads(); }
    float mx = red[0];
    __syncthreads();
    float e = __expf(v - mx);
    red[t] = e;
    __syncthreads();
    for (int o = 128; o > 0; o >>= 1) { if (t < o) red[t] += red[t + o]; __syncthreads(); }
    float p = e / red[0];
    __nv_bfloat16 h = __float2bfloat16(p);
    oh[(long)row * 256 + t] = h;
    ol[(long)row * 256 + t] = __float2bfloat16(p - __bfloat162float(h));
}

// ================= fc3a: streaming split-K over W3a (packed f32x2 FMA) ======
__global__ __launch_bounds__(256)
void fc3a_partial_kernel(const float* __restrict__ x, const float* __restrict__ W,
                         float* __restrict__ part) {
    __shared__ float2 xs[512][8];   // 32KB
    const int n = blockIdx.x * 256 + threadIdx.x;
    const int f0 = blockIdx.y * 512;
#pragma unroll
    for (int it = 0; it < 32; it++) {
        int i = threadIdx.x + 256 * it;
        int b = i >> 9, f = i & 511;
        float v = x[(long)b * FIN + f0 + f];
        reinterpret_cast<float*>(&xs[f][(b >> 1) ^ (f & 7)])[b & 1] = v;
    }
    __syncthreads();

    unsigned long long acc[8];
#pragma unroll
    for (int p = 0; p < 8; p++) acc[p] = 0ull;

    const float* Wp = W + (long)f0 * DD + n;
#pragma unroll 8
    for (int f = 0; f < 512; f++) {
        float w = Wp[(long)f * DD];
        unsigned long long wp;
        asm("mov.b64 %0, {%1,%1};" : "=l"(wp) : "r"(__float_as_uint(w)));
        const float2* row = xs[f];
        const int f7 = f & 7;
#pragma unroll
        for (int p = 0; p < 8; p++) {
            unsigned long long xv =
                *reinterpret_cast<const unsigned long long*>(&row[p ^ f7]);
            asm("fma.rn.f32x2 %0, %1, %2, %0;" : "+l"(acc[p]) : "l"(xv), "l"(wp));
        }
    }
#pragma unroll
    for (int p = 0; p < 8; p++) {
        unsigned lo, hi;
        asm("mov.b64 {%0,%1}, %2;" : "=r"(lo), "=r"(hi) : "l"(acc[p]));
        part[((long)blockIdx.y * BB + 2 * p) * DD + n]     = __uint_as_float(lo);
        part[((long)blockIdx.y * BB + 2 * p + 1) * DD + n] = __uint_as_float(hi);
    }
}

// fused reduce(256 chunks) + LayerNorm + ReLU -> x1; grid 16, block 1024
__global__ __launch_bounds__(1024)
void fc3a_reduce_ln_kernel(const float* __restrict__ part,
                           const float* __restrict__ gamma, const float* __restrict__ beta,
                           float* __restrict__ x1) {
    int b = blockIdx.x, n = threadIdx.x;
    float s = 0.f;
#pragma unroll 4
    for (int c = 0; c < 256; c++) s += part[((long)c * BB + b) * DD + n];
    __shared__ float rs[1024], rq[1024];
    rs[n] = s; rq[n] = s * s;
    __syncthreads();
    for (int o = 512; o > 0; o >>= 1) {
        if (n < o) { rs[n] += rs[n + o]; rq[n] += rq[n + o]; }
        __syncthreads();
    }
    float mean = rs[0] * (1.f / 1024.f);
    float var = rq[0] * (1.f / 1024.f) - mean * mean;
    float r = rsqrtf(var + LN_EPS);
    float v = (s - mean) * r * gamma[n] + beta[n];
    x1[(long)b * DD + n] = fmaxf(v, 0.f);
}

// ================= fc3b: [16,1024] @ [1024,1024] =================
__global__ void small_gemm_kernel(const float* __restrict__ A, const float* __restrict__ W,
                                  float* __restrict__ C, int K, int N) {
    int n = blockIdx.x * 256 + threadIdx.x;
    int b = blockIdx.y;
    float acc = 0.f;
#pragma unroll 4
    for (int k = 0; k < K; k++) acc += A[(long)b * K + k] * W[(long)k * N + n];
    C[(long)b * N + n] = acc;
}

// ================= heads =================
__global__ void heads_kernel(const float* __restrict__ x2,
                             const float* __restrict__ Wr, const float* __restrict__ br,
                             const float* __restrict__ Wt, const float* __restrict__ bt,
                             float* __restrict__ out) {
    int b = blockIdx.x;
    int w = threadIdx.x >> 5, lane = threadIdx.x & 31;
    __shared__ float vals[7];
    if (w < 7) {
        const float* Wp = (w < 4) ? Wr : Wt;
        int ncol = (w < 4) ? 4 : 3;
        int j = (w < 4) ? w : (w - 4);
        float acc = 0.f;
        for (int k = lane; k < DD; k += 32) acc += x2[(long)b * DD + k] * Wp[(long)k * ncol + j];
        for (int o = 16; o > 0; o >>= 1) acc += __shfl_down_sync(0xffffffffu, acc, o);
        if (lane == 0) vals[w] = acc + ((w < 4) ? br[j] : bt[j]);
    }
    __syncthreads();
    if (threadIdx.x == 0) {
        float nn = sqrtf(vals[0]*vals[0] + vals[1]*vals[1] + vals[2]*vals[2] + vals[3]*vals[3]);
        nn = fmaxf(nn, 1e-12f);
        for (int j = 0; j < 4; j++) out[b * 4 + j] = vals[j] / nn;
        for (int j = 0; j < 3; j++) out[64 + b * 3 + j] = vals[4 + j];
    }
}

// ================= host driver =================
extern "C" void kernel_launch(void* const* d_in, const int* in_sizes, int n_in,
                              void* d_out, int out_size) {
    const float* sgm_feats = nullptr; const float* velo_feats = nullptr;
    const int* sbidx = nullptr; const int* vbidx = nullptr;
    int N_sgm = 0, N_velo = 0;
    const float* w[22]; int wi = 0;
    for (int i = 0; i < n_in; i++) {
        int s = in_sizes[i];
        if (s == 3000 * 1024)      { sgm_feats = (const float*)d_in[i]; }
        else if (s == 6000 * 1024) { velo_feats = (const float*)d_in[i]; }
        else if (s == 3000)        { sbidx = (const int*)d_in[i]; N_sgm = s; }
        else if (s == 6000)        { vbidx = (const int*)d_in[i]; N_velo = s; }
        else if (wi < 22)          { w[wi++] = (const float*)d_in[i]; }
    }
    const float *gq = w[1], *bq = w[2];
    const float *Wq = w[0], *Wk = w[3], *gk = w[4], *bk = w[5];
    const float *Wv1 = w[6], *gv1 = w[7], *bv1 = w[8];
    const float *Wv2 = w[9], *gv2 = w[10], *bv2 = w[11];
    const float *W3a = w[12], *g3a = w[13], *b3a = w[14];
    const float *W3b = w[15], *g3b = w[16], *b3b = w[17];
    const float *Wr = w[18], *brr = w[19], *Wt = w[20], *btt = w[21];

    float* fb = nullptr;
    cudaGetSymbolAddress((void**)&fb, g_buf);
    __nv_bfloat16* bb = nullptr;
    cudaGetSymbolAddress((void**)&bb, g_bf);

    float* dTMP  = fb + OFF_TMP;
    float* dTMP2 = fb + OFF_TMP2;
    float* dV1F  = fb + OFF_V1F;
    float* dX    = fb + OFF_X;
    float* dATT  = fb + OFF_ATTNF;
    float* dPART = fb + OFF_PART;
    float* dX1   = fb + OFF_X1;
    float* dX2   = fb + OFF_X2;
    float* out   = (float*)d_out;

    constexpr int SMEM_A = 2 * 2 * (128 + 128) * 64;   // 65536
    constexpr int SMEM_B = 2 * 2 * (64 + 64) * 64;     // 32768
    cudaFuncSetAttribute(mma_gemm_big, cudaFuncAttributeMaxDynamicSharedMemorySize, SMEM_A);

    // 1. build dense hi/lo bf16 (gather + zero fill), one launch
    build_dense_kernel<<<BB * (SS + TT), 256>>>(sgm_feats, sbidx, N_sgm,
                                                velo_feats, vbidx, N_velo);

    // 2. all weight transposes, one launch
    transpose_w4_kernel<<<dim3(32, 32, 4), 256>>>(Wq, Wk, Wv2, Wv1);

    // 3. merged big GEMM: [q|v2] (y<16) + [k|v1] (y>=16)
    mma_gemm_big<<<dim3(12, 48), 256, SMEM_A>>>(dTMP, dTMP2);

    // 4. merged dual-LN for both outputs
    dual_ln2_kernel<<<2048 + 4096, 256>>>(dTMP, dTMP2, gq, bq, gv2, bv2,
                                          gk, bk, gv1, bv1, dX, dV1F);

    // 5. v1T: [16][256][512] -> [16][512][256] hi/lo
    transpose_split_kernel<<<dim3(16, 8, BB), 256>>>(dV1F, bb + BO_V1TH, bb + BO_V1TL,
                                                     TT, 512, (long)TT * 512, (long)TT * 512);

    // 6. scores = q @ k^T, softmax -> bf16 hi/lo
    mma_gemm_t<64, 64, 2, 2><<<dim3(4, 2, BB), 128, SMEM_B>>>(
        bb + BO_QH, bb + BO_QL, bb + BO_KH, bb + BO_KL,
        dATT, DD, TT, (long)SS * DD, (long)TT * DD, (long)SS * TT);
    softmax_bf_kernel<<<BB * SS, 256>>>(dATT, bb + BO_ATH, bb + BO_ATL);

    // 7. ctx = attn @ v1 -> X[:, s*1024 + 512..1023]
    mma_gemm_t<64, 64, 2, 2><<<dim3(8, 2, BB), 128, SMEM_B>>>(
        bb + BO_ATH, bb + BO_ATL, bb + BO_V1TH, bb + BO_V1TL,
        dX + 512, TT, DD, (long)SS * TT, (long)512 * TT, (long)FIN);

    // 8. fc3a (f32x2 FMA, DRAM streaming) + fused reduce+LN -> x1
    fc3a_partial_kernel<<<dim3(DD / 256, FIN / 512), 256>>>(dX, W3a, dPART);
    fc3a_reduce_ln_kernel<<<BB, 1024>>>(dPART, g3a, b3a, dX1);

    // 9. fc3b + LN -> x2
    small_gemm_kernel<<<dim3(DD / 256, BB), 256>>>(dX1, W3b, dTMP, DD, DD);
    ln_relu_kernel<<<BB, 256>>>(dTMP, g3b, b3b, dX2, DD);

    // 10. heads
    heads_kernel<<<BB, 256>>>(dX2, Wr, brr, Wt, btt, out);
    (void)out_size;
}

// round 7
// speedup vs baseline: 2.5226x; 1.0278x over previous
#include <cuda_runtime.h>
#include <cuda_bf16.h>
#include <math.h>
#include <stdint.h>

// ---------------- problem constants ----------------
#define BB   16
#define SS   128
#define TT   256
#define DD   1024
#define FIN  (DD * SS)          // 131072
#define LN_EPS 1e-5f

// ---------------- fp32 scratch (floats) ----------------
#define OFF_TMP   0L             // 3145728 (2048 x 1536)  qv2 out
#define OFF_TMP2  3145728L       // 6291456 (4096 x 1536)  kv1 out
#define OFF_V1F   9437184L       // 2097152 (16*256*512)
#define OFF_X     11534336L      // 2097152 (16*131072)
#define OFF_ATTNF 13631488L      // 524288  (16*128*256)
#define OFF_PART  14155776L      // 4194304 (256*16*1024)
#define OFF_X1    18350080L      // 16384
#define OFF_X2    18366464L      // 16384
#define FBUF_TOTAL 18382848L
__device__ __align__(128) float g_buf[FBUF_TOTAL];

// ---------------- bf16 scratch (elements) ----------------
#define BO_SGMH   0L             // 2097152
#define BO_SGML   2097152L
#define BO_VELOH  4194304L       // 4194304
#define BO_VELOL  8388608L
#define BO_QH     12582912L      // 2097152
#define BO_QL     14680064L
#define BO_KH     16777216L      // 4194304
#define BO_KL     20971520L
#define BO_WQV2H  25165824L      // 1572864 ([1536][1024])
#define BO_WQV2L  26738688L
#define BO_WKV1H  28311552L
#define BO_WKV1L  29884416L
#define BO_V1TH   31457280L      // 2097152 ([16][512][256])
#define BO_V1TL   33554432L
#define BO_ATH    35651584L      // 524288
#define BO_ATL    36175872L
#define BBUF_TOTAL 36700160L
__device__ __align__(128) __nv_bfloat16 g_bf[BBUF_TOTAL];

// ================= PTX helpers (baseline ISA, plain sm_103) =======
__device__ __forceinline__ uint32_t smem_u32(const void* p) {
    uint32_t a;
    asm("{ .reg .u64 t; cvta.to.shared.u64 t, %1; cvt.u32.u64 %0, t; }" : "=r"(a) : "l"(p));
    return a;
}
__device__ __forceinline__ void cpasync16(uint32_t dst, const void* src) {
    asm volatile("cp.async.cg.shared.global [%0], [%1], 16;" :: "r"(dst), "l"(src));
}
#define CP_COMMIT() asm volatile("cp.async.commit_group;" ::: "memory")
#define CP_WAIT(n)  asm volatile("cp.async.wait_group %0;" :: "n"(n) : "memory")

__device__ __forceinline__ void ldm_x4(uint32_t addr, uint32_t* r) {
    asm volatile("ldmatrix.sync.aligned.m8n8.x4.shared.b16 {%0,%1,%2,%3}, [%4];"
                 : "=r"(r[0]), "=r"(r[1]), "=r"(r[2]), "=r"(r[3]) : "r"(addr));
}
__device__ __forceinline__ void mma16816(float* d, const uint32_t* a, const uint32_t* b) {
    asm volatile("mma.sync.aligned.m16n8k16.row.col.f32.bf16.bf16.f32 "
                 "{%0,%1,%2,%3}, {%4,%5,%6,%7}, {%8,%9}, {%0,%1,%2,%3};"
                 : "+f"(d[0]), "+f"(d[1]), "+f"(d[2]), "+f"(d[3])
                 : "r"(a[0]), "r"(a[1]), "r"(a[2]), "r"(a[3]), "r"(b[0]), "r"(b[1]));
}

// ---------------- hi/lo split helpers ----------------
__device__ __forceinline__ void split2(float a, float b, unsigned& h, unsigned& l) {
    __nv_bfloat162 hh = __floats2bfloat162_rn(a, b);
    float ra = a - __bfloat162float(__low2bfloat16(hh));
    float rb = b - __bfloat162float(__high2bfloat16(hh));
    __nv_bfloat162 ll = __floats2bfloat162_rn(ra, rb);
    h = *reinterpret_cast<unsigned*>(&hh);
    l = *reinterpret_cast<unsigned*>(&ll);
}

// ================= dense-build body (gather; zero-fill missing) =============
__device__ __forceinline__ void build_slot(int slot, const float* __restrict__ sgm,
                                           const int* __restrict__ sb, int Ns,
                                           const float* __restrict__ velo,
                                           const int* __restrict__ vb, int Nv) {
    const float* feats; const int* bidx; int N, local; long base, ldelta;
    if (slot < BB * SS) { feats = sgm; bidx = sb; N = Ns; local = SS; base = BO_SGMH; ldelta = BO_SGML - BO_SGMH; }
    else { slot -= BB * SS; feats = velo; bidx = vb; N = Nv; local = TT; base = BO_VELOH; ldelta = BO_VELOL - BO_VELOH; }
    int b = slot / local, r = slot % local;
    __shared__ int s_src;
    if (threadIdx.x == 0) {
        int lo = 0, hi = N;
        while (lo < hi) { int mid = (lo + hi) >> 1; if (bidx[mid] < b) lo = mid + 1; else hi = mid; }
        int src = lo + r;
        s_src = (src < N && bidx[src] == b) ? src : -1;
    }
    __syncthreads();
    int src = s_src;
    __nv_bfloat16* dh = g_bf + base + (long)slot * DD;
    __nv_bfloat16* dl = dh + ldelta;
    int c = threadIdx.x * 4;
    uint2 h = make_uint2(0, 0), l = make_uint2(0, 0);
    if (src >= 0) {
        const float4 v = *reinterpret_cast<const float4*>(feats + (long)src * DD + c);
        split2(v.x, v.y, h.x, l.x);
        split2(v.z, v.w, h.y, l.y);
    }
    *reinterpret_cast<uint2*>(dh + c) = h;
    *reinterpret_cast<uint2*>(dl + c) = l;
}

// ================= transpose + split (generic body) ==========================
__device__ __forceinline__ void tsp_body(const float* __restrict__ in,
                                         __nv_bfloat16* __restrict__ oh,
                                         __nv_bfloat16* __restrict__ ol,
                                         int R, int C, int bx, int by) {
    __shared__ float t[32][33];
    int r0 = by * 32, c0 = bx * 32;
    int tx = threadIdx.x & 31, ty = threadIdx.x >> 5;
#pragma unroll
    for (int i = 0; i < 32; i += 8)
        t[ty + i][tx] = in[(long)(r0 + ty + i) * C + c0 + tx];
    __syncthreads();
#pragma unroll
    for (int i = 0; i < 32; i += 8) {
        float v = t[tx][ty + i];
        __nv_bfloat16 h = __float2bfloat16(v);
        __nv_bfloat16 l = __float2bfloat16(v - __bfloat162float(h));
        long o = (long)(c0 + ty + i) * R + r0 + tx;
        oh[o] = h; ol[o] = l;
    }
}

// ================= prep: build_dense (6144) + 4 weight transposes (3072) ====
__global__ void prep_kernel(const float* __restrict__ sgm, const int* __restrict__ sb, int Ns,
                            const float* __restrict__ velo, const int* __restrict__ vb, int Nv,
                            const float* __restrict__ Wq, const float* __restrict__ Wk,
                            const float* __restrict__ Wv2, const float* __restrict__ Wv1) {
    int bid = blockIdx.x;
    if (bid < 6144) { build_slot(bid, sgm, sb, Ns, velo, vb, Nv); return; }
    bid -= 6144;
    if (bid < 1024) {
        tsp_body(Wq, g_bf + BO_WQV2H, g_bf + BO_WQV2L, 1024, 1024, bid & 31, bid >> 5);
    } else if (bid < 2048) {
        bid -= 1024;
        tsp_body(Wk, g_bf + BO_WKV1H, g_bf + BO_WKV1L, 1024, 1024, bid & 31, bid >> 5);
    } else if (bid < 2560) {
        bid -= 2048;
        tsp_body(Wv2, g_bf + BO_WQV2H + 1048576L, g_bf + BO_WQV2L + 1048576L, 1024, 512,
                 bid & 15, bid >> 4);
    } else {
        bid -= 2560;
        tsp_body(Wv1, g_bf + BO_WKV1H + 1048576L, g_bf + BO_WKV1L + 1048576L, 1024, 512,
                 bid & 15, bid >> 4);
    }
}

// batched v1 transpose
__global__ void transpose_split_kernel(const float* __restrict__ in,
                                       __nv_bfloat16* __restrict__ oh,
                                       __nv_bfloat16* __restrict__ ol,
                                       int R, int C, long inB, long outB) {
    int z = blockIdx.z;
    tsp_body(in + (long)z * inB, oh + (long)z * outB, ol + (long)z * outB,
             R, C, blockIdx.x, blockIdx.y);
}

// ================= HMMA GEMM body: C = A[M,K] @ B[N,K]^T (tile) =============
template<int BM, int BN, int WM_CNT, int WN_CNT>
__device__ __forceinline__ void gemm_body(
    const __nv_bfloat16* __restrict__ Ah, const __nv_bfloat16* __restrict__ Al,
    const __nv_bfloat16* __restrict__ Bh, const __nv_bfloat16* __restrict__ Bl,
    float* __restrict__ Cp, int K, int ldc, uint32_t sb) {
    constexpr int T   = 32 * WM_CNT * WN_CNT;
    constexpr int WTM = BM / WM_CNT, WTN = BN / WN_CNT;
    constexpr int MI  = WTM / 16;
    constexpr int NB  = WTN / 16;
    constexpr int NJ  = WTN / 8;
    constexpr int OAL = BM * 64, OBH = 2 * BM * 64, OBL = OBH + BN * 64;
    constexpr int STAGE = 2 * (BM + BN) * 64;
    constexpr int RPT = T >> 2;
    constexpr int AIT = BM / RPT, BIT = BN / RPT;

    const int tid = threadIdx.x, lane = tid & 31, wid = tid >> 5;
    const int wm = wid % WM_CNT, wn = wid / WM_CNT;
    const int r_ld = tid >> 2, c_ld = tid & 3;

    float acc[MI][NJ][4];
#pragma unroll
    for (int i = 0; i < MI; i++)
#pragma unroll
        for (int j = 0; j < NJ; j++)
#pragma unroll
            for (int q = 0; q < 4; q++) acc[i][j][q] = 0.f;

    const int NC = K >> 5;

    auto load_chunk = [&](int ci, int st) {
        const int k0 = ci << 5;
        const uint32_t s0 = sb + (uint32_t)st * STAGE;
#pragma unroll
        for (int i = 0; i < AIT; i++) {
            int r = r_ld + i * RPT;
            uint32_t d = (uint32_t)(r * 64 + ((c_ld ^ (r & 3)) << 4));
            long go = (long)r * K + k0 + c_ld * 8;
            cpasync16(s0 + d,       Ah + go);
            cpasync16(s0 + OAL + d, Al + go);
        }
#pragma unroll
        for (int i = 0; i < BIT; i++) {
            int r = r_ld + i * RPT;
            uint32_t d = (uint32_t)(r * 64 + ((c_ld ^ (r & 3)) << 4));
            long go = (long)r * K + k0 + c_ld * 8;
            cpasync16(s0 + OBH + d, Bh + go);
            cpasync16(s0 + OBL + d, Bl + go);
        }
    };

    const int a_sub = ((lane >> 3) & 1) * 8 + (lane & 7);
    const int a_kc = lane >> 4;
    const int b_sub = ((lane >> 4) & 1) * 8 + (lane & 7);
    const int b_kc = (lane >> 3) & 1;

    load_chunk(0, 0); CP_COMMIT();

    for (int i = 0; i < NC; i++) {
        if (i + 1 < NC) { load_chunk(i + 1, (i + 1) & 1); CP_COMMIT(); CP_WAIT(1); }
        else            { CP_WAIT(0); }
        __syncthreads();
        const uint32_t s0 = sb + ((i & 1) ? (uint32_t)STAGE : 0u);
#pragma unroll
        for (int ks = 0; ks < 2; ks++) {
            uint32_t ah[MI][4], al[MI][4];
#pragma unroll
            for (int mi = 0; mi < MI; mi++) {
                int mrow = wm * WTM + mi * 16 + a_sub;
                int kc = ks * 2 + a_kc;
                uint32_t ad = s0 + mrow * 64 + ((kc ^ (mrow & 3)) << 4);
                ldm_x4(ad, ah[mi]);
                ldm_x4(ad + OAL, al[mi]);
            }
#pragma unroll
            for (int np = 0; np < NB; np++) {
                int nrow = wn * WTN + np * 16 + b_sub;
                int kc = ks * 2 + b_kc;
                uint32_t bd = s0 + OBH + nrow * 64 + ((kc ^ (nrow & 3)) << 4);
                uint32_t bh[4], bl[4];
                ldm_x4(bd, bh);
                ldm_x4(bd + BN * 64, bl);
#pragma unroll
                for (int mi = 0; mi < MI; mi++)
#pragma unroll
                    for (int j = 0; j < 2; j++) {
                        float* a4 = acc[mi][np * 2 + j];
                        mma16816(a4, ah[mi], bh + 2 * j);
                        mma16816(a4, ah[mi], bl + 2 * j);
                        mma16816(a4, al[mi], bh + 2 * j);
                    }
            }
        }
        __syncthreads();
    }

    const int er = lane >> 2, ec = (lane & 3) * 2;
    const long mb = wm * WTM + er;
    const int nb = wn * WTN + ec;
#pragma unroll
    for (int mi = 0; mi < MI; mi++)
#pragma unroll
        for (int nj = 0; nj < NJ; nj++) {
            float* p0 = Cp + (mb + mi * 16) * ldc + nb + nj * 8;
            float* p1 = p0 + 8L * ldc;
            *reinterpret_cast<float2*>(p0) = make_float2(acc[mi][nj][0], acc[mi][nj][1]);
            *reinterpret_cast<float2*>(p1) = make_float2(acc[mi][nj][2], acc[mi][nj][3]);
        }
}

// merged big GEMM: qv2 (blockIdx.y<16) + kv1 (y>=16); grid (12, 48)
__global__ __launch_bounds__(256, 2)
void mma_gemm_big(float* __restrict__ c1, float* __restrict__ c2) {
    extern __shared__ char smem[];
    const uint32_t sb = smem_u32(smem);
    const int K = DD, ldc = 1536;
    const long n0 = (long)blockIdx.x * 128;
    const __nv_bfloat16 *Ah, *Al, *Bh, *Bl;
    float* Cp;
    if (blockIdx.y < 16) {
        long m0 = (long)blockIdx.y * 128;
        Ah = g_bf + BO_SGMH + m0 * K;  Al = g_bf + BO_SGML + m0 * K;
        Bh = g_bf + BO_WQV2H + n0 * K; Bl = g_bf + BO_WQV2L + n0 * K;
        Cp = c1 + m0 * ldc + n0;
    } else {
        long m0 = (long)(blockIdx.y - 16) * 128;
        Ah = g_bf + BO_VELOH + m0 * K; Al = g_bf + BO_VELOL + m0 * K;
        Bh = g_bf + BO_WKV1H + n0 * K; Bl = g_bf + BO_WKV1L + n0 * K;
        Cp = c2 + m0 * ldc + n0;
    }
    gemm_body<128, 128, 4, 2>(Ah, Al, Bh, Bl, Cp, K, ldc, sb);
}

// small batched GEMM kernel (scores / ctx)
template<int BM, int BN, int WM_CNT, int WN_CNT>
__global__ __launch_bounds__(32 * WM_CNT * WN_CNT, 2)
void mma_gemm_t(const __nv_bfloat16* __restrict__ Ahp, const __nv_bfloat16* __restrict__ Alp,
                const __nv_bfloat16* __restrict__ Bhp, const __nv_bfloat16* __restrict__ Blp,
                float* __restrict__ C, int K, int ldc,
                long aB, long bB, long cB) {
    extern __shared__ char smem[];
    const uint32_t sb = smem_u32(smem);
    const int z = blockIdx.z;
    const long m0 = (long)blockIdx.y * BM, n0 = (long)blockIdx.x * BN;
    gemm_body<BM, BN, WM_CNT, WN_CNT>(
        Ahp + (long)z * aB + m0 * K, Alp + (long)z * aB + m0 * K,
        Bhp + (long)z * bB + n0 * K, Blp + (long)z * bB + n0 * K,
        C + (long)z * cB + m0 * ldc + n0, K, ldc, sb);
}

// ================= merged dual LayerNorm+ReLU (vectorized) ==================
__global__ void dual_ln2_kernel(const float* __restrict__ in1, const float* __restrict__ in2,
                                const float* __restrict__ gq, const float* __restrict__ bq,
                                const float* __restrict__ gv2, const float* __restrict__ bv2,
                                const float* __restrict__ gk, const float* __restrict__ bk,
                                const float* __restrict__ gv1, const float* __restrict__ bv1,
                                float* __restrict__ dX, float* __restrict__ dV1F) {
    int row = blockIdx.x, t = threadIdx.x;
    int lane = t & 31, wid = t >> 5;
    const float* ip;
    const float *g1, *b1, *g2, *b2;
    __nv_bfloat16 *oh, *ol;
    float* out2;
    if (row < 2048) {
        ip = in1 + (long)row * 1536;
        g1 = gq; b1 = bq; g2 = gv2; b2 = bv2;
        oh = g_bf + BO_QH + (long)row * 1024;
        ol = g_bf + BO_QL + (long)row * 1024;
        out2 = dX + (long)(row >> 7) * FIN + (long)(row & 127) * 1024;
    } else {
        int r2 = row - 2048;
        ip = in2 + (long)r2 * 1536;
        g1 = gk; b1 = bk; g2 = gv1; b2 = bv1;
        oh = g_bf + BO_KH + (long)r2 * 1024;
        ol = g_bf + BO_KL + (long)r2 * 1024;
        out2 = dV1F + (long)r2 * 512;
    }
    __shared__ float ws[8], wq[8];

    // ---- segment 1: cols [0,1024), thread owns 4 contiguous ----
    float4 va = *reinterpret_cast<const float4*>(ip + 4 * t);
    float s = va.x + va.y + va.z + va.w;
    float ss = va.x * va.x + va.y * va.y + va.z * va.z + va.w * va.w;
#pragma unroll
    for (int o = 16; o > 0; o >>= 1) {
        s  += __shfl_down_sync(0xffffffffu, s, o);
        ss += __shfl_down_sync(0xffffffffu, ss, o);
    }
    if (lane == 0) { ws[wid] = s; wq[wid] = ss; }
    __syncthreads();
    float st = 0.f, sq = 0.f;
#pragma unroll
    for (int i = 0; i < 8; i++) { st += ws[i]; sq += wq[i]; }
    float mean = st * (1.f / 1024.f);
    float var = sq * (1.f / 1024.f) - mean * mean;
    float r = rsqrtf(var + LN_EPS);
    {
        float4 gg = *reinterpret_cast<const float4*>(g1 + 4 * t);
        float4 bb = *reinterpret_cast<const float4*>(b1 + 4 * t);
        float v0 = fmaxf((va.x - mean) * r * gg.x + bb.x, 0.f);
        float v1 = fmaxf((va.y - mean) * r * gg.y + bb.y, 0.f);
        float v2 = fmaxf((va.z - mean) * r * gg.z + bb.z, 0.f);
        float v3 = fmaxf((va.w - mean) * r * gg.w + bb.w, 0.f);
        uint2 h, l;
        split2(v0, v1, h.x, l.x);
        split2(v2, v3, h.y, l.y);
        *reinterpret_cast<uint2*>(oh + 4 * t) = h;
        *reinterpret_cast<uint2*>(ol + 4 * t) = l;
    }

    // ---- segment 2: cols [1024,1536), thread owns 2 contiguous ----
    float2 vb = *reinterpret_cast<const float2*>(ip + 1024 + 2 * t);
    s = vb.x + vb.y;
    ss = vb.x * vb.x + vb.y * vb.y;
#pragma unroll
    for (int o = 16; o > 0; o >>= 1) {
        s  += __shfl_down_sync(0xffffffffu, s, o);
        ss += __shfl_down_sync(0xffffffffu, ss, o);
    }
    __syncthreads();
    if (lane == 0) { ws[wid] = s; wq[wid] = ss; }
    __syncthreads();
    st = 0.f; sq = 0.f;
#pragma unroll
    for (int i = 0; i < 8; i++) { st += ws[i]; sq += wq[i]; }
    mean = st * (1.f / 512.f);
    var = sq * (1.f / 512.f) - mean * mean;
    r = rsqrtf(var + LN_EPS);
    {
        float2 gg = *reinterpret_cast<const float2*>(g2 + 2 * t);
        float2 bb = *reinterpret_cast<const float2*>(b2 + 2 * t);
        float2 o2;
        o2.x = fmaxf((vb.x - mean) * r * gg.x + bb.x, 0.f);
        o2.y = fmaxf((vb.y - mean) * r * gg.y + bb.y, 0.f);
        *reinterpret_cast<float2*>(out2 + 2 * t) = o2;
    }
}

// ================= plain LN+ReLU (fp32 out) =================
__global__ void ln_relu_kernel(const float* __restrict__ in,
                               const float* __restrict__ gamma,
                               const float* __restrict__ beta,
                               float* __restrict__ outp, int C) {
    int row = blockIdx.x;
    int t = threadIdx.x;
    const float* ip = in + (long)row * C;
    float s = 0.f, ss = 0.f;
    for (int c = t; c < C; c += 256) { float v = ip[c]; s += v; ss += v * v; }
    __shared__ float rs[256], rq[256];
    rs[t] = s; rq[t] = ss;
    __syncthreads();
    for (int o = 128; o > 0; o >>= 1) {
        if (t < o) { rs[t] += rs[t + o]; rq[t] += rq[t + o]; }
        __syncthreads();
    }
    float mean = rs[0] / C;
    float var = rq[0] / C - mean * mean;
    float r = rsqrtf(var + LN_EPS);
    float* op = outp + (long)row * C;
    for (int c = t; c < C; c += 256) {
        float v = (ip[c] - mean) * r * gamma[c] + beta[c];
        op[c] = fmaxf(v, 0.f);
    }
}

// ================= softmax (256 wide) -> packed bf16 hi/lo ================
__global__ void softmax_bf_kernel(const float* __restrict__ sc,
                                  __nv_bfloat16* __restrict__ oh,
                                  __nv_bfloat16* __restrict__ ol) {
    int row = blockIdx.x;
    int t = threadIdx.x;
    float v = sc[(long)row * 256 + t];
    __shared__ float red[256];
    red[t] = v;
    __syncthreads();
    for (int o = 128; o > 0; o >>= 1) { if (t < o) red[t] = fmaxf(red[t], red[t + o]); __syncthreads(); }
    float mx = red[0];
    __syncthreads();
    float e = __expf(v - mx);
    red[t] = e;
    __syncthreads();
    for (int o = 128; o > 0; o >>= 1) { if (t < o) red[t] += red[t + o]; __syncthreads(); }
    float p = e / red[0];
    float pn = __shfl_down_sync(0xffffffffu, p, 1);
    if ((t & 1) == 0) {
        unsigned h, l;
        split2(p, pn, h, l);
        *reinterpret_cast<unsigned*>(oh + (long)row * 256 + t) = h;
        *reinterpret_cast<unsigned*>(ol + (long)row * 256 + t) = l;
    }
}

// ================= fc3a: streaming split-K over W3a (packed f32x2 FMA) ======
__global__ __launch_bounds__(256)
void fc3a_partial_kernel(const float* __restrict__ x, const float* __restrict__ W,
                         float* __restrict__ part) {
    __shared__ float2 xs[512][8];   // 32KB
    const int n = blockIdx.x * 256 + threadIdx.x;
    const int f0 = blockIdx.y * 512;
#pragma unroll
    for (int it = 0; it < 32; it++) {
        int i = threadIdx.x + 256 * it;
        int b = i >> 9, f = i & 511;
        float v = x[(long)b * FIN + f0 + f];
        reinterpret_cast<float*>(&xs[f][(b >> 1) ^ (f & 7)])[b & 1] = v;
    }
    __syncthreads();

    unsigned long long acc[8];
#pragma unroll
    for (int p = 0; p < 8; p++) acc[p] = 0ull;

    const float* Wp = W + (long)f0 * DD + n;
#pragma unroll 8
    for (int f = 0; f < 512; f++) {
        float w = Wp[(long)f * DD];
        unsigned long long wp;
        asm("mov.b64 %0, {%1,%1};" : "=l"(wp) : "r"(__float_as_uint(w)));
        const float2* row = xs[f];
        const int f7 = f & 7;
#pragma unroll
        for (int p = 0; p < 8; p++) {
            unsigned long long xv =
                *reinterpret_cast<const unsigned long long*>(&row[p ^ f7]);
            asm("fma.rn.f32x2 %0, %1, %2, %0;" : "+l"(acc[p]) : "l"(xv), "l"(wp));
        }
    }
#pragma unroll
    for (int p = 0; p < 8; p++) {
        unsigned lo, hi;
        asm("mov.b64 {%0,%1}, %2;" : "=r"(lo), "=r"(hi) : "l"(acc[p]));
        part[((long)blockIdx.y * BB + 2 * p) * DD + n]     = __uint_as_float(lo);
        part[((long)blockIdx.y * BB + 2 * p + 1) * DD + n] = __uint_as_float(hi);
    }
}

// fused reduce(256 chunks) + LayerNorm + ReLU -> x1; grid 16, block 1024
__global__ __launch_bounds__(1024)
void fc3a_reduce_ln_kernel(const float* __restrict__ part,
                           const float* __restrict__ gamma, const float* __restrict__ beta,
                           float* __restrict__ x1) {
    int b = blockIdx.x, n = threadIdx.x;
    float s = 0.f;
#pragma unroll 4
    for (int c = 0; c < 256; c++) s += part[((long)c * BB + b) * DD + n];
    __shared__ float rs[1024], rq[1024];
    rs[n] = s; rq[n] = s * s;
    __syncthreads();
    for (int o = 512; o > 0; o >>= 1) {
        if (n < o) { rs[n] += rs[n + o]; rq[n] += rq[n + o]; }
        __syncthreads();
    }
    float mean = rs[0] * (1.f / 1024.f);
    float var = rq[0] * (1.f / 1024.f) - mean * mean;
    float r = rsqrtf(var + LN_EPS);
    float v = (s - mean) * r * gamma[n] + beta[n];
    x1[(long)b * DD + n] = fmaxf(v, 0.f);
}

// ================= fc3b: [16,1024] @ [1024,1024] =================
__global__ void small_gemm_kernel(const float* __restrict__ A, const float* __restrict__ W,
                                  float* __restrict__ C, int K, int N) {
    int n = blockIdx.x * 256 + threadIdx.x;
    int b = blockIdx.y;
    float acc = 0.f;
#pragma unroll 4
    for (int k = 0; k < K; k++) acc += A[(long)b * K + k] * W[(long)k * N + n];
    C[(long)b * N + n] = acc;
}

// ================= heads =================
__global__ void heads_kernel(const float* __restrict__ x2,
                             const float* __restrict__ Wr, const float* __restrict__ br,
                             const float* __restrict__ Wt, const float* __restrict__ bt,
                             float* __restrict__ out) {
    int b = blockIdx.x;
    int w = threadIdx.x >> 5, lane = threadIdx.x & 31;
    __shared__ float vals[7];
    if (w < 7) {
        const float* Wp = (w < 4) ? Wr : Wt;
        int ncol = (w < 4) ? 4 : 3;
        int j = (w < 4) ? w : (w - 4);
        float acc = 0.f;
        for (int k = lane; k < DD; k += 32) acc += x2[(long)b * DD + k] * Wp[(long)k * ncol + j];
        for (int o = 16; o > 0; o >>= 1) acc += __shfl_down_sync(0xffffffffu, acc, o);
        if (lane == 0) vals[w] = acc + ((w < 4) ? br[j] : bt[j]);
    }
    __syncthreads();
    if (threadIdx.x == 0) {
        float nn = sqrtf(vals[0]*vals[0] + vals[1]*vals[1] + vals[2]*vals[2] + vals[3]*vals[3]);
        nn = fmaxf(nn, 1e-12f);
        for (int j = 0; j < 4; j++) out[b * 4 + j] = vals[j] / nn;
        for (int j = 0; j < 3; j++) out[64 + b * 3 + j] = vals[4 + j];
    }
}

// ================= host driver =================
extern "C" void kernel_launch(void* const* d_in, const int* in_sizes, int n_in,
                              void* d_out, int out_size) {
    const float* sgm_feats = nullptr; const float* velo_feats = nullptr;
    const int* sbidx = nullptr; const int* vbidx = nullptr;
    int N_sgm = 0, N_velo = 0;
    const float* w[22]; int wi = 0;
    for (int i = 0; i < n_in; i++) {
        int s = in_sizes[i];
        if (s == 3000 * 1024)      { sgm_feats = (const float*)d_in[i]; }
        else if (s == 6000 * 1024) { velo_feats = (const float*)d_in[i]; }
        else if (s == 3000)        { sbidx = (const int*)d_in[i]; N_sgm = s; }
        else if (s == 6000)        { vbidx = (const int*)d_in[i]; N_velo = s; }
        else if (wi < 22)          { w[wi++] = (const float*)d_in[i]; }
    }
    const float *gq = w[1], *bq = w[2];
    const float *Wq = w[0], *Wk = w[3], *gk = w[4], *bk = w[5];
    const float *Wv1 = w[6], *gv1 = w[7], *bv1 = w[8];
    const float *Wv2 = w[9], *gv2 = w[10], *bv2 = w[11];
    const float *W3a = w[12], *g3a = w[13], *b3a = w[14];
    const float *W3b = w[15], *g3b = w[16], *b3b = w[17];
    const float *Wr = w[18], *brr = w[19], *Wt = w[20], *btt = w[21];

    float* fb = nullptr;
    cudaGetSymbolAddress((void**)&fb, g_buf);
    __nv_bfloat16* bb = nullptr;
    cudaGetSymbolAddress((void**)&bb, g_bf);

    float* dTMP  = fb + OFF_TMP;
    float* dTMP2 = fb + OFF_TMP2;
    float* dV1F  = fb + OFF_V1F;
    float* dX    = fb + OFF_X;
    float* dATT  = fb + OFF_ATTNF;
    float* dPART = fb + OFF_PART;
    float* dX1   = fb + OFF_X1;
    float* dX2   = fb + OFF_X2;
    float* out   = (float*)d_out;

    constexpr int SMEM_A = 2 * 2 * (128 + 128) * 64;   // 65536
    constexpr int SMEM_B = 2 * 2 * (64 + 64) * 64;     // 32768
    constexpr int SMEM_C = 2 * 2 * (32 + 64) * 64;     // 24576
    cudaFuncSetAttribute(mma_gemm_big, cudaFuncAttributeMaxDynamicSharedMemorySize, SMEM_A);

    // 1. prep: dense build + all weight transposes, one launch
    prep_kernel<<<6144 + 3072, 256>>>(sgm_feats, sbidx, N_sgm, velo_feats, vbidx, N_velo,
                                      Wq, Wk, Wv2, Wv1);

    // 2. merged big GEMM: [q|v2] (y<16) + [k|v1] (y>=16)
    mma_gemm_big<<<dim3(12, 48), 256, SMEM_A>>>(dTMP, dTMP2);

    // 3. merged dual-LN for both outputs
    dual_ln2_kernel<<<2048 + 4096, 256>>>(dTMP, dTMP2, gq, bq, gv2, bv2,
                                          gk, bk, gv1, bv1, dX, dV1F);

    // 4. v1T: [16][256][512] -> [16][512][256] hi/lo
    transpose_split_kernel<<<dim3(16, 8, BB), 256>>>(dV1F, bb + BO_V1TH, bb + BO_V1TL,
                                                     TT, 512, (long)TT * 512, (long)TT * 512);

    // 5. scores = q @ k^T (32x64 tiles -> 256 CTAs), softmax -> packed bf16
    mma_gemm_t<32, 64, 2, 2><<<dim3(4, 4, BB), 128, SMEM_C>>>(
        bb + BO_QH, bb + BO_QL, bb + BO_KH, bb + BO_KL,
        dATT, DD, TT, (long)SS * DD, (long)TT * DD, (long)SS * TT);
    softmax_bf_kernel<<<BB * SS, 256>>>(dATT, bb + BO_ATH, bb + BO_ATL);

    // 6. ctx = attn @ v1 -> X[:, s*1024 + 512..1023]
    mma_gemm_t<64, 64, 2, 2><<<dim3(8, 2, BB), 128, SMEM_B>>>(
        bb + BO_ATH, bb + BO_ATL, bb + BO_V1TH, bb + BO_V1TL,
        dX + 512, TT, DD, (long)SS * TT, (long)512 * TT, (long)FIN);

    // 7. fc3a (f32x2 FMA, DRAM streaming) + fused reduce+LN -> x1
    fc3a_partial_kernel<<<dim3(DD / 256, FIN / 512), 256>>>(dX, W3a, dPART);
    fc3a_reduce_ln_kernel<<<BB, 1024>>>(dPART, g3a, b3a, dX1);

    // 8. fc3b + LN -> x2
    small_gemm_kernel<<<dim3(DD / 256, BB), 256>>>(dX1, W3b, dTMP, DD, DD);
    ln_relu_kernel<<<BB, 256>>>(dTMP, g3b, b3b, dX2, DD);

    // 9. heads
    heads_kernel<<<BB, 256>>>(dX2, Wr, brr, Wt, btt, out);
    (void)out_size;
}

// round 9
// speedup vs baseline: 2.5281x; 1.0022x over previous
#include <cuda_runtime.h>
#include <cuda_fp16.h>
#include <math.h>
#include <stdint.h>

// ---------------- problem constants ----------------
#define BB   16
#define SS   128
#define TT   256
#define DD   1024
#define FIN  (DD * SS)          // 131072
#define LN_EPS 1e-5f

// ---------------- fp32 scratch (floats) ----------------
#define OFF_TMP   0L             // 3145728 (2048 x 1536)  qv2 out
#define OFF_TMP2  3145728L       // 6291456 (4096 x 1536)  kv1 out
#define OFF_V1F   9437184L       // 2097152 (16*256*512)
#define OFF_X     11534336L      // 2097152 (16*131072)
#define OFF_ATTNF 13631488L      // 524288  (16*128*256)
#define OFF_PART  14155776L      // 4194304 (256*16*1024)
#define OFF_X1    18350080L      // 16384
#define OFF_X2    18366464L      // 16384
#define FBUF_TOTAL 18382848L
__device__ __align__(128) float g_buf[FBUF_TOTAL];

// ---------------- fp16 scratch (elements) ----------------
#define BO_SGMH   0L             // 2097152
#define BO_SGML   2097152L
#define BO_VELOH  4194304L       // 4194304
#define BO_VELOL  8388608L
#define BO_QH     12582912L      // 2097152
#define BO_QL     14680064L
#define BO_KH     16777216L      // 4194304
#define BO_KL     20971520L
#define BO_WQV2H  25165824L      // 1572864 ([1536][1024])
#define BO_WQV2L  26738688L
#define BO_WKV1H  28311552L
#define BO_WKV1L  29884416L
#define BO_V1TH   31457280L      // 2097152 ([16][512][256])
#define BO_V1TL   33554432L
#define BO_ATH    35651584L      // 524288
#define BO_ATL    36175872L
#define BBUF_TOTAL 36700160L
__device__ __align__(128) __half g_hf[BBUF_TOTAL];

// ================= PTX helpers (baseline ISA, plain sm_103) =======
__device__ __forceinline__ uint32_t smem_u32(const void* p) {
    uint32_t a;
    asm("{ .reg .u64 t; cvta.to.shared.u64 t, %1; cvt.u32.u64 %0, t; }" : "=r"(a) : "l"(p));
    return a;
}
__device__ __forceinline__ void cpasync16(uint32_t dst, const void* src) {
    asm volatile("cp.async.cg.shared.global [%0], [%1], 16;" :: "r"(dst), "l"(src));
}
#define CP_COMMIT() asm volatile("cp.async.commit_group;" ::: "memory")
#define CP_WAIT(n)  asm volatile("cp.async.wait_group %0;" :: "n"(n) : "memory")

__device__ __forceinline__ void ldm_x4(uint32_t addr, uint32_t* r) {
    asm volatile("ldmatrix.sync.aligned.m8n8.x4.shared.b16 {%0,%1,%2,%3}, [%4];"
                 : "=r"(r[0]), "=r"(r[1]), "=r"(r[2]), "=r"(r[3]) : "r"(addr));
}
__device__ __forceinline__ void mma16816h(float* d, const uint32_t* a, const uint32_t* b) {
    asm volatile("mma.sync.aligned.m16n8k16.row.col.f32.f16.f16.f32 "
                 "{%0,%1,%2,%3}, {%4,%5,%6,%7}, {%8,%9}, {%0,%1,%2,%3};"
                 : "+f"(d[0]), "+f"(d[1]), "+f"(d[2]), "+f"(d[3])
                 : "r"(a[0]), "r"(a[1]), "r"(a[2]), "r"(a[3]), "r"(b[0]), "r"(b[1]));
}

// ---------------- fp16 split helpers ----------------
__device__ __forceinline__ void split2h(float a, float b, unsigned& h, unsigned& l) {
    __half2 hh = __floats2half2_rn(a, b);
    float ra = a - __half2float(__low2half(hh));
    float rb = b - __half2float(__high2half(hh));
    __half2 ll = __floats2half2_rn(ra, rb);
    h = *reinterpret_cast<unsigned*>(&hh);
    l = *reinterpret_cast<unsigned*>(&ll);
}

// ================= dense-build body (gather; zero-fill missing) =============
__device__ __forceinline__ void build_slot(int slot, const float* __restrict__ sgm,
                                           const int* __restrict__ sb, int Ns,
                                           const float* __restrict__ velo,
                                           const int* __restrict__ vb, int Nv) {
    const float* feats; const int* bidx; int N, local; long base, ldelta;
    if (slot < BB * SS) { feats = sgm; bidx = sb; N = Ns; local = SS; base = BO_SGMH; ldelta = BO_SGML - BO_SGMH; }
    else { slot -= BB * SS; feats = velo; bidx = vb; N = Nv; local = TT; base = BO_VELOH; ldelta = BO_VELOL - BO_VELOH; }
    int b = slot / local, r = slot % local;
    __shared__ int s_src;
    if (threadIdx.x == 0) {
        int lo = 0, hi = N;
        while (lo < hi) { int mid = (lo + hi) >> 1; if (bidx[mid] < b) lo = mid + 1; else hi = mid; }
        int src = lo + r;
        s_src = (src < N && bidx[src] == b) ? src : -1;
    }
    __syncthreads();
    int src = s_src;
    __half* dh = g_hf + base + (long)slot * DD;
    __half* dl = dh + ldelta;
    int c = threadIdx.x * 4;
    uint2 h = make_uint2(0, 0), l = make_uint2(0, 0);
    if (src >= 0) {
        const float4 v = *reinterpret_cast<const float4*>(feats + (long)src * DD + c);
        split2h(v.x, v.y, h.x, l.x);
        split2h(v.z, v.w, h.y, l.y);
    }
    *reinterpret_cast<uint2*>(dh + c) = h;
    *reinterpret_cast<uint2*>(dl + c) = l;
}

// ================= transpose + split hi/lo body =============================
__device__ __forceinline__ void tsp_body(float (*t)[33], const float* __restrict__ in,
                                         __half* __restrict__ oh, __half* __restrict__ ol,
                                         int R, int C, int bx, int by) {
    int r0 = by * 32, c0 = bx * 32;
    int tx = threadIdx.x & 31, ty = threadIdx.x >> 5;
#pragma unroll
    for (int i = 0; i < 32; i += 8)
        t[ty + i][tx] = in[(long)(r0 + ty + i) * C + c0 + tx];
    __syncthreads();
#pragma unroll
    for (int i = 0; i < 32; i += 8) {
        float v = t[tx][ty + i];
        __half h = __float2half_rn(v);
        __half l = __float2half_rn(v - __half2float(h));
        long o = (long)(c0 + ty + i) * R + r0 + tx;
        oh[o] = h; ol[o] = l;
    }
}

// ================= fc3a half body (packed f32x2 FMA) ========================
__device__ __forceinline__ void fc3a_half_body(float2 (*xs)[8],
                                               const float* __restrict__ W,
                                               int nchunk, int c, int half) {
    const float* x = g_buf + OFF_X;
    float* part = g_buf + OFF_PART;
    const int n = nchunk * 256 + threadIdx.x;
    const int f0 = c * 1024 + half * 512;
#pragma unroll
    for (int it = 0; it < 32; it++) {
        int i = threadIdx.x + 256 * it;
        int b = i >> 9, f = i & 511;
        float v = x[(long)b * FIN + f0 + f];
        reinterpret_cast<float*>(&xs[f][(b >> 1) ^ (f & 7)])[b & 1] = v;
    }
    __syncthreads();

    unsigned long long acc[8];
#pragma unroll
    for (int p = 0; p < 8; p++) acc[p] = 0ull;

    const float* Wp = W + (long)f0 * DD + n;
#pragma unroll 8
    for (int f = 0; f < 512; f++) {
        float w = Wp[(long)f * DD];
        unsigned long long wp;
        asm("mov.b64 %0, {%1,%1};" : "=l"(wp) : "r"(__float_as_uint(w)));
        const float2* row = xs[f];
        const int f7 = f & 7;
#pragma unroll
        for (int p = 0; p < 8; p++) {
            unsigned long long xv =
                *reinterpret_cast<const unsigned long long*>(&row[p ^ f7]);
            asm("fma.rn.f32x2 %0, %1, %2, %0;" : "+l"(acc[p]) : "l"(xv), "l"(wp));
        }
    }
    const int ci = half * 128 + c;
#pragma unroll
    for (int p = 0; p < 8; p++) {
        unsigned lo, hi;
        asm("mov.b64 {%0,%1}, %2;" : "=r"(lo), "=r"(hi) : "l"(acc[p]));
        part[((long)ci * BB + 2 * p) * DD + n]     = __uint_as_float(lo);
        part[((long)ci * BB + 2 * p + 1) * DD + n] = __uint_as_float(hi);
    }
}

// ================= HMMA GEMM body (fp16 3-term) =============================
template<int BM, int BN, int WM_CNT, int WN_CNT>
__device__ __forceinline__ void gemm_body(
    const __half* __restrict__ Ah, const __half* __restrict__ Al,
    const __half* __restrict__ Bh, const __half* __restrict__ Bl,
    float* __restrict__ Cp, int K, int ldc, uint32_t sb) {
    constexpr int T   = 32 * WM_CNT * WN_CNT;
    constexpr int WTM = BM / WM_CNT, WTN = BN / WN_CNT;
    constexpr int MI  = WTM / 16;
    constexpr int NB  = WTN / 16;
    constexpr int NJ  = WTN / 8;
    constexpr int OAL = BM * 64, OBH = 2 * BM * 64, OBL = OBH + BN * 64;
    constexpr int STAGE = 2 * (BM + BN) * 64;
    constexpr int RPT = T >> 2;
    constexpr int AIT = BM / RPT, BIT = BN / RPT;

    const int tid = threadIdx.x, lane = tid & 31, wid = tid >> 5;
    const int wm = wid % WM_CNT, wn = wid / WM_CNT;
    const int r_ld = tid >> 2, c_ld = tid & 3;

    float acc[MI][NJ][4];
#pragma unroll
    for (int i = 0; i < MI; i++)
#pragma unroll
        for (int j = 0; j < NJ; j++)
#pragma unroll
            for (int q = 0; q < 4; q++) acc[i][j][q] = 0.f;

    const int NC = K >> 5;

    auto load_chunk = [&](int ci, int st) {
        const int k0 = ci << 5;
        const uint32_t s0 = sb + (uint32_t)st * STAGE;
#pragma unroll
        for (int i = 0; i < AIT; i++) {
            int r = r_ld + i * RPT;
            uint32_t d = (uint32_t)(r * 64 + ((c_ld ^ (r & 3)) << 4));
            long go = (long)r * K + k0 + c_ld * 8;
            cpasync16(s0 + d,       Ah + go);
            cpasync16(s0 + OAL + d, Al + go);
        }
#pragma unroll
        for (int i = 0; i < BIT; i++) {
            int r = r_ld + i * RPT;
            uint32_t d = (uint32_t)(r * 64 + ((c_ld ^ (r & 3)) << 4));
            long go = (long)r * K + k0 + c_ld * 8;
            cpasync16(s0 + OBH + d, Bh + go);
            cpasync16(s0 + OBL + d, Bl + go);
        }
    };

    const int a_sub = ((lane >> 3) & 1) * 8 + (lane & 7);
    const int a_kc = lane >> 4;
    const int b_sub = ((lane >> 4) & 1) * 8 + (lane & 7);
    const int b_kc = (lane >> 3) & 1;

    load_chunk(0, 0); CP_COMMIT();

    for (int i = 0; i < NC; i++) {
        if (i + 1 < NC) { load_chunk(i + 1, (i + 1) & 1); CP_COMMIT(); CP_WAIT(1); }
        else            { CP_WAIT(0); }
        __syncthreads();
        const uint32_t s0 = sb + ((i & 1) ? (uint32_t)STAGE : 0u);
#pragma unroll
        for (int ks = 0; ks < 2; ks++) {
            uint32_t ah[MI][4], al[MI][4];
#pragma unroll
            for (int mi = 0; mi < MI; mi++) {
                int mrow = wm * WTM + mi * 16 + a_sub;
                int kc = ks * 2 + a_kc;
                uint32_t ad = s0 + mrow * 64 + ((kc ^ (mrow & 3)) << 4);
                ldm_x4(ad, ah[mi]);
                ldm_x4(ad + OAL, al[mi]);
            }
#pragma unroll
            for (int np = 0; np < NB; np++) {
                int nrow = wn * WTN + np * 16 + b_sub;
                int kc = ks * 2 + b_kc;
                uint32_t bd = s0 + OBH + nrow * 64 + ((kc ^ (nrow & 3)) << 4);
                uint32_t bh[4], bl[4];
                ldm_x4(bd, bh);
                ldm_x4(bd + BN * 64, bl);
#pragma unroll
                for (int mi = 0; mi < MI; mi++)
#pragma unroll
                    for (int j = 0; j < 2; j++) {
                        float* a4 = acc[mi][np * 2 + j];
                        mma16816h(a4, ah[mi], bh + 2 * j);
                        mma16816h(a4, ah[mi], bl + 2 * j);
                        mma16816h(a4, al[mi], bh + 2 * j);
                    }
            }
        }
        __syncthreads();
    }

    const int er = lane >> 2, ec = (lane & 3) * 2;
    const long mb = wm * WTM + er;
    const int nb = wn * WTN + ec;
#pragma unroll
    for (int mi = 0; mi < MI; mi++)
#pragma unroll
        for (int nj = 0; nj < NJ; nj++) {
            float* p0 = Cp + (mb + mi * 16) * ldc + nb + nj * 8;
            float* p1 = p0 + 8L * ldc;
            *reinterpret_cast<float2*>(p0) = make_float2(acc[mi][nj][0], acc[mi][nj][1]);
            *reinterpret_cast<float2*>(p1) = make_float2(acc[mi][nj][2], acc[mi][nj][3]);
        }
}

// ================= prep: build_dense (6144) + 4 weight transposes (3072) ====
__global__ void prep_kernel(const float* __restrict__ sgm, const int* __restrict__ sb, int Ns,
                            const float* __restrict__ velo, const int* __restrict__ vb, int Nv,
                            const float* __restrict__ Wq, const float* __restrict__ Wk,
                            const float* __restrict__ Wv2, const float* __restrict__ Wv1) {
    __shared__ float t[32][33];
    int bid = blockIdx.x;
    if (bid < 6144) { build_slot(bid, sgm, sb, Ns, velo, vb, Nv); return; }
    bid -= 6144;
    if (bid < 1024) {
        tsp_body(t, Wq, g_hf + BO_WQV2H, g_hf + BO_WQV2L, 1024, 1024, bid & 31, bid >> 5);
    } else if (bid < 2048) {
        bid -= 1024;
        tsp_body(t, Wk, g_hf + BO_WKV1H, g_hf + BO_WKV1L, 1024, 1024, bid & 31, bid >> 5);
    } else if (bid < 2560) {
        bid -= 2048;
        tsp_body(t, Wv2, g_hf + BO_WQV2H + 1048576L, g_hf + BO_WQV2L + 1048576L, 1024, 512,
                 bid & 15, bid >> 4);
    } else {
        bid -= 2560;
        tsp_body(t, Wv1, g_hf + BO_WKV1H + 1048576L, g_hf + BO_WKV1L + 1048576L, 1024, 512,
                 bid & 15, bid >> 4);
    }
}

// merged big GEMM: qv2 (blockIdx.y<16) + kv1 (y>=16); grid (12, 48)
__global__ __launch_bounds__(256, 2)
void mma_gemm_big(float* __restrict__ c1, float* __restrict__ c2) {
    extern __shared__ char smem[];
    const uint32_t sb = smem_u32(smem);
    const int K = DD, ldc = 1536;
    const long n0 = (long)blockIdx.x * 128;
    const __half *Ah, *Al, *Bh, *Bl;
    float* Cp;
    if (blockIdx.y < 16) {
        long m0 = (long)blockIdx.y * 128;
        Ah = g_hf + BO_SGMH + m0 * K;  Al = g_hf + BO_SGML + m0 * K;
        Bh = g_hf + BO_WQV2H + n0 * K; Bl = g_hf + BO_WQV2L + n0 * K;
        Cp = c1 + m0 * ldc + n0;
    } else {
        long m0 = (long)(blockIdx.y - 16) * 128;
        Ah = g_hf + BO_VELOH + m0 * K; Al = g_hf + BO_VELOL + m0 * K;
        Bh = g_hf + BO_WKV1H + n0 * K; Bl = g_hf + BO_WKV1L + n0 * K;
        Cp = c2 + m0 * ldc + n0;
    }
    gemm_body<128, 128, 4, 2>(Ah, Al, Bh, Bl, Cp, K, ldc, sb);
}

// ================= MEGA1: scores GEMM + v1T transpose + fc3a v2-half ========
__global__ __launch_bounds__(256)
void mega1_kernel(const float* __restrict__ W3a) {
    extern __shared__ char dsm[];
    int bid = blockIdx.x;
    if (bid < 128) {
        const uint32_t sb = smem_u32(dsm);
        int x = bid & 3, y = (bid >> 2) & 1, z = bid >> 3;
        long m0 = (long)y * 64, n0 = (long)x * 64;
        gemm_body<64, 64, 2, 4>(
            g_hf + BO_QH + (long)z * SS * DD + m0 * DD,
            g_hf + BO_QL + (long)z * SS * DD + m0 * DD,
            g_hf + BO_KH + (long)z * TT * DD + n0 * DD,
            g_hf + BO_KL + (long)z * TT * DD + n0 * DD,
            g_buf + OFF_ATTNF + (long)z * SS * TT + m0 * TT + n0, DD, TT, sb);
    } else if (bid < 2176) {
        int b2 = bid - 128;
        int bx = b2 & 15, by = (b2 >> 4) & 7, bz = b2 >> 7;
        tsp_body(reinterpret_cast<float(*)[33]>(dsm),
                 g_buf + OFF_V1F + (long)bz * TT * 512,
                 g_hf + BO_V1TH + (long)bz * 512 * TT,
                 g_hf + BO_V1TL + (long)bz * 512 * TT,
                 TT, 512, bx, by);
    } else {
        int b3 = bid - 2176;
        fc3a_half_body(reinterpret_cast<float2(*)[8]>(dsm), W3a, b3 & 3, b3 >> 2, 0);
    }
}

// ctx GEMM (batched 64x64, 4 warps)
__global__ __launch_bounds__(128, 2)
void ctx_gemm_kernel(float* __restrict__ C) {
    extern __shared__ char smem[];
    const uint32_t sb = smem_u32(smem);
    const int z = blockIdx.z;
    const long m0 = (long)blockIdx.y * 64, n0 = (long)blockIdx.x * 64;
    gemm_body<64, 64, 2, 2>(
        g_hf + BO_ATH + (long)z * SS * TT + m0 * TT,
        g_hf + BO_ATL + (long)z * SS * TT + m0 * TT,
        g_hf + BO_V1TH + (long)z * 512 * TT + n0 * TT,
        g_hf + BO_V1TL + (long)z * 512 * TT + n0 * TT,
        C + (long)z * FIN + m0 * DD + n0, TT, DD, sb);
}

// fc3a ctx-half
__global__ __launch_bounds__(256)
void fc3a_ctx_kernel(const float* __restrict__ W3a) {
    __shared__ float2 xs[512][8];
    fc3a_half_body(xs, W3a, blockIdx.x, blockIdx.y, 1);
}

// ================= merged dual LayerNorm+ReLU (vectorized) ==================
__global__ void dual_ln2_kernel(const float* __restrict__ in1, const float* __restrict__ in2,
                                const float* __restrict__ gq, const float* __restrict__ bq,
                                const float* __restrict__ gv2, const float* __restrict__ bv2,
                                const float* __restrict__ gk, const float* __restrict__ bk,
                                const float* __restrict__ gv1, const float* __restrict__ bv1,
                                float* __restrict__ dX, float* __restrict__ dV1F) {
    int row = blockIdx.x, t = threadIdx.x;
    int lane = t & 31, wid = t >> 5;
    const float* ip;
    const float *g1, *b1, *g2, *b2;
    __half *oh, *ol;
    float* out2;
    if (row < 2048) {
        ip = in1 + (long)row * 1536;
        g1 = gq; b1 = bq; g2 = gv2; b2 = bv2;
        oh = g_hf + BO_QH + (long)row * 1024;
        ol = g_hf + BO_QL + (long)row * 1024;
        out2 = dX + (long)(row >> 7) * FIN + (long)(row & 127) * 1024;
    } else {
        int r2 = row - 2048;
        ip = in2 + (long)r2 * 1536;
        g1 = gk; b1 = bk; g2 = gv1; b2 = bv1;
        oh = g_hf + BO_KH + (long)r2 * 1024;
        ol = g_hf + BO_KL + (long)r2 * 1024;
        out2 = dV1F + (long)r2 * 512;
    }
    __shared__ float ws[8], wq[8];

    float4 va = *reinterpret_cast<const float4*>(ip + 4 * t);
    float s = va.x + va.y + va.z + va.w;
    float ss = va.x * va.x + va.y * va.y + va.z * va.z + va.w * va.w;
#pragma unroll
    for (int o = 16; o > 0; o >>= 1) {
        s  += __shfl_down_sync(0xffffffffu, s, o);
        ss += __shfl_down_sync(0xffffffffu, ss, o);
    }
    if (lane == 0) { ws[wid] = s; wq[wid] = ss; }
    __syncthreads();
    float st = 0.f, sq = 0.f;
#pragma unroll
    for (int i = 0; i < 8; i++) { st += ws[i]; sq += wq[i]; }
    float mean = st * (1.f / 1024.f);
    float var = sq * (1.f / 1024.f) - mean * mean;
    float r = rsqrtf(var + LN_EPS);
    {
        float4 gg = *reinterpret_cast<const float4*>(g1 + 4 * t);
        float4 bb = *reinterpret_cast<const float4*>(b1 + 4 * t);
        float v0 = fmaxf((va.x - mean) * r * gg.x + bb.x, 0.f);
        float v1 = fmaxf((va.y - mean) * r * gg.y + bb.y, 0.f);
        float v2 = fmaxf((va.z - mean) * r * gg.z + bb.z, 0.f);
        float v3 = fmaxf((va.w - mean) * r * gg.w + bb.w, 0.f);
        uint2 h, l;
        split2h(v0, v1, h.x, l.x);
        split2h(v2, v3, h.y, l.y);
        *reinterpret_cast<uint2*>(oh + 4 * t) = h;
        *reinterpret_cast<uint2*>(ol + 4 * t) = l;
    }

    float2 vb = *reinterpret_cast<const float2*>(ip + 1024 + 2 * t);
    s = vb.x + vb.y;
    ss = vb.x * vb.x + vb.y * vb.y;
#pragma unroll
    for (int o = 16; o > 0; o >>= 1) {
        s  += __shfl_down_sync(0xffffffffu, s, o);
        ss += __shfl_down_sync(0xffffffffu, ss, o);
    }
    __syncthreads();
    if (lane == 0) { ws[wid] = s; wq[wid] = ss; }
    __syncthreads();
    st = 0.f; sq = 0.f;
#pragma unroll
    for (int i = 0; i < 8; i++) { st += ws[i]; sq += wq[i]; }
    mean = st * (1.f / 512.f);
    var = sq * (1.f / 512.f) - mean * mean;
    r = rsqrtf(var + LN_EPS);
    {
        float2 gg = *reinterpret_cast<const float2*>(g2 + 2 * t);
        float2 bb = *reinterpret_cast<const float2*>(b2 + 2 * t);
        float2 o2;
        o2.x = fmaxf((vb.x - mean) * r * gg.x + bb.x, 0.f);
        o2.y = fmaxf((vb.y - mean) * r * gg.y + bb.y, 0.f);
        *reinterpret_cast<float2*>(out2 + 2 * t) = o2;
    }
}

// ================= plain LN+ReLU (fp32 out) =================
__global__ void ln_relu_kernel(const float* __restrict__ in,
                               const float* __restrict__ gamma,
                               const float* __restrict__ beta,
                               float* __restrict__ outp, int C) {
    int row = blockIdx.x;
    int t = threadIdx.x;
    const float* ip = in + (long)row * C;
    float s = 0.f, ss = 0.f;
    for (int c = t; c < C; c += 256) { float v = ip[c]; s += v; ss += v * v; }
    __shared__ float rs[256], rq[256];
    rs[t] = s; rq[t] = ss;
    __syncthreads();
    for (int o = 128; o > 0; o >>= 1) {
        if (t < o) { rs[t] += rs[t + o]; rq[t] += rq[t + o]; }
        __syncthreads();
    }
    float mean = rs[0] / C;
    float var = rq[0] / C - mean * mean;
    float r = rsqrtf(var + LN_EPS);
    float* op = outp + (long)row * C;
    for (int c = t; c < C; c += 256) {
        float v = (ip[c] - mean) * r * gamma[c] + beta[c];
        op[c] = fmaxf(v, 0.f);
    }
}

// ================= softmax (256 wide) -> packed fp16 hi/lo ================
__global__ void softmax_bf_kernel(const float* __restrict__ sc) {
    int row = blockIdx.x;
    int t = threadIdx.x;
    float v = sc[(long)row * 256 + t];
    __shared__ float red[256];
    red[t] = v;
    __syncthreads();
    for (int o = 128; o > 0; o >>= 1) { if (t < o) red[t] = fmaxf(red[t], red[t + o]); __syncthreads(); }
    float mx = red[0];
    __syncthreads();
    float e = __expf(v - mx);
    red[t] = e;
    __syncthreads();
    for (int o = 128; o > 0; o >>= 1) { if (t < o) red[t] += red[t + o]; __syncthreads(); }
    float p = e / red[0];
    float pn = __shfl_down_sync(0xffffffffu, p, 1);
    if ((t & 1) == 0) {
        unsigned h, l;
        split2h(p, pn, h, l);
        *reinterpret_cast<unsigned*>(g_hf + BO_ATH + (long)row * 256 + t) = h;
        *reinterpret_cast<unsigned*>(g_hf + BO_ATL + (long)row * 256 + t) = l;
    }
}

// fused reduce(256 chunks) + LayerNorm + ReLU -> x1; grid 16, block 1024
__global__ __launch_bounds__(1024)
void fc3a_reduce_ln_kernel(const float* __restrict__ part,
                           const float* __restrict__ gamma, const float* __restrict__ beta,
                           float* __restrict__ x1) {
    int b = blockIdx.x, n = threadIdx.x;
    float s = 0.f;
#pragma unroll 4
    for (int c = 0; c < 256; c++) s += part[((long)c * BB + b) * DD + n];
    __shared__ float rs[1024], rq[1024];
    rs[n] = s; rq[n] = s * s;
    __syncthreads();
    for (int o = 512; o > 0; o >>= 1) {
        if (n < o) { rs[n] += rs[n + o]; rq[n] += rq[n + o]; }
        __syncthreads();
    }
    float mean = rs[0] * (1.f / 1024.f);
    float var = rq[0] * (1.f / 1024.f) - mean * mean;
    float r = rsqrtf(var + LN_EPS);
    float v = (s - mean) * r * gamma[n] + beta[n];
    x1[(long)b * DD + n] = fmaxf(v, 0.f);
}

// ================= fc3b: [16,1024] @ [1024,1024] =================
__global__ void small_gemm_kernel(const float* __restrict__ A, const float* __restrict__ W,
                                  float* __restrict__ C, int K, int N) {
    int n = blockIdx.x * 256 + threadIdx.x;
    int b = blockIdx.y;
    float acc = 0.f;
#pragma unroll 4
    for (int k = 0; k < K; k++) acc += A[(long)b * K + k] * W[(long)k * N + n];
    C[(long)b * N + n] = acc;
}

// ================= heads =================
__global__ void heads_kernel(const float* __restrict__ x2,
                             const float* __restrict__ Wr, const float* __restrict__ br,
                             const float* __restrict__ Wt, const float* __restrict__ bt,
                             float* __restrict__ out) {
    int b = blockIdx.x;
    int w = threadIdx.x >> 5, lane = threadIdx.x & 31;
    __shared__ float vals[7];
    if (w < 7) {
        const float* Wp = (w < 4) ? Wr : Wt;
        int ncol = (w < 4) ? 4 : 3;
        int j = (w < 4) ? w : (w - 4);
        float acc = 0.f;
        for (int k = lane; k < DD; k += 32) acc += x2[(long)b * DD + k] * Wp[(long)k * ncol + j];
        for (int o = 16; o > 0; o >>= 1) acc += __shfl_down_sync(0xffffffffu, acc, o);
        if (lane == 0) vals[w] = acc + ((w < 4) ? br[j] : bt[j]);
    }
    __syncthreads();
    if (threadIdx.x == 0) {
        float nn = sqrtf(vals[0]*vals[0] + vals[1]*vals[1] + vals[2]*vals[2] + vals[3]*vals[3]);
        nn = fmaxf(nn, 1e-12f);
        for (int j = 0; j < 4; j++) out[b * 4 + j] = vals[j] / nn;
        for (int j = 0; j < 3; j++) out[64 + b * 3 + j] = vals[4 + j];
    }
}

// ================= host driver =================
extern "C" void kernel_launch(void* const* d_in, const int* in_sizes, int n_in,
                              void* d_out, int out_size) {
    const float* sgm_feats = nullptr; const float* velo_feats = nullptr;
    const int* sbidx = nullptr; const int* vbidx = nullptr;
    int N_sgm = 0, N_velo = 0;
    const float* w[22]; int wi = 0;
    for (int i = 0; i < n_in; i++) {
        int s = in_sizes[i];
        if (s == 3000 * 1024)      { sgm_feats = (const float*)d_in[i]; }
        else if (s == 6000 * 1024) { velo_feats = (const float*)d_in[i]; }
        else if (s == 3000)        { sbidx = (const int*)d_in[i]; N_sgm = s; }
        else if (s == 6000)        { vbidx = (const int*)d_in[i]; N_velo = s; }
        else if (wi < 22)          { w[wi++] = (const float*)d_in[i]; }
    }
    const float *gq = w[1], *bq = w[2];
    const float *Wq = w[0], *Wk = w[3], *gk = w[4], *bk = w[5];
    const float *Wv1 = w[6], *gv1 = w[7], *bv1 = w[8];
    const float *Wv2 = w[9], *gv2 = w[10], *bv2 = w[11];
    const float *W3a = w[12], *g3a = w[13], *b3a = w[14];
    const float *W3b = w[15], *g3b = w[16], *b3b = w[17];
    const float *Wr = w[18], *brr = w[19], *Wt = w[20], *btt = w[21];

    float* fb = nullptr;
    cudaGetSymbolAddress((void**)&fb, g_buf);

    float* dTMP  = fb + OFF_TMP;
    float* dTMP2 = fb + OFF_TMP2;
    float* dV1F  = fb + OFF_V1F;
    float* dX    = fb + OFF_X;
    float* dATT  = fb + OFF_ATTNF;
    float* dPART = fb + OFF_PART;
    float* dX1   = fb + OFF_X1;
    float* dX2   = fb + OFF_X2;
    float* out   = (float*)d_out;

    constexpr int SMEM_A = 2 * 2 * (128 + 128) * 64;   // 65536
    constexpr int SMEM_M = 32768;
    cudaFuncSetAttribute(mma_gemm_big, cudaFuncAttributeMaxDynamicSharedMemorySize, SMEM_A);

    // 1. prep: dense build + all weight transposes
    prep_kernel<<<6144 + 3072, 256>>>(sgm_feats, sbidx, N_sgm, velo_feats, vbidx, N_velo,
                                      Wq, Wk, Wv2, Wv1);

    // 2. merged big GEMM: [q|v2] + [k|v1]
    mma_gemm_big<<<dim3(12, 48), 256, SMEM_A>>>(dTMP, dTMP2);

    // 3. merged dual-LN
    dual_ln2_kernel<<<2048 + 4096, 256>>>(dTMP, dTMP2, gq, bq, gv2, bv2,
                                          gk, bk, gv1, bv1, dX, dV1F);

    // 4. MEGA1: scores + v1T + fc3a v2-half (overlapped in one launch)
    mega1_kernel<<<2688, 256, SMEM_M>>>(W3a);

    // 5. softmax -> packed fp16 hi/lo
    softmax_bf_kernel<<<BB * SS, 256>>>(dATT);

    // 6. ctx = attn @ v1 -> X[:, s*1024 + 512..1023]
    ctx_gemm_kernel<<<dim3(8, 2, BB), 128, SMEM_M>>>(dX + 512);

    // 7. fc3a ctx-half
    fc3a_ctx_kernel<<<dim3(4, 128), 256>>>(W3a);

    // 8. fused reduce + LN -> x1
    fc3a_reduce_ln_kernel<<<BB, 1024>>>(dPART, g3a, b3a, dX1);

    // 9. fc3b + LN -> x2
    small_gemm_kernel<<<dim3(DD / 256, BB), 256>>>(dX1, W3b, dTMP, DD, DD);
    ln_relu_kernel<<<BB, 256>>>(dTMP, g3b, b3b, dX2, DD);

    // 10. heads
    heads_kernel<<<BB, 256>>>(dX2, Wr, brr, Wt, btt, out);
    (void)out_size;
}